// round 9
// baseline (speedup 1.0000x reference)
#include <cuda_runtime.h>
#include <cuda_bf16.h>
#include <math.h>
#include <stdint.h>

// Problem constants (fixed shapes per reference)
#define S_LEN   4096
#define D_MODEL 1024
#define NHEADS  16
#define D_K     64

// ---------------------------------------------------------------------------
// Scratch (device globals; no allocation allowed)
// ---------------------------------------------------------------------------
__device__ __nv_bfloat16 g_xh[S_LEN * D_MODEL];
__device__ __nv_bfloat16 g_xl[S_LEN * D_MODEL];
__device__ __nv_bfloat16 g_ch[S_LEN * D_MODEL];
__device__ __nv_bfloat16 g_cl[S_LEN * D_MODEL];
__device__ __nv_bfloat16 g_Qh[S_LEN * D_MODEL];
__device__ __nv_bfloat16 g_Ql[S_LEN * D_MODEL];
__device__ __nv_bfloat16 g_Kh[S_LEN * D_MODEL];
__device__ __nv_bfloat16 g_Kl[S_LEN * D_MODEL];
__device__ __nv_bfloat16 g_Vh[S_LEN * D_MODEL];
__device__ __nv_bfloat16 g_Vl[S_LEN * D_MODEL];
__device__ __nv_bfloat16 g_wqh[D_MODEL * D_MODEL];
__device__ __nv_bfloat16 g_wql[D_MODEL * D_MODEL];
__device__ __nv_bfloat16 g_wkh[D_MODEL * D_MODEL];
__device__ __nv_bfloat16 g_wkl[D_MODEL * D_MODEL];
__device__ __nv_bfloat16 g_wvh[D_MODEL * D_MODEL];
__device__ __nv_bfloat16 g_wvl[D_MODEL * D_MODEL];
__device__ __nv_bfloat16 g_woh[D_MODEL * D_MODEL];
__device__ __nv_bfloat16 g_wol[D_MODEL * D_MODEL];

// ---------------------------------------------------------------------------
// PTX helpers (base sm_80+ features only — build targets plain compute_103)
// ---------------------------------------------------------------------------
__device__ __forceinline__ uint32_t smem_u32(const void* p) {
    uint32_t a;
    asm("{ .reg .u64 t; cvta.to.shared.u64 t, %1; cvt.u32.u64 %0, t; }"
        : "=r"(a) : "l"(p));
    return a;
}

__device__ __forceinline__ void cp_async16(uint32_t smem_dst, const void* gmem_src) {
    asm volatile("cp.async.cg.shared.global [%0], [%1], 16;\n"
                 :: "r"(smem_dst), "l"(gmem_src));
}

__device__ __forceinline__ void ldsm_x4(uint32_t* r, uint32_t addr) {
    asm volatile("ldmatrix.sync.aligned.m8n8.x4.shared.b16 {%0,%1,%2,%3}, [%4];"
                 : "=r"(r[0]), "=r"(r[1]), "=r"(r[2]), "=r"(r[3]) : "r"(addr));
}

__device__ __forceinline__ void ldsm_x4_t(uint32_t* r, uint32_t addr) {
    asm volatile("ldmatrix.sync.aligned.m8n8.x4.trans.shared.b16 {%0,%1,%2,%3}, [%4];"
                 : "=r"(r[0]), "=r"(r[1]), "=r"(r[2]), "=r"(r[3]) : "r"(addr));
}

__device__ __forceinline__ void mma_16816(float* d, const uint32_t* a, const uint32_t* b) {
    asm volatile(
        "mma.sync.aligned.m16n8k16.row.col.f32.bf16.bf16.f32 "
        "{%0,%1,%2,%3}, {%4,%5,%6,%7}, {%8,%9}, {%0,%1,%2,%3};"
        : "+f"(d[0]), "+f"(d[1]), "+f"(d[2]), "+f"(d[3])
        : "r"(a[0]), "r"(a[1]), "r"(a[2]), "r"(a[3]), "r"(b[0]), "r"(b[1]));
}

__device__ __forceinline__ float fast_exp2(float x) {
    float r; asm("ex2.approx.f32 %0, %1;" : "=f"(r) : "f"(x)); return r;
}

// pack two fp32 -> bf16x2 (x in low half, y in high half)
__device__ __forceinline__ uint32_t pack_bf(float x, float y) {
    uint32_t r;
    asm("cvt.rn.bf16x2.f32 %0, %1, %2;" : "=r"(r) : "f"(y), "f"(x));
    return r;
}
__device__ __forceinline__ float bf_lo(uint32_t r) { return __uint_as_float(r << 16); }
__device__ __forceinline__ float bf_hi(uint32_t r) { return __uint_as_float(r & 0xffff0000u); }

// ---------------------------------------------------------------------------
// Split fp32 -> bf16 hi/lo  (hi = bf16(x), lo = bf16(x - float(hi)))
// ---------------------------------------------------------------------------
__device__ __forceinline__ void split_one(const float* in, __nv_bfloat16* hi,
                                          __nv_bfloat16* lo, int i)
{
    float4 v = ((const float4*)in)[i];
    uint32_t h01 = pack_bf(v.x, v.y);
    uint32_t h23 = pack_bf(v.z, v.w);
    uint32_t l01 = pack_bf(v.x - bf_lo(h01), v.y - bf_hi(h01));
    uint32_t l23 = pack_bf(v.z - bf_lo(h23), v.w - bf_hi(h23));
    ((uint32_t*)hi)[i * 2 + 0] = h01;
    ((uint32_t*)hi)[i * 2 + 1] = h23;
    ((uint32_t*)lo)[i * 2 + 0] = l01;
    ((uint32_t*)lo)[i * 2 + 1] = l23;
}

__global__ void split_bf16_kernel(const float* __restrict__ in,
                                  __nv_bfloat16* __restrict__ hi,
                                  __nv_bfloat16* __restrict__ lo, int n4)
{
    int i = blockIdx.x * blockDim.x + threadIdx.x;
    if (i >= n4) return;
    split_one(in, hi, lo, i);
}

// All 4 weight matrices in one launch; idx>>18 routes (n_w4 = 2^18).
__global__ void split_w4_kernel(
    const float* __restrict__ w0, const float* __restrict__ w1,
    const float* __restrict__ w2, const float* __restrict__ w3,
    __nv_bfloat16* __restrict__ h0, __nv_bfloat16* __restrict__ l0,
    __nv_bfloat16* __restrict__ h1, __nv_bfloat16* __restrict__ l1,
    __nv_bfloat16* __restrict__ h2, __nv_bfloat16* __restrict__ l2,
    __nv_bfloat16* __restrict__ h3, __nv_bfloat16* __restrict__ l3)
{
    int idx = blockIdx.x * blockDim.x + threadIdx.x;
    int sel = idx >> 18;
    int i   = idx & ((1 << 18) - 1);
    const float* in = sel == 0 ? w0 : sel == 1 ? w1 : sel == 2 ? w2 : w3;
    __nv_bfloat16* hi = sel == 0 ? h0 : sel == 1 ? h1 : sel == 2 ? h2 : h3;
    __nv_bfloat16* lo = sel == 0 ? l0 : sel == 1 ? l1 : sel == 2 ? l2 : l3;
    split_one(in, hi, lo, i);
}

// ---------------------------------------------------------------------------
// Tensor-core GEMM body (HMMA, bf16, fp32 acc):
//   acc = Ahi*Bhi^T + Ahi*Blo^T + Alo*Bhi^T  over K=1024, tile 128x128
// ---------------------------------------------------------------------------
#define GK     1024
#define GBK    32
#define ROWB   80
#define TILEB  (128 * ROWB)     // 10240
#define SETB   (4 * TILEB)      // 40960 per stage
#define GSM_TOTAL (2 * SETB)    // 81920
#define NKCH   32

__device__ __forceinline__ void load_chunk4(
    const __nv_bfloat16* __restrict__ Ah, const __nv_bfloat16* __restrict__ Al,
    const __nv_bfloat16* __restrict__ Bh, const __nv_bfloat16* __restrict__ Bl,
    int bm, int bn, int k0, uint32_t dst, int tid)
{
#pragma unroll
    for (int t = 0; t < 2; t++) {
        int u = tid + t * 256;
        int r = u >> 2;
        int c = (u & 3) * 16;
        size_t ao = (size_t)(bm + r) * GK + k0;
        size_t bo = (size_t)(bn + r) * GK + k0;
        uint32_t so = (uint32_t)(r * ROWB + c);
        cp_async16(dst + so,             (const char*)(Ah + ao) + c);
        cp_async16(dst + TILEB + so,     (const char*)(Al + ao) + c);
        cp_async16(dst + 2 * TILEB + so, (const char*)(Bh + bo) + c);
        cp_async16(dst + 3 * TILEB + so, (const char*)(Bl + bo) + c);
    }
    asm volatile("cp.async.commit_group;\n" ::: "memory");
}

__device__ __forceinline__ void gemm_body(
    const __nv_bfloat16* __restrict__ A_hi, const __nv_bfloat16* __restrict__ A_lo,
    const __nv_bfloat16* __restrict__ B_hi, const __nv_bfloat16* __restrict__ B_lo,
    int bm, int bn, uint32_t sb, float acc[2][8][4])
{
    const int tid  = threadIdx.x;
    const int lane = tid & 31;
    const int w    = tid >> 5;
    const int m_off = (w & 3) * 32;
    const int n_off = (w >> 2) * 64;

#pragma unroll
    for (int mt = 0; mt < 2; mt++)
#pragma unroll
        for (int nt = 0; nt < 8; nt++)
#pragma unroll
            for (int i = 0; i < 4; i++) acc[mt][nt][i] = 0.0f;

    const uint32_t a_off = (uint32_t)((m_off + (lane & 15)) * ROWB + 16 * (lane >> 4));
    const uint32_t b_off = (uint32_t)((n_off + (lane & 7) + 8 * (lane >> 4)) * ROWB
                                      + 16 * ((lane >> 3) & 1));

    load_chunk4(A_hi, A_lo, B_hi, B_lo, bm, bn, 0,   sb,        tid);
    load_chunk4(A_hi, A_lo, B_hi, B_lo, bm, bn, GBK, sb + SETB, tid);

    for (int i = 0; i < NKCH; i++) {
        if (i + 1 < NKCH) {
            asm volatile("cp.async.wait_group 1;\n" ::: "memory");
        } else {
            asm volatile("cp.async.wait_group 0;\n" ::: "memory");
        }
        __syncthreads();

        const uint32_t base = sb + (uint32_t)(i & 1) * SETB;
#pragma unroll
        for (int ks = 0; ks < 2; ks++) {
            uint32_t ah[2][4], al[2][4];
#pragma unroll
            for (int mt = 0; mt < 2; mt++) {
                uint32_t aadr = base + a_off + (uint32_t)(mt * 16 * ROWB + ks * 32);
                ldsm_x4(ah[mt], aadr);
                ldsm_x4(al[mt], aadr + TILEB);
            }
            uint32_t b2[8][2];
#pragma unroll
            for (int np = 0; np < 4; np++) {
                uint32_t r4[4];
                ldsm_x4(r4, base + 2 * TILEB + b_off + (uint32_t)(np * 16 * ROWB + ks * 32));
                b2[2*np][0] = r4[0]; b2[2*np][1] = r4[1];
                b2[2*np+1][0] = r4[2]; b2[2*np+1][1] = r4[3];
            }
#pragma unroll
            for (int mt = 0; mt < 2; mt++)
#pragma unroll
                for (int nt = 0; nt < 8; nt++) {
                    mma_16816(acc[mt][nt], ah[mt], b2[nt]);
                    mma_16816(acc[mt][nt], al[mt], b2[nt]);
                }
#pragma unroll
            for (int np = 0; np < 4; np++) {
                uint32_t r4[4];
                ldsm_x4(r4, base + 3 * TILEB + b_off + (uint32_t)(np * 16 * ROWB + ks * 32));
                b2[2*np][0] = r4[0]; b2[2*np][1] = r4[1];
                b2[2*np+1][0] = r4[2]; b2[2*np+1][1] = r4[3];
            }
#pragma unroll
            for (int mt = 0; mt < 2; mt++)
#pragma unroll
                for (int nt = 0; nt < 8; nt++)
                    mma_16816(acc[mt][nt], ah[mt], b2[nt]);
        }
        __syncthreads();

        if (i + 2 < NKCH)
            load_chunk4(A_hi, A_lo, B_hi, B_lo, bm, bn, (i + 2) * GBK, base, tid);
    }
}

// Fused QKV: blockIdx.x in [0,24); sel = bx>>3 routes weight/output.
__global__ __launch_bounds__(256, 2) void gemm_qkv_kernel(
    const __nv_bfloat16* __restrict__ A_hi, const __nv_bfloat16* __restrict__ A_lo,
    const __nv_bfloat16* __restrict__ Wqh, const __nv_bfloat16* __restrict__ Wql,
    const __nv_bfloat16* __restrict__ Wkh, const __nv_bfloat16* __restrict__ Wkl,
    const __nv_bfloat16* __restrict__ Wvh, const __nv_bfloat16* __restrict__ Wvl,
    __nv_bfloat16* __restrict__ Qh, __nv_bfloat16* __restrict__ Ql,
    __nv_bfloat16* __restrict__ Kh, __nv_bfloat16* __restrict__ Kl,
    __nv_bfloat16* __restrict__ Vh, __nv_bfloat16* __restrict__ Vl)
{
    extern __shared__ __align__(16) char gsm[];
    const uint32_t sb = smem_u32(gsm);
    const int sel = blockIdx.x >> 3;
    const int bn  = (blockIdx.x & 7) * 128;
    const int bm  = blockIdx.y * 128;
    const __nv_bfloat16* Bh = sel == 0 ? Wqh : sel == 1 ? Wkh : Wvh;
    const __nv_bfloat16* Bl = sel == 0 ? Wql : sel == 1 ? Wkl : Wvl;
    __nv_bfloat16* Ch = sel == 0 ? Qh : sel == 1 ? Kh : Vh;
    __nv_bfloat16* Cl = sel == 0 ? Ql : sel == 1 ? Kl : Vl;

    float acc[2][8][4];
    gemm_body(A_hi, A_lo, Bh, Bl, bm, bn, sb, acc);

    const int lane = threadIdx.x & 31;
    const int w    = threadIdx.x >> 5;
    const int m_off = (w & 3) * 32;
    const int n_off = (w >> 2) * 64;
    const int g = lane >> 2;
    const int q = lane & 3;
#pragma unroll
    for (int mt = 0; mt < 2; mt++) {
#pragma unroll
        for (int nt = 0; nt < 8; nt++) {
            int row = bm + m_off + mt * 16 + g;
            int col = bn + n_off + nt * 8 + q * 2;
            uint32_t h0 = pack_bf(acc[mt][nt][0], acc[mt][nt][1]);
            uint32_t l0 = pack_bf(acc[mt][nt][0] - bf_lo(h0),
                                  acc[mt][nt][1] - bf_hi(h0));
            *(uint32_t*)(Ch + (size_t)row * D_MODEL + col) = h0;
            *(uint32_t*)(Cl + (size_t)row * D_MODEL + col) = l0;
            uint32_t h1 = pack_bf(acc[mt][nt][2], acc[mt][nt][3]);
            uint32_t l1 = pack_bf(acc[mt][nt][2] - bf_lo(h1),
                                  acc[mt][nt][3] - bf_hi(h1));
            *(uint32_t*)(Ch + (size_t)(row + 8) * D_MODEL + col) = h1;
            *(uint32_t*)(Cl + (size_t)(row + 8) * D_MODEL + col) = l1;
        }
    }
}

// Output GEMM: fp32 C
__global__ __launch_bounds__(256, 2) void gemm_out_kernel(
    const __nv_bfloat16* __restrict__ A_hi, const __nv_bfloat16* __restrict__ A_lo,
    const __nv_bfloat16* __restrict__ B_hi, const __nv_bfloat16* __restrict__ B_lo,
    float* __restrict__ Cf)
{
    extern __shared__ __align__(16) char gsm[];
    const uint32_t sb = smem_u32(gsm);
    const int bn = blockIdx.x * 128;
    const int bm = blockIdx.y * 128;

    float acc[2][8][4];
    gemm_body(A_hi, A_lo, B_hi, B_lo, bm, bn, sb, acc);

    const int lane = threadIdx.x & 31;
    const int w    = threadIdx.x >> 5;
    const int m_off = (w & 3) * 32;
    const int n_off = (w >> 2) * 64;
    const int g = lane >> 2;
    const int q = lane & 3;
#pragma unroll
    for (int mt = 0; mt < 2; mt++) {
#pragma unroll
        for (int nt = 0; nt < 8; nt++) {
            int row = bm + m_off + mt * 16 + g;
            int col = bn + n_off + nt * 8 + q * 2;
            *(float2*)(Cf + (size_t)row * D_MODEL + col) =
                make_float2(acc[mt][nt][0], acc[mt][nt][1]);
            *(float2*)(Cf + (size_t)(row + 8) * D_MODEL + col) =
                make_float2(acc[mt][nt][2], acc[mt][nt][3]);
        }
    }
}

// ---------------------------------------------------------------------------
// Tensor-core causal flash attention (FA2-style register softmax).
// CTA: 128 q-rows x one head, 8 warps x 16 rows. 32-key tiles in a 4-stage
// ring, processed in PAIRS with ONE __syncthreads per pair (64 keys):
// warps drift between the two tiles, overlapping softmax with other warps'
// MMAs. Pair p+1's load is issued right after sync_p into the half freed by
// pair p-1 (WAR-safe). Numerics identical to R6 (3-term scores, 3-term PV).
// ---------------------------------------------------------------------------
#define AQT 128
#define AKT 32
#define AROWB 144
#define AQ_BYTES   (128 * AROWB)       // 18432
#define AKV_BYTES  (32 * AROWB)        // 4608 per tile component
#define ASET_BYTES (4 * AKV_BYTES)     // 18432 per stage (Kh,Kl,Vh,Vl)
#define ANSTAGE    4
#define ASM_KV0    (2 * AQ_BYTES)      // 36864
#define ASM_TOTAL  (ASM_KV0 + ANSTAGE * ASET_BYTES)   // 110592

__device__ __forceinline__ void load_kv_tile_nc(
    const __nv_bfloat16* __restrict__ Kh, const __nv_bfloat16* __restrict__ Kl,
    const __nv_bfloat16* __restrict__ Vh, const __nv_bfloat16* __restrict__ Vl,
    int k0, int h, uint32_t base, int tid)
{
    int r = tid >> 3, c = tid & 7;
    uint32_t so = (uint32_t)(r * AROWB + c * 16);
    size_t  go = (size_t)(k0 + r) * D_MODEL + h * D_K + c * 8;
    cp_async16(base + 0 * AKV_BYTES + so, Kh + go);
    cp_async16(base + 1 * AKV_BYTES + so, Kl + go);
    cp_async16(base + 2 * AKV_BYTES + so, Vh + go);
    cp_async16(base + 3 * AKV_BYTES + so, Vl + go);
}

__global__ __launch_bounds__(256, 2) void flash_mma_kernel(
    const __nv_bfloat16* __restrict__ Qh, const __nv_bfloat16* __restrict__ Ql,
    const __nv_bfloat16* __restrict__ Kh, const __nv_bfloat16* __restrict__ Kl,
    const __nv_bfloat16* __restrict__ Vh, const __nv_bfloat16* __restrict__ Vl,
    __nv_bfloat16* __restrict__ Ch, __nv_bfloat16* __restrict__ Cl)
{
    extern __shared__ char smem[];
    const uint32_t sb = smem_u32(smem);
    const int tid  = threadIdx.x;
    const int lane = tid & 31;
    const int wid  = tid >> 5;
    const int m_off = wid * 16;          // 8 warps x 16 rows
    const int h  = blockIdx.y;
    const int q0 = (int)(gridDim.x - 1 - blockIdx.x) * AQT;   // heavy blocks first
    const int g  = lane >> 2;
    const int qd = lane & 3;

    // Stage Q (hi at +0, lo at +AQ_BYTES): 8 x 16B per thread
#pragma unroll
    for (int t = 0; t < 8; t++) {
        const __nv_bfloat16* src = (t < 4) ? Qh : Ql;
        int v = (t & 3) * 256 + tid;        // 0..1023
        int r = v >> 3, c = v & 7;
        cp_async16(sb + (t >> 2) * AQ_BYTES + r * AROWB + c * 16,
                   src + (size_t)(q0 + r) * D_MODEL + h * D_K + c * 8);
    }
    asm volatile("cp.async.commit_group;\n" ::: "memory");

    const int ntiles = q0 / AKT + AQT / AKT;   // multiple of 4
    const int npairs = ntiles / 2;             // >= 2

    // preload pairs 0 (tiles 0,1) and 1 (tiles 2,3) — one group each
    load_kv_tile_nc(Kh, Kl, Vh, Vl, 0 * AKT, h, sb + ASM_KV0 + 0 * ASET_BYTES, tid);
    load_kv_tile_nc(Kh, Kl, Vh, Vl, 1 * AKT, h, sb + ASM_KV0 + 1 * ASET_BYTES, tid);
    asm volatile("cp.async.commit_group;\n" ::: "memory");
    load_kv_tile_nc(Kh, Kl, Vh, Vl, 2 * AKT, h, sb + ASM_KV0 + 2 * ASET_BYTES, tid);
    load_kv_tile_nc(Kh, Kl, Vh, Vl, 3 * AKT, h, sb + ASM_KV0 + 3 * ASET_BYTES, tid);
    asm volatile("cp.async.commit_group;\n" ::: "memory");

    float m_i[2] = { -1e30f, -1e30f };
    float l_i[2] = { 0.f, 0.f };
    float O[8][4];
#pragma unroll
    for (int no = 0; no < 8; no++)
#pragma unroll
        for (int i = 0; i < 4; i++) O[no][i] = 0.f;

    const float C1 = 0.18033688011112042f;   // log2(e) / sqrt(64)

    // per-thread fragment offsets (tile-invariant)
    const uint32_t q_base = sb + (uint32_t)((m_off + (lane & 15)) * AROWB + 16 * (lane >> 4));
    const uint32_t k_base = (uint32_t)(((lane & 7) + 8 * (lane >> 4)) * AROWB
                                       + 16 * ((lane >> 3) & 1));
    const uint32_t v_base = (uint32_t)(((lane & 7) + 8 * ((lane >> 3) & 1)) * AROWB
                                       + 16 * (lane >> 4));

    for (int p = 0; p < npairs; p++) {
        // pair p's loads (and everything older) must be complete
        asm volatile("cp.async.wait_group 0;\n" ::: "memory");
        __syncthreads();

        // issue pair p+1's load into the half freed by pair p-1 (WAR-safe:
        // all warps passed this barrier after reading pair p-1)
        if (p >= 1 && p + 1 < npairs) {
            int t0 = 2 * (p + 1);
            load_kv_tile_nc(Kh, Kl, Vh, Vl, t0 * AKT, h,
                            sb + ASM_KV0 + (uint32_t)(t0 & 3) * ASET_BYTES, tid);
            load_kv_tile_nc(Kh, Kl, Vh, Vl, (t0 + 1) * AKT, h,
                            sb + ASM_KV0 + (uint32_t)((t0 + 1) & 3) * ASET_BYTES, tid);
            asm volatile("cp.async.commit_group;\n" ::: "memory");
        }

        // process both tiles of the pair with NO barrier in between
#pragma unroll
        for (int sub = 0; sub < 2; sub++) {
            const int t  = 2 * p + sub;
            const uint32_t kvb = sb + ASM_KV0 + (uint32_t)(t & 3) * ASET_BYTES;
            const int k0 = t * AKT;

            // ---- scores S[4][4] (16 q-rows x 32 keys), 3-term split ----
            float S[4][4];
#pragma unroll
            for (int nt = 0; nt < 4; nt++)
#pragma unroll
                for (int i = 0; i < 4; i++) S[nt][i] = 0.f;

#pragma unroll
            for (int ks = 0; ks < 4; ks++) {
                uint32_t qa[4], qla[4];
                uint32_t qaddr = q_base + (uint32_t)(ks * 32);
                ldsm_x4(qa, qaddr);
                ldsm_x4(qla, qaddr + AQ_BYTES);

                uint32_t b2[4][2];
#pragma unroll
                for (int np = 0; np < 2; np++) {
                    uint32_t r4[4];
                    ldsm_x4(r4, kvb + k_base + (uint32_t)(np * 16 * AROWB + ks * 32));
                    b2[2*np][0] = r4[0]; b2[2*np][1] = r4[1];
                    b2[2*np+1][0] = r4[2]; b2[2*np+1][1] = r4[3];
                }
#pragma unroll
                for (int nt = 0; nt < 4; nt++) {
                    mma_16816(S[nt], qa,  b2[nt]);
                    mma_16816(S[nt], qla, b2[nt]);
                }
#pragma unroll
                for (int np = 0; np < 2; np++) {
                    uint32_t r4[4];
                    ldsm_x4(r4, kvb + AKV_BYTES + k_base
                                + (uint32_t)(np * 16 * AROWB + ks * 32));
                    b2[2*np][0] = r4[0]; b2[2*np][1] = r4[1];
                    b2[2*np+1][0] = r4[2]; b2[2*np+1][1] = r4[3];
                }
#pragma unroll
                for (int nt = 0; nt < 4; nt++)
                    mma_16816(S[nt], qa, b2[nt]);
            }

            // ---- causal mask (boundary tiles only) ----
            if (k0 + AKT > q0) {
                int qg0 = q0 + m_off + g;
#pragma unroll
                for (int nt = 0; nt < 4; nt++) {
                    int kg = k0 + nt * 8 + 2 * qd;
                    if (kg     > qg0)     S[nt][0] = -1e30f;
                    if (kg + 1 > qg0)     S[nt][1] = -1e30f;
                    if (kg     > qg0 + 8) S[nt][2] = -1e30f;
                    if (kg + 1 > qg0 + 8) S[nt][3] = -1e30f;
                }
            }

            // ---- online softmax per row half (rows g and g+8) ----
#pragma unroll
            for (int hf = 0; hf < 2; hf++) {
                float mx = -1e30f;
#pragma unroll
                for (int nt = 0; nt < 4; nt++)
                    mx = fmaxf(mx, fmaxf(S[nt][2*hf], S[nt][2*hf+1]));
                mx = fmaxf(mx, __shfl_xor_sync(0xffffffffu, mx, 1));
                mx = fmaxf(mx, __shfl_xor_sync(0xffffffffu, mx, 2));
                float mold = m_i[hf];
                float mnew = fmaxf(mold, mx);
                float f  = fast_exp2((mold - mnew) * C1);
                float nm = mnew * C1;
                float sum = 0.f;
#pragma unroll
                for (int nt = 0; nt < 4; nt++) {
                    float p0 = fast_exp2(fmaf(S[nt][2*hf],   C1, -nm));
                    float p1 = fast_exp2(fmaf(S[nt][2*hf+1], C1, -nm));
                    S[nt][2*hf] = p0; S[nt][2*hf+1] = p1;
                    sum += p0 + p1;
                }
                sum += __shfl_xor_sync(0xffffffffu, sum, 1);
                sum += __shfl_xor_sync(0xffffffffu, sum, 2);
                l_i[hf] = l_i[hf] * f + sum;
                m_i[hf] = mnew;
#pragma unroll
                for (int no = 0; no < 8; no++) {
                    O[no][2*hf]   *= f;
                    O[no][2*hf+1] *= f;
                }
            }

            // ---- P·V, 3-term split (PhVh + PhVl + PlVh) ----
#pragma unroll
            for (int j = 0; j < 2; j++) {
                uint32_t ph[4], pl[4];
                ph[0] = pack_bf(S[2*j][0],   S[2*j][1]);
                ph[1] = pack_bf(S[2*j][2],   S[2*j][3]);
                ph[2] = pack_bf(S[2*j+1][0], S[2*j+1][1]);
                ph[3] = pack_bf(S[2*j+1][2], S[2*j+1][3]);
                pl[0] = pack_bf(S[2*j][0]   - bf_lo(ph[0]), S[2*j][1]   - bf_hi(ph[0]));
                pl[1] = pack_bf(S[2*j][2]   - bf_lo(ph[1]), S[2*j][3]   - bf_hi(ph[1]));
                pl[2] = pack_bf(S[2*j+1][0] - bf_lo(ph[2]), S[2*j+1][1] - bf_hi(ph[2]));
                pl[3] = pack_bf(S[2*j+1][2] - bf_lo(ph[3]), S[2*j+1][3] - bf_hi(ph[3]));

                uint32_t v2[8][2];
#pragma unroll
                for (int np = 0; np < 4; np++) {
                    uint32_t r4[4];
                    ldsm_x4_t(r4, kvb + 2 * AKV_BYTES + v_base
                                  + (uint32_t)(j * 16 * AROWB + np * 32));
                    v2[2*np][0] = r4[0]; v2[2*np][1] = r4[1];
                    v2[2*np+1][0] = r4[2]; v2[2*np+1][1] = r4[3];
                }
#pragma unroll
                for (int no = 0; no < 8; no++) {
                    mma_16816(O[no], ph, v2[no]);
                    mma_16816(O[no], pl, v2[no]);
                }
#pragma unroll
                for (int np = 0; np < 4; np++) {
                    uint32_t r4[4];
                    ldsm_x4_t(r4, kvb + 3 * AKV_BYTES + v_base
                                  + (uint32_t)(j * 16 * AROWB + np * 32));
                    v2[2*np][0] = r4[0]; v2[2*np][1] = r4[1];
                    v2[2*np+1][0] = r4[2]; v2[2*np+1][1] = r4[3];
                }
#pragma unroll
                for (int no = 0; no < 8; no++)
                    mma_16816(O[no], ph, v2[no]);
            }
        }
    }

    // ---- epilogue: normalize + write bf16 hi/lo context ----
    {
        float inv0 = 1.f / l_i[0];
        float inv1 = 1.f / l_i[1];
        int r0 = q0 + m_off + g;
#pragma unroll
        for (int no = 0; no < 8; no++) {
            int col = h * D_K + no * 8 + 2 * qd;
            float o0 = O[no][0] * inv0, o1 = O[no][1] * inv0;
            float o2 = O[no][2] * inv1, o3 = O[no][3] * inv1;
            uint32_t h0 = pack_bf(o0, o1);
            uint32_t l0 = pack_bf(o0 - bf_lo(h0), o1 - bf_hi(h0));
            *(uint32_t*)(Ch + (size_t)r0 * D_MODEL + col) = h0;
            *(uint32_t*)(Cl + (size_t)r0 * D_MODEL + col) = l0;
            uint32_t h1 = pack_bf(o2, o3);
            uint32_t l1 = pack_bf(o2 - bf_lo(h1), o3 - bf_hi(h1));
            *(uint32_t*)(Ch + (size_t)(r0 + 8) * D_MODEL + col) = h1;
            *(uint32_t*)(Cl + (size_t)(r0 + 8) * D_MODEL + col) = l1;
        }
    }
}

// ---------------------------------------------------------------------------
// Launch
// ---------------------------------------------------------------------------
extern "C" void kernel_launch(void* const* d_in, const int* in_sizes, int n_in,
                              void* d_out, int out_size)
{
    const float* x   = (const float*)d_in[0];
    const float* W_q = (const float*)d_in[1];
    const float* W_k = (const float*)d_in[2];
    const float* W_v = (const float*)d_in[3];
    const float* W_o = (const float*)d_in[4];
    float* out = (float*)d_out;

    static __nv_bfloat16* xh = nullptr;
    static __nv_bfloat16 *xl, *ch, *cl, *qh, *ql, *kh, *kl, *vh, *vl;
    static __nv_bfloat16 *wqh, *wql, *wkh, *wkl, *wvh, *wvl, *woh, *wol;
    if (xh == nullptr) {
        cudaGetSymbolAddress((void**)&xl, g_xl);
        cudaGetSymbolAddress((void**)&ch, g_ch);
        cudaGetSymbolAddress((void**)&cl, g_cl);
        cudaGetSymbolAddress((void**)&qh, g_Qh);
        cudaGetSymbolAddress((void**)&ql, g_Ql);
        cudaGetSymbolAddress((void**)&kh, g_Kh);
        cudaGetSymbolAddress((void**)&kl, g_Kl);
        cudaGetSymbolAddress((void**)&vh, g_Vh);
        cudaGetSymbolAddress((void**)&vl, g_Vl);
        cudaGetSymbolAddress((void**)&wqh, g_wqh);
        cudaGetSymbolAddress((void**)&wql, g_wql);
        cudaGetSymbolAddress((void**)&wkh, g_wkh);
        cudaGetSymbolAddress((void**)&wkl, g_wkl);
        cudaGetSymbolAddress((void**)&wvh, g_wvh);
        cudaGetSymbolAddress((void**)&wvl, g_wvl);
        cudaGetSymbolAddress((void**)&woh, g_woh);
        cudaGetSymbolAddress((void**)&wol, g_wol);
        cudaFuncSetAttribute(flash_mma_kernel,
                             cudaFuncAttributeMaxDynamicSharedMemorySize, ASM_TOTAL);
        cudaFuncSetAttribute(gemm_qkv_kernel,
                             cudaFuncAttributeMaxDynamicSharedMemorySize, GSM_TOTAL);
        cudaFuncSetAttribute(gemm_out_kernel,
                             cudaFuncAttributeMaxDynamicSharedMemorySize, GSM_TOTAL);
        cudaGetSymbolAddress((void**)&xh, g_xh);   // last: publishes init
    }

    const int n_x4 = S_LEN * D_MODEL / 4;      // 1M float4s
    split_bf16_kernel<<<(n_x4 + 255) / 256, 256>>>(x, xh, xl, n_x4);
    split_w4_kernel<<<(4 * (1 << 18)) / 256, 256>>>(
        W_q, W_k, W_v, W_o,
        wqh, wql, wkh, wkl, wvh, wvl, woh, wol);

    dim3 qkvgrid(24, 32);
    gemm_qkv_kernel<<<qkvgrid, 256, GSM_TOTAL>>>(
        xh, xl, wqh, wql, wkh, wkl, wvh, wvl,
        qh, ql, kh, kl, vh, vl);

    dim3 agrid(S_LEN / AQT, NHEADS);          // (32, 16)
    flash_mma_kernel<<<agrid, 256, ASM_TOTAL>>>(qh, ql, kh, kl, vh, vl, ch, cl);

    dim3 ogrid(8, 32);
    gemm_out_kernel<<<ogrid, 256, GSM_TOTAL>>>(ch, cl, woh, wol, out);
}

// round 10
// speedup vs baseline: 1.0134x; 1.0134x over previous
#include <cuda_runtime.h>
#include <cuda_bf16.h>
#include <math.h>
#include <stdint.h>

// Problem constants (fixed shapes per reference)
#define S_LEN   4096
#define D_MODEL 1024
#define NHEADS  16
#define D_K     64

// ---------------------------------------------------------------------------
// Scratch (device globals; no allocation allowed)
// ---------------------------------------------------------------------------
__device__ __nv_bfloat16 g_xh[S_LEN * D_MODEL];
__device__ __nv_bfloat16 g_xl[S_LEN * D_MODEL];
__device__ __nv_bfloat16 g_ch[S_LEN * D_MODEL];
__device__ __nv_bfloat16 g_cl[S_LEN * D_MODEL];
__device__ __nv_bfloat16 g_Qh[S_LEN * D_MODEL];
__device__ __nv_bfloat16 g_Ql[S_LEN * D_MODEL];
__device__ __nv_bfloat16 g_Kh[S_LEN * D_MODEL];
__device__ __nv_bfloat16 g_Kl[S_LEN * D_MODEL];
__device__ __nv_bfloat16 g_Vh[S_LEN * D_MODEL];
__device__ __nv_bfloat16 g_Vl[S_LEN * D_MODEL];
__device__ __nv_bfloat16 g_wqh[D_MODEL * D_MODEL];
__device__ __nv_bfloat16 g_wql[D_MODEL * D_MODEL];
__device__ __nv_bfloat16 g_wkh[D_MODEL * D_MODEL];
__device__ __nv_bfloat16 g_wkl[D_MODEL * D_MODEL];
__device__ __nv_bfloat16 g_wvh[D_MODEL * D_MODEL];
__device__ __nv_bfloat16 g_wvl[D_MODEL * D_MODEL];
__device__ __nv_bfloat16 g_woh[D_MODEL * D_MODEL];
__device__ __nv_bfloat16 g_wol[D_MODEL * D_MODEL];

// ---------------------------------------------------------------------------
// PTX helpers (base sm_80+ features only — build targets plain compute_103)
// ---------------------------------------------------------------------------
__device__ __forceinline__ uint32_t smem_u32(const void* p) {
    uint32_t a;
    asm("{ .reg .u64 t; cvta.to.shared.u64 t, %1; cvt.u32.u64 %0, t; }"
        : "=r"(a) : "l"(p));
    return a;
}

__device__ __forceinline__ void cp_async16(uint32_t smem_dst, const void* gmem_src) {
    asm volatile("cp.async.cg.shared.global [%0], [%1], 16;\n"
                 :: "r"(smem_dst), "l"(gmem_src));
}

__device__ __forceinline__ void ldsm_x4(uint32_t* r, uint32_t addr) {
    asm volatile("ldmatrix.sync.aligned.m8n8.x4.shared.b16 {%0,%1,%2,%3}, [%4];"
                 : "=r"(r[0]), "=r"(r[1]), "=r"(r[2]), "=r"(r[3]) : "r"(addr));
}

__device__ __forceinline__ void ldsm_x4_t(uint32_t* r, uint32_t addr) {
    asm volatile("ldmatrix.sync.aligned.m8n8.x4.trans.shared.b16 {%0,%1,%2,%3}, [%4];"
                 : "=r"(r[0]), "=r"(r[1]), "=r"(r[2]), "=r"(r[3]) : "r"(addr));
}

__device__ __forceinline__ void mma_16816(float* d, const uint32_t* a, const uint32_t* b) {
    asm volatile(
        "mma.sync.aligned.m16n8k16.row.col.f32.bf16.bf16.f32 "
        "{%0,%1,%2,%3}, {%4,%5,%6,%7}, {%8,%9}, {%0,%1,%2,%3};"
        : "+f"(d[0]), "+f"(d[1]), "+f"(d[2]), "+f"(d[3])
        : "r"(a[0]), "r"(a[1]), "r"(a[2]), "r"(a[3]), "r"(b[0]), "r"(b[1]));
}

__device__ __forceinline__ float fast_exp2(float x) {
    float r; asm("ex2.approx.f32 %0, %1;" : "=f"(r) : "f"(x)); return r;
}

// pack two fp32 -> bf16x2 (x in low half, y in high half)
__device__ __forceinline__ uint32_t pack_bf(float x, float y) {
    uint32_t r;
    asm("cvt.rn.bf16x2.f32 %0, %1, %2;" : "=r"(r) : "f"(y), "f"(x));
    return r;
}
__device__ __forceinline__ float bf_lo(uint32_t r) { return __uint_as_float(r << 16); }
__device__ __forceinline__ float bf_hi(uint32_t r) { return __uint_as_float(r & 0xffff0000u); }

// ---------------------------------------------------------------------------
// Split fp32 -> bf16 hi/lo  (hi = bf16(x), lo = bf16(x - float(hi)))
// ---------------------------------------------------------------------------
__device__ __forceinline__ void split_one(const float* in, __nv_bfloat16* hi,
                                          __nv_bfloat16* lo, int i)
{
    float4 v = ((const float4*)in)[i];
    uint32_t h01 = pack_bf(v.x, v.y);
    uint32_t h23 = pack_bf(v.z, v.w);
    uint32_t l01 = pack_bf(v.x - bf_lo(h01), v.y - bf_hi(h01));
    uint32_t l23 = pack_bf(v.z - bf_lo(h23), v.w - bf_hi(h23));
    ((uint32_t*)hi)[i * 2 + 0] = h01;
    ((uint32_t*)hi)[i * 2 + 1] = h23;
    ((uint32_t*)lo)[i * 2 + 0] = l01;
    ((uint32_t*)lo)[i * 2 + 1] = l23;
}

__global__ void split_bf16_kernel(const float* __restrict__ in,
                                  __nv_bfloat16* __restrict__ hi,
                                  __nv_bfloat16* __restrict__ lo, int n4)
{
    int i = blockIdx.x * blockDim.x + threadIdx.x;
    if (i >= n4) return;
    split_one(in, hi, lo, i);
}

// All 4 weight matrices in one launch; idx>>18 routes (n_w4 = 2^18).
__global__ void split_w4_kernel(
    const float* __restrict__ w0, const float* __restrict__ w1,
    const float* __restrict__ w2, const float* __restrict__ w3,
    __nv_bfloat16* __restrict__ h0, __nv_bfloat16* __restrict__ l0,
    __nv_bfloat16* __restrict__ h1, __nv_bfloat16* __restrict__ l1,
    __nv_bfloat16* __restrict__ h2, __nv_bfloat16* __restrict__ l2,
    __nv_bfloat16* __restrict__ h3, __nv_bfloat16* __restrict__ l3)
{
    int idx = blockIdx.x * blockDim.x + threadIdx.x;
    int sel = idx >> 18;
    int i   = idx & ((1 << 18) - 1);
    const float* in = sel == 0 ? w0 : sel == 1 ? w1 : sel == 2 ? w2 : w3;
    __nv_bfloat16* hi = sel == 0 ? h0 : sel == 1 ? h1 : sel == 2 ? h2 : h3;
    __nv_bfloat16* lo = sel == 0 ? l0 : sel == 1 ? l1 : sel == 2 ? l2 : l3;
    split_one(in, hi, lo, i);
}

// ---------------------------------------------------------------------------
// Tensor-core GEMM body (HMMA, bf16, fp32 acc):
//   acc = Ahi*Bhi^T + Ahi*Blo^T + Alo*Bhi^T  over K=1024, tile 128x128
// ---------------------------------------------------------------------------
#define GK     1024
#define GBK    32
#define ROWB   80
#define TILEB  (128 * ROWB)     // 10240
#define SETB   (4 * TILEB)      // 40960 per stage
#define GSM_TOTAL (2 * SETB)    // 81920
#define NKCH   32

__device__ __forceinline__ void load_chunk4(
    const __nv_bfloat16* __restrict__ Ah, const __nv_bfloat16* __restrict__ Al,
    const __nv_bfloat16* __restrict__ Bh, const __nv_bfloat16* __restrict__ Bl,
    int bm, int bn, int k0, uint32_t dst, int tid)
{
#pragma unroll
    for (int t = 0; t < 2; t++) {
        int u = tid + t * 256;
        int r = u >> 2;
        int c = (u & 3) * 16;
        size_t ao = (size_t)(bm + r) * GK + k0;
        size_t bo = (size_t)(bn + r) * GK + k0;
        uint32_t so = (uint32_t)(r * ROWB + c);
        cp_async16(dst + so,             (const char*)(Ah + ao) + c);
        cp_async16(dst + TILEB + so,     (const char*)(Al + ao) + c);
        cp_async16(dst + 2 * TILEB + so, (const char*)(Bh + bo) + c);
        cp_async16(dst + 3 * TILEB + so, (const char*)(Bl + bo) + c);
    }
    asm volatile("cp.async.commit_group;\n" ::: "memory");
}

__device__ __forceinline__ void gemm_body(
    const __nv_bfloat16* __restrict__ A_hi, const __nv_bfloat16* __restrict__ A_lo,
    const __nv_bfloat16* __restrict__ B_hi, const __nv_bfloat16* __restrict__ B_lo,
    int bm, int bn, uint32_t sb, float acc[2][8][4])
{
    const int tid  = threadIdx.x;
    const int lane = tid & 31;
    const int w    = tid >> 5;
    const int m_off = (w & 3) * 32;
    const int n_off = (w >> 2) * 64;

#pragma unroll
    for (int mt = 0; mt < 2; mt++)
#pragma unroll
        for (int nt = 0; nt < 8; nt++)
#pragma unroll
            for (int i = 0; i < 4; i++) acc[mt][nt][i] = 0.0f;

    const uint32_t a_off = (uint32_t)((m_off + (lane & 15)) * ROWB + 16 * (lane >> 4));
    const uint32_t b_off = (uint32_t)((n_off + (lane & 7) + 8 * (lane >> 4)) * ROWB
                                      + 16 * ((lane >> 3) & 1));

    load_chunk4(A_hi, A_lo, B_hi, B_lo, bm, bn, 0,   sb,        tid);
    load_chunk4(A_hi, A_lo, B_hi, B_lo, bm, bn, GBK, sb + SETB, tid);

    for (int i = 0; i < NKCH; i++) {
        if (i + 1 < NKCH) {
            asm volatile("cp.async.wait_group 1;\n" ::: "memory");
        } else {
            asm volatile("cp.async.wait_group 0;\n" ::: "memory");
        }
        __syncthreads();

        const uint32_t base = sb + (uint32_t)(i & 1) * SETB;
#pragma unroll
        for (int ks = 0; ks < 2; ks++) {
            uint32_t ah[2][4], al[2][4];
#pragma unroll
            for (int mt = 0; mt < 2; mt++) {
                uint32_t aadr = base + a_off + (uint32_t)(mt * 16 * ROWB + ks * 32);
                ldsm_x4(ah[mt], aadr);
                ldsm_x4(al[mt], aadr + TILEB);
            }
            uint32_t b2[8][2];
#pragma unroll
            for (int np = 0; np < 4; np++) {
                uint32_t r4[4];
                ldsm_x4(r4, base + 2 * TILEB + b_off + (uint32_t)(np * 16 * ROWB + ks * 32));
                b2[2*np][0] = r4[0]; b2[2*np][1] = r4[1];
                b2[2*np+1][0] = r4[2]; b2[2*np+1][1] = r4[3];
            }
#pragma unroll
            for (int mt = 0; mt < 2; mt++)
#pragma unroll
                for (int nt = 0; nt < 8; nt++) {
                    mma_16816(acc[mt][nt], ah[mt], b2[nt]);
                    mma_16816(acc[mt][nt], al[mt], b2[nt]);
                }
#pragma unroll
            for (int np = 0; np < 4; np++) {
                uint32_t r4[4];
                ldsm_x4(r4, base + 3 * TILEB + b_off + (uint32_t)(np * 16 * ROWB + ks * 32));
                b2[2*np][0] = r4[0]; b2[2*np][1] = r4[1];
                b2[2*np+1][0] = r4[2]; b2[2*np+1][1] = r4[3];
            }
#pragma unroll
            for (int mt = 0; mt < 2; mt++)
#pragma unroll
                for (int nt = 0; nt < 8; nt++)
                    mma_16816(acc[mt][nt], ah[mt], b2[nt]);
        }
        __syncthreads();

        if (i + 2 < NKCH)
            load_chunk4(A_hi, A_lo, B_hi, B_lo, bm, bn, (i + 2) * GBK, base, tid);
    }
}

// Fused QKV: blockIdx.x in [0,24); sel = bx>>3 routes weight/output.
__global__ __launch_bounds__(256, 2) void gemm_qkv_kernel(
    const __nv_bfloat16* __restrict__ A_hi, const __nv_bfloat16* __restrict__ A_lo,
    const __nv_bfloat16* __restrict__ Wqh, const __nv_bfloat16* __restrict__ Wql,
    const __nv_bfloat16* __restrict__ Wkh, const __nv_bfloat16* __restrict__ Wkl,
    const __nv_bfloat16* __restrict__ Wvh, const __nv_bfloat16* __restrict__ Wvl,
    __nv_bfloat16* __restrict__ Qh, __nv_bfloat16* __restrict__ Ql,
    __nv_bfloat16* __restrict__ Kh, __nv_bfloat16* __restrict__ Kl,
    __nv_bfloat16* __restrict__ Vh, __nv_bfloat16* __restrict__ Vl)
{
    extern __shared__ __align__(16) char gsm[];
    const uint32_t sb = smem_u32(gsm);
    const int sel = blockIdx.x >> 3;
    const int bn  = (blockIdx.x & 7) * 128;
    const int bm  = blockIdx.y * 128;
    const __nv_bfloat16* Bh = sel == 0 ? Wqh : sel == 1 ? Wkh : Wvh;
    const __nv_bfloat16* Bl = sel == 0 ? Wql : sel == 1 ? Wkl : Wvl;
    __nv_bfloat16* Ch = sel == 0 ? Qh : sel == 1 ? Kh : Vh;
    __nv_bfloat16* Cl = sel == 0 ? Ql : sel == 1 ? Kl : Vl;

    float acc[2][8][4];
    gemm_body(A_hi, A_lo, Bh, Bl, bm, bn, sb, acc);

    const int lane = threadIdx.x & 31;
    const int w    = threadIdx.x >> 5;
    const int m_off = (w & 3) * 32;
    const int n_off = (w >> 2) * 64;
    const int g = lane >> 2;
    const int q = lane & 3;
#pragma unroll
    for (int mt = 0; mt < 2; mt++) {
#pragma unroll
        for (int nt = 0; nt < 8; nt++) {
            int row = bm + m_off + mt * 16 + g;
            int col = bn + n_off + nt * 8 + q * 2;
            uint32_t h0 = pack_bf(acc[mt][nt][0], acc[mt][nt][1]);
            uint32_t l0 = pack_bf(acc[mt][nt][0] - bf_lo(h0),
                                  acc[mt][nt][1] - bf_hi(h0));
            *(uint32_t*)(Ch + (size_t)row * D_MODEL + col) = h0;
            *(uint32_t*)(Cl + (size_t)row * D_MODEL + col) = l0;
            uint32_t h1 = pack_bf(acc[mt][nt][2], acc[mt][nt][3]);
            uint32_t l1 = pack_bf(acc[mt][nt][2] - bf_lo(h1),
                                  acc[mt][nt][3] - bf_hi(h1));
            *(uint32_t*)(Ch + (size_t)(row + 8) * D_MODEL + col) = h1;
            *(uint32_t*)(Cl + (size_t)(row + 8) * D_MODEL + col) = l1;
        }
    }
}

// Output GEMM: fp32 C
__global__ __launch_bounds__(256, 2) void gemm_out_kernel(
    const __nv_bfloat16* __restrict__ A_hi, const __nv_bfloat16* __restrict__ A_lo,
    const __nv_bfloat16* __restrict__ B_hi, const __nv_bfloat16* __restrict__ B_lo,
    float* __restrict__ Cf)
{
    extern __shared__ __align__(16) char gsm[];
    const uint32_t sb = smem_u32(gsm);
    const int bn = blockIdx.x * 128;
    const int bm = blockIdx.y * 128;

    float acc[2][8][4];
    gemm_body(A_hi, A_lo, B_hi, B_lo, bm, bn, sb, acc);

    const int lane = threadIdx.x & 31;
    const int w    = threadIdx.x >> 5;
    const int m_off = (w & 3) * 32;
    const int n_off = (w >> 2) * 64;
    const int g = lane >> 2;
    const int q = lane & 3;
#pragma unroll
    for (int mt = 0; mt < 2; mt++) {
#pragma unroll
        for (int nt = 0; nt < 8; nt++) {
            int row = bm + m_off + mt * 16 + g;
            int col = bn + n_off + nt * 8 + q * 2;
            *(float2*)(Cf + (size_t)row * D_MODEL + col) =
                make_float2(acc[mt][nt][0], acc[mt][nt][1]);
            *(float2*)(Cf + (size_t)(row + 8) * D_MODEL + col) =
                make_float2(acc[mt][nt][2], acc[mt][nt][3]);
        }
    }
}

// ---------------------------------------------------------------------------
// Tensor-core causal flash attention, software-pipelined softmax:
// per pair of 32-key tiles: scores(S0), scores(S1) back-to-back (96 HMMA run),
// then stats(S0), stats(S1), rescale+PV(S0), rescale+PV(S1). PV(S0)'s MMAs
// are independent of stats(S1)'s ALU => tensor pipe stays fed through softmax.
// Numerics identical to R6 (3-term scores, 3-term PV).
// ---------------------------------------------------------------------------
#define AQT 128
#define AKT 32
#define AROWB 144
#define AQ_BYTES   (128 * AROWB)       // 18432
#define AKV_BYTES  (32 * AROWB)        // 4608 per tile component
#define ASET_BYTES (4 * AKV_BYTES)     // 18432 per stage (Kh,Kl,Vh,Vl)
#define ANSTAGE    4
#define ASM_KV0    (2 * AQ_BYTES)      // 36864
#define ASM_TOTAL  (ASM_KV0 + ANSTAGE * ASET_BYTES)   // 110592

#define FA_C1 0.18033688011112042f   // log2(e) / sqrt(64)

__device__ __forceinline__ void load_kv_tile_nc(
    const __nv_bfloat16* __restrict__ Kh, const __nv_bfloat16* __restrict__ Kl,
    const __nv_bfloat16* __restrict__ Vh, const __nv_bfloat16* __restrict__ Vl,
    int k0, int h, uint32_t base, int tid)
{
    int r = tid >> 3, c = tid & 7;
    uint32_t so = (uint32_t)(r * AROWB + c * 16);
    size_t  go = (size_t)(k0 + r) * D_MODEL + h * D_K + c * 8;
    cp_async16(base + 0 * AKV_BYTES + so, Kh + go);
    cp_async16(base + 1 * AKV_BYTES + so, Kl + go);
    cp_async16(base + 2 * AKV_BYTES + so, Vh + go);
    cp_async16(base + 3 * AKV_BYTES + so, Vl + go);
}

// scores S[4][4] for one 32-key tile (3-term split)
__device__ __forceinline__ void fa_scores(
    float S[4][4], uint32_t kvb, uint32_t q_base, uint32_t k_base)
{
#pragma unroll
    for (int nt = 0; nt < 4; nt++)
#pragma unroll
        for (int i = 0; i < 4; i++) S[nt][i] = 0.f;

#pragma unroll
    for (int ks = 0; ks < 4; ks++) {
        uint32_t qa[4], qla[4];
        uint32_t qaddr = q_base + (uint32_t)(ks * 32);
        ldsm_x4(qa, qaddr);
        ldsm_x4(qla, qaddr + AQ_BYTES);

        uint32_t b2[4][2];
#pragma unroll
        for (int np = 0; np < 2; np++) {
            uint32_t r4[4];
            ldsm_x4(r4, kvb + k_base + (uint32_t)(np * 16 * AROWB + ks * 32));
            b2[2*np][0] = r4[0]; b2[2*np][1] = r4[1];
            b2[2*np+1][0] = r4[2]; b2[2*np+1][1] = r4[3];
        }
#pragma unroll
        for (int nt = 0; nt < 4; nt++) {
            mma_16816(S[nt], qa,  b2[nt]);
            mma_16816(S[nt], qla, b2[nt]);
        }
#pragma unroll
        for (int np = 0; np < 2; np++) {
            uint32_t r4[4];
            ldsm_x4(r4, kvb + AKV_BYTES + k_base + (uint32_t)(np * 16 * AROWB + ks * 32));
            b2[2*np][0] = r4[0]; b2[2*np][1] = r4[1];
            b2[2*np+1][0] = r4[2]; b2[2*np+1][1] = r4[3];
        }
#pragma unroll
        for (int nt = 0; nt < 4; nt++)
            mma_16816(S[nt], qa, b2[nt]);
    }
}

// online-softmax stats: updates m_i/l_i, converts S -> P, emits rescale f[2]
__device__ __forceinline__ void fa_stats(
    float S[4][4], float m_i[2], float l_i[2], float f[2])
{
#pragma unroll
    for (int hf = 0; hf < 2; hf++) {
        float mx = -1e30f;
#pragma unroll
        for (int nt = 0; nt < 4; nt++)
            mx = fmaxf(mx, fmaxf(S[nt][2*hf], S[nt][2*hf+1]));
        mx = fmaxf(mx, __shfl_xor_sync(0xffffffffu, mx, 1));
        mx = fmaxf(mx, __shfl_xor_sync(0xffffffffu, mx, 2));
        float mold = m_i[hf];
        float mnew = fmaxf(mold, mx);
        f[hf] = fast_exp2((mold - mnew) * FA_C1);
        float nm = mnew * FA_C1;
        float sum = 0.f;
#pragma unroll
        for (int nt = 0; nt < 4; nt++) {
            float p0 = fast_exp2(fmaf(S[nt][2*hf],   FA_C1, -nm));
            float p1 = fast_exp2(fmaf(S[nt][2*hf+1], FA_C1, -nm));
            S[nt][2*hf] = p0; S[nt][2*hf+1] = p1;
            sum += p0 + p1;
        }
        sum += __shfl_xor_sync(0xffffffffu, sum, 1);
        sum += __shfl_xor_sync(0xffffffffu, sum, 2);
        l_i[hf] = l_i[hf] * f[hf] + sum;
        m_i[hf] = mnew;
    }
}

// O *= f, then O += P*V (3-term split)
__device__ __forceinline__ void fa_pv(
    float O[8][4], float S[4][4], const float f[2], uint32_t kvb, uint32_t v_base)
{
#pragma unroll
    for (int no = 0; no < 8; no++) {
        O[no][0] *= f[0]; O[no][1] *= f[0];
        O[no][2] *= f[1]; O[no][3] *= f[1];
    }
#pragma unroll
    for (int j = 0; j < 2; j++) {
        uint32_t ph[4], pl[4];
        ph[0] = pack_bf(S[2*j][0],   S[2*j][1]);
        ph[1] = pack_bf(S[2*j][2],   S[2*j][3]);
        ph[2] = pack_bf(S[2*j+1][0], S[2*j+1][1]);
        ph[3] = pack_bf(S[2*j+1][2], S[2*j+1][3]);
        pl[0] = pack_bf(S[2*j][0]   - bf_lo(ph[0]), S[2*j][1]   - bf_hi(ph[0]));
        pl[1] = pack_bf(S[2*j][2]   - bf_lo(ph[1]), S[2*j][3]   - bf_hi(ph[1]));
        pl[2] = pack_bf(S[2*j+1][0] - bf_lo(ph[2]), S[2*j+1][1] - bf_hi(ph[2]));
        pl[3] = pack_bf(S[2*j+1][2] - bf_lo(ph[3]), S[2*j+1][3] - bf_hi(ph[3]));

        uint32_t v2[8][2];
#pragma unroll
        for (int np = 0; np < 4; np++) {
            uint32_t r4[4];
            ldsm_x4_t(r4, kvb + 2 * AKV_BYTES + v_base
                          + (uint32_t)(j * 16 * AROWB + np * 32));
            v2[2*np][0] = r4[0]; v2[2*np][1] = r4[1];
            v2[2*np+1][0] = r4[2]; v2[2*np+1][1] = r4[3];
        }
#pragma unroll
        for (int no = 0; no < 8; no++) {
            mma_16816(O[no], ph, v2[no]);
            mma_16816(O[no], pl, v2[no]);
        }
#pragma unroll
        for (int np = 0; np < 4; np++) {
            uint32_t r4[4];
            ldsm_x4_t(r4, kvb + 3 * AKV_BYTES + v_base
                          + (uint32_t)(j * 16 * AROWB + np * 32));
            v2[2*np][0] = r4[0]; v2[2*np][1] = r4[1];
            v2[2*np+1][0] = r4[2]; v2[2*np+1][1] = r4[3];
        }
#pragma unroll
        for (int no = 0; no < 8; no++)
            mma_16816(O[no], ph, v2[no]);
    }
}

__device__ __forceinline__ void fa_mask(
    float S[4][4], int k0, int q0, int m_off, int g, int qd)
{
    if (k0 + AKT > q0) {
        int qg0 = q0 + m_off + g;
#pragma unroll
        for (int nt = 0; nt < 4; nt++) {
            int kg = k0 + nt * 8 + 2 * qd;
            if (kg     > qg0)     S[nt][0] = -1e30f;
            if (kg + 1 > qg0)     S[nt][1] = -1e30f;
            if (kg     > qg0 + 8) S[nt][2] = -1e30f;
            if (kg + 1 > qg0 + 8) S[nt][3] = -1e30f;
        }
    }
}

__global__ __launch_bounds__(256, 2) void flash_mma_kernel(
    const __nv_bfloat16* __restrict__ Qh, const __nv_bfloat16* __restrict__ Ql,
    const __nv_bfloat16* __restrict__ Kh, const __nv_bfloat16* __restrict__ Kl,
    const __nv_bfloat16* __restrict__ Vh, const __nv_bfloat16* __restrict__ Vl,
    __nv_bfloat16* __restrict__ Ch, __nv_bfloat16* __restrict__ Cl)
{
    extern __shared__ char smem[];
    const uint32_t sb = smem_u32(smem);
    const int tid  = threadIdx.x;
    const int lane = tid & 31;
    const int wid  = tid >> 5;
    const int m_off = wid * 16;          // 8 warps x 16 rows
    const int h  = blockIdx.y;
    const int q0 = (int)(gridDim.x - 1 - blockIdx.x) * AQT;   // heavy blocks first
    const int g  = lane >> 2;
    const int qd = lane & 3;

    // Stage Q (hi at +0, lo at +AQ_BYTES): 8 x 16B per thread
#pragma unroll
    for (int t = 0; t < 8; t++) {
        const __nv_bfloat16* src = (t < 4) ? Qh : Ql;
        int v = (t & 3) * 256 + tid;        // 0..1023
        int r = v >> 3, c = v & 7;
        cp_async16(sb + (t >> 2) * AQ_BYTES + r * AROWB + c * 16,
                   src + (size_t)(q0 + r) * D_MODEL + h * D_K + c * 8);
    }
    asm volatile("cp.async.commit_group;\n" ::: "memory");

    const int ntiles = q0 / AKT + AQT / AKT;   // multiple of 4
    const int npairs = ntiles / 2;             // >= 2

    // preload pairs 0 and 1 (one cp.async group each)
    load_kv_tile_nc(Kh, Kl, Vh, Vl, 0 * AKT, h, sb + ASM_KV0 + 0 * ASET_BYTES, tid);
    load_kv_tile_nc(Kh, Kl, Vh, Vl, 1 * AKT, h, sb + ASM_KV0 + 1 * ASET_BYTES, tid);
    asm volatile("cp.async.commit_group;\n" ::: "memory");
    load_kv_tile_nc(Kh, Kl, Vh, Vl, 2 * AKT, h, sb + ASM_KV0 + 2 * ASET_BYTES, tid);
    load_kv_tile_nc(Kh, Kl, Vh, Vl, 3 * AKT, h, sb + ASM_KV0 + 3 * ASET_BYTES, tid);
    asm volatile("cp.async.commit_group;\n" ::: "memory");

    float m_i[2] = { -1e30f, -1e30f };
    float l_i[2] = { 0.f, 0.f };
    float O[8][4];
#pragma unroll
    for (int no = 0; no < 8; no++)
#pragma unroll
        for (int i = 0; i < 4; i++) O[no][i] = 0.f;

    // per-thread fragment offsets (tile-invariant)
    const uint32_t q_base = sb + (uint32_t)((m_off + (lane & 15)) * AROWB + 16 * (lane >> 4));
    const uint32_t k_base = (uint32_t)(((lane & 7) + 8 * (lane >> 4)) * AROWB
                                       + 16 * ((lane >> 3) & 1));
    const uint32_t v_base = (uint32_t)(((lane & 7) + 8 * ((lane >> 3) & 1)) * AROWB
                                       + 16 * (lane >> 4));

    for (int p = 0; p < npairs; p++) {
        asm volatile("cp.async.wait_group 0;\n" ::: "memory");
        __syncthreads();

        // issue pair p+1's load into the half freed by pair p-1 (WAR-safe)
        if (p >= 1 && p + 1 < npairs) {
            int t0n = 2 * (p + 1);
            load_kv_tile_nc(Kh, Kl, Vh, Vl, t0n * AKT, h,
                            sb + ASM_KV0 + (uint32_t)(t0n & 3) * ASET_BYTES, tid);
            load_kv_tile_nc(Kh, Kl, Vh, Vl, (t0n + 1) * AKT, h,
                            sb + ASM_KV0 + (uint32_t)((t0n + 1) & 3) * ASET_BYTES, tid);
            asm volatile("cp.async.commit_group;\n" ::: "memory");
        }

        const int t0 = 2 * p, t1 = 2 * p + 1;
        const uint32_t kvb0 = sb + ASM_KV0 + (uint32_t)(t0 & 3) * ASET_BYTES;
        const uint32_t kvb1 = sb + ASM_KV0 + (uint32_t)(t1 & 3) * ASET_BYTES;

        // ---- back-to-back score MMAs for both tiles (96 HMMA run) ----
        float S0[4][4], S1[4][4];
        fa_scores(S0, kvb0, q_base, k_base);
        fa_scores(S1, kvb1, q_base, k_base);
        fa_mask(S0, t0 * AKT, q0, m_off, g, qd);
        fa_mask(S1, t1 * AKT, q0, m_off, g, qd);

        // ---- stats (ALU) for both tiles; PV0's MMAs independent of stats1 ----
        float f0[2], f1[2];
        fa_stats(S0, m_i, l_i, f0);
        fa_stats(S1, m_i, l_i, f1);

        fa_pv(O, S0, f0, kvb0, v_base);
        fa_pv(O, S1, f1, kvb1, v_base);
    }

    // ---- epilogue: normalize + write bf16 hi/lo context ----
    {
        float inv0 = 1.f / l_i[0];
        float inv1 = 1.f / l_i[1];
        int r0 = q0 + m_off + g;
#pragma unroll
        for (int no = 0; no < 8; no++) {
            int col = h * D_K + no * 8 + 2 * qd;
            float o0 = O[no][0] * inv0, o1 = O[no][1] * inv0;
            float o2 = O[no][2] * inv1, o3 = O[no][3] * inv1;
            uint32_t h0 = pack_bf(o0, o1);
            uint32_t l0 = pack_bf(o0 - bf_lo(h0), o1 - bf_hi(h0));
            *(uint32_t*)(Ch + (size_t)r0 * D_MODEL + col) = h0;
            *(uint32_t*)(Cl + (size_t)r0 * D_MODEL + col) = l0;
            uint32_t h1 = pack_bf(o2, o3);
            uint32_t l1 = pack_bf(o2 - bf_lo(h1), o3 - bf_hi(h1));
            *(uint32_t*)(Ch + (size_t)(r0 + 8) * D_MODEL + col) = h1;
            *(uint32_t*)(Cl + (size_t)(r0 + 8) * D_MODEL + col) = l1;
        }
    }
}

// ---------------------------------------------------------------------------
// Launch
// ---------------------------------------------------------------------------
extern "C" void kernel_launch(void* const* d_in, const int* in_sizes, int n_in,
                              void* d_out, int out_size)
{
    const float* x   = (const float*)d_in[0];
    const float* W_q = (const float*)d_in[1];
    const float* W_k = (const float*)d_in[2];
    const float* W_v = (const float*)d_in[3];
    const float* W_o = (const float*)d_in[4];
    float* out = (float*)d_out;

    static __nv_bfloat16* xh = nullptr;
    static __nv_bfloat16 *xl, *ch, *cl, *qh, *ql, *kh, *kl, *vh, *vl;
    static __nv_bfloat16 *wqh, *wql, *wkh, *wkl, *wvh, *wvl, *woh, *wol;
    if (xh == nullptr) {
        cudaGetSymbolAddress((void**)&xl, g_xl);
        cudaGetSymbolAddress((void**)&ch, g_ch);
        cudaGetSymbolAddress((void**)&cl, g_cl);
        cudaGetSymbolAddress((void**)&qh, g_Qh);
        cudaGetSymbolAddress((void**)&ql, g_Ql);
        cudaGetSymbolAddress((void**)&kh, g_Kh);
        cudaGetSymbolAddress((void**)&kl, g_Kl);
        cudaGetSymbolAddress((void**)&vh, g_Vh);
        cudaGetSymbolAddress((void**)&vl, g_Vl);
        cudaGetSymbolAddress((void**)&wqh, g_wqh);
        cudaGetSymbolAddress((void**)&wql, g_wql);
        cudaGetSymbolAddress((void**)&wkh, g_wkh);
        cudaGetSymbolAddress((void**)&wkl, g_wkl);
        cudaGetSymbolAddress((void**)&wvh, g_wvh);
        cudaGetSymbolAddress((void**)&wvl, g_wvl);
        cudaGetSymbolAddress((void**)&woh, g_woh);
        cudaGetSymbolAddress((void**)&wol, g_wol);
        cudaFuncSetAttribute(flash_mma_kernel,
                             cudaFuncAttributeMaxDynamicSharedMemorySize, ASM_TOTAL);
        cudaFuncSetAttribute(gemm_qkv_kernel,
                             cudaFuncAttributeMaxDynamicSharedMemorySize, GSM_TOTAL);
        cudaFuncSetAttribute(gemm_out_kernel,
                             cudaFuncAttributeMaxDynamicSharedMemorySize, GSM_TOTAL);
        cudaGetSymbolAddress((void**)&xh, g_xh);   // last: publishes init
    }

    const int n_x4 = S_LEN * D_MODEL / 4;      // 1M float4s
    split_bf16_kernel<<<(n_x4 + 255) / 256, 256>>>(x, xh, xl, n_x4);
    split_w4_kernel<<<(4 * (1 << 18)) / 256, 256>>>(
        W_q, W_k, W_v, W_o,
        wqh, wql, wkh, wkl, wvh, wvl, woh, wol);

    dim3 qkvgrid(24, 32);
    gemm_qkv_kernel<<<qkvgrid, 256, GSM_TOTAL>>>(
        xh, xl, wqh, wql, wkh, wkl, wvh, wvl,
        qh, ql, kh, kl, vh, vl);

    dim3 agrid(S_LEN / AQT, NHEADS);          // (32, 16)
    flash_mma_kernel<<<agrid, 256, ASM_TOTAL>>>(qh, ql, kh, kl, vh, vl, ch, cl);

    dim3 ogrid(8, 32);
    gemm_out_kernel<<<ogrid, 256, GSM_TOTAL>>>(ch, cl, woh, wol, out);
}

// round 11
// speedup vs baseline: 1.1996x; 1.1837x over previous
#include <cuda_runtime.h>
#include <cuda_bf16.h>
#include <cuda_fp16.h>
#include <math.h>
#include <stdint.h>

// Problem constants (fixed shapes per reference)
#define S_LEN   4096
#define D_MODEL 1024
#define NHEADS  16
#define D_K     64

// ---------------------------------------------------------------------------
// Scratch (device globals; no allocation allowed)
// ---------------------------------------------------------------------------
__device__ __nv_bfloat16 g_xh[S_LEN * D_MODEL];
__device__ __nv_bfloat16 g_xl[S_LEN * D_MODEL];
__device__ __nv_bfloat16 g_ch[S_LEN * D_MODEL];
__device__ __nv_bfloat16 g_cl[S_LEN * D_MODEL];
__device__ __half g_Qh[S_LEN * D_MODEL];
__device__ __half g_Ql[S_LEN * D_MODEL];
__device__ __half g_Kh[S_LEN * D_MODEL];
__device__ __half g_Kl[S_LEN * D_MODEL];
__device__ __half g_Vf[S_LEN * D_MODEL];
__device__ __nv_bfloat16 g_wqh[D_MODEL * D_MODEL];
__device__ __nv_bfloat16 g_wql[D_MODEL * D_MODEL];
__device__ __nv_bfloat16 g_wkh[D_MODEL * D_MODEL];
__device__ __nv_bfloat16 g_wkl[D_MODEL * D_MODEL];
__device__ __nv_bfloat16 g_wvh[D_MODEL * D_MODEL];
__device__ __nv_bfloat16 g_wvl[D_MODEL * D_MODEL];
__device__ __nv_bfloat16 g_woh[D_MODEL * D_MODEL];
__device__ __nv_bfloat16 g_wol[D_MODEL * D_MODEL];

// ---------------------------------------------------------------------------
// PTX helpers (base sm_80+ features only — build targets plain compute_103)
// ---------------------------------------------------------------------------
__device__ __forceinline__ uint32_t smem_u32(const void* p) {
    uint32_t a;
    asm("{ .reg .u64 t; cvta.to.shared.u64 t, %1; cvt.u32.u64 %0, t; }"
        : "=r"(a) : "l"(p));
    return a;
}

__device__ __forceinline__ void cp_async16(uint32_t smem_dst, const void* gmem_src) {
    asm volatile("cp.async.cg.shared.global [%0], [%1], 16;\n"
                 :: "r"(smem_dst), "l"(gmem_src));
}

__device__ __forceinline__ void ldsm_x4(uint32_t* r, uint32_t addr) {
    asm volatile("ldmatrix.sync.aligned.m8n8.x4.shared.b16 {%0,%1,%2,%3}, [%4];"
                 : "=r"(r[0]), "=r"(r[1]), "=r"(r[2]), "=r"(r[3]) : "r"(addr));
}

__device__ __forceinline__ void ldsm_x4_t(uint32_t* r, uint32_t addr) {
    asm volatile("ldmatrix.sync.aligned.m8n8.x4.trans.shared.b16 {%0,%1,%2,%3}, [%4];"
                 : "=r"(r[0]), "=r"(r[1]), "=r"(r[2]), "=r"(r[3]) : "r"(addr));
}

// bf16 MMA (projection GEMMs)
__device__ __forceinline__ void mma_16816(float* d, const uint32_t* a, const uint32_t* b) {
    asm volatile(
        "mma.sync.aligned.m16n8k16.row.col.f32.bf16.bf16.f32 "
        "{%0,%1,%2,%3}, {%4,%5,%6,%7}, {%8,%9}, {%0,%1,%2,%3};"
        : "+f"(d[0]), "+f"(d[1]), "+f"(d[2]), "+f"(d[3])
        : "r"(a[0]), "r"(a[1]), "r"(a[2]), "r"(a[3]), "r"(b[0]), "r"(b[1]));
}

// fp16 MMA (attention)
__device__ __forceinline__ void mma_16816_f16(float* d, const uint32_t* a, const uint32_t* b) {
    asm volatile(
        "mma.sync.aligned.m16n8k16.row.col.f32.f16.f16.f32 "
        "{%0,%1,%2,%3}, {%4,%5,%6,%7}, {%8,%9}, {%0,%1,%2,%3};"
        : "+f"(d[0]), "+f"(d[1]), "+f"(d[2]), "+f"(d[3])
        : "r"(a[0]), "r"(a[1]), "r"(a[2]), "r"(a[3]), "r"(b[0]), "r"(b[1]));
}

__device__ __forceinline__ float fast_exp2(float x) {
    float r; asm("ex2.approx.f32 %0, %1;" : "=f"(r) : "f"(x)); return r;
}

// pack two fp32 -> bf16x2 (x in low half, y in high half)
__device__ __forceinline__ uint32_t pack_bf(float x, float y) {
    uint32_t r;
    asm("cvt.rn.bf16x2.f32 %0, %1, %2;" : "=r"(r) : "f"(y), "f"(x));
    return r;
}
__device__ __forceinline__ float bf_lo(uint32_t r) { return __uint_as_float(r << 16); }
__device__ __forceinline__ float bf_hi(uint32_t r) { return __uint_as_float(r & 0xffff0000u); }

// pack two fp32 -> fp16x2 (x in low half, y in high half)
__device__ __forceinline__ uint32_t pack_f16(float x, float y) {
    uint32_t r;
    asm("cvt.rn.f16x2.f32 %0, %1, %2;" : "=r"(r) : "f"(y), "f"(x));
    return r;
}
__device__ __forceinline__ float f16_lo(uint32_t r) {
    float f;
    asm("{ .reg .f16 a, b; mov.b32 {a, b}, %1; cvt.f32.f16 %0, a; }" : "=f"(f) : "r"(r));
    return f;
}
__device__ __forceinline__ float f16_hi(uint32_t r) {
    float f;
    asm("{ .reg .f16 a, b; mov.b32 {a, b}, %1; cvt.f32.f16 %0, b; }" : "=f"(f) : "r"(r));
    return f;
}

// ---------------------------------------------------------------------------
// Split fp32 -> bf16 hi/lo  (hi = bf16(x), lo = bf16(x - float(hi)))
// ---------------------------------------------------------------------------
__device__ __forceinline__ void split_one(const float* in, __nv_bfloat16* hi,
                                          __nv_bfloat16* lo, int i)
{
    float4 v = ((const float4*)in)[i];
    uint32_t h01 = pack_bf(v.x, v.y);
    uint32_t h23 = pack_bf(v.z, v.w);
    uint32_t l01 = pack_bf(v.x - bf_lo(h01), v.y - bf_hi(h01));
    uint32_t l23 = pack_bf(v.z - bf_lo(h23), v.w - bf_hi(h23));
    ((uint32_t*)hi)[i * 2 + 0] = h01;
    ((uint32_t*)hi)[i * 2 + 1] = h23;
    ((uint32_t*)lo)[i * 2 + 0] = l01;
    ((uint32_t*)lo)[i * 2 + 1] = l23;
}

__global__ void split_bf16_kernel(const float* __restrict__ in,
                                  __nv_bfloat16* __restrict__ hi,
                                  __nv_bfloat16* __restrict__ lo, int n4)
{
    int i = blockIdx.x * blockDim.x + threadIdx.x;
    if (i >= n4) return;
    split_one(in, hi, lo, i);
}

// All 4 weight matrices in one launch; idx>>18 routes (n_w4 = 2^18).
__global__ void split_w4_kernel(
    const float* __restrict__ w0, const float* __restrict__ w1,
    const float* __restrict__ w2, const float* __restrict__ w3,
    __nv_bfloat16* __restrict__ h0, __nv_bfloat16* __restrict__ l0,
    __nv_bfloat16* __restrict__ h1, __nv_bfloat16* __restrict__ l1,
    __nv_bfloat16* __restrict__ h2, __nv_bfloat16* __restrict__ l2,
    __nv_bfloat16* __restrict__ h3, __nv_bfloat16* __restrict__ l3)
{
    int idx = blockIdx.x * blockDim.x + threadIdx.x;
    int sel = idx >> 18;
    int i   = idx & ((1 << 18) - 1);
    const float* in = sel == 0 ? w0 : sel == 1 ? w1 : sel == 2 ? w2 : w3;
    __nv_bfloat16* hi = sel == 0 ? h0 : sel == 1 ? h1 : sel == 2 ? h2 : h3;
    __nv_bfloat16* lo = sel == 0 ? l0 : sel == 1 ? l1 : sel == 2 ? l2 : l3;
    split_one(in, hi, lo, i);
}

// ---------------------------------------------------------------------------
// Tensor-core GEMM body (HMMA, bf16, fp32 acc):
//   acc = Ahi*Bhi^T + Ahi*Blo^T + Alo*Bhi^T  over K=1024, tile 128x128
// ---------------------------------------------------------------------------
#define GK     1024
#define GBK    32
#define ROWB   80
#define TILEB  (128 * ROWB)     // 10240
#define SETB   (4 * TILEB)      // 40960 per stage
#define GSM_TOTAL (2 * SETB)    // 81920
#define NKCH   32

__device__ __forceinline__ void load_chunk4(
    const __nv_bfloat16* __restrict__ Ah, const __nv_bfloat16* __restrict__ Al,
    const __nv_bfloat16* __restrict__ Bh, const __nv_bfloat16* __restrict__ Bl,
    int bm, int bn, int k0, uint32_t dst, int tid)
{
#pragma unroll
    for (int t = 0; t < 2; t++) {
        int u = tid + t * 256;
        int r = u >> 2;
        int c = (u & 3) * 16;
        size_t ao = (size_t)(bm + r) * GK + k0;
        size_t bo = (size_t)(bn + r) * GK + k0;
        uint32_t so = (uint32_t)(r * ROWB + c);
        cp_async16(dst + so,             (const char*)(Ah + ao) + c);
        cp_async16(dst + TILEB + so,     (const char*)(Al + ao) + c);
        cp_async16(dst + 2 * TILEB + so, (const char*)(Bh + bo) + c);
        cp_async16(dst + 3 * TILEB + so, (const char*)(Bl + bo) + c);
    }
    asm volatile("cp.async.commit_group;\n" ::: "memory");
}

__device__ __forceinline__ void gemm_body(
    const __nv_bfloat16* __restrict__ A_hi, const __nv_bfloat16* __restrict__ A_lo,
    const __nv_bfloat16* __restrict__ B_hi, const __nv_bfloat16* __restrict__ B_lo,
    int bm, int bn, uint32_t sb, float acc[2][8][4])
{
    const int tid  = threadIdx.x;
    const int lane = tid & 31;
    const int w    = tid >> 5;
    const int m_off = (w & 3) * 32;
    const int n_off = (w >> 2) * 64;

#pragma unroll
    for (int mt = 0; mt < 2; mt++)
#pragma unroll
        for (int nt = 0; nt < 8; nt++)
#pragma unroll
            for (int i = 0; i < 4; i++) acc[mt][nt][i] = 0.0f;

    const uint32_t a_off = (uint32_t)((m_off + (lane & 15)) * ROWB + 16 * (lane >> 4));
    const uint32_t b_off = (uint32_t)((n_off + (lane & 7) + 8 * (lane >> 4)) * ROWB
                                      + 16 * ((lane >> 3) & 1));

    load_chunk4(A_hi, A_lo, B_hi, B_lo, bm, bn, 0,   sb,        tid);
    load_chunk4(A_hi, A_lo, B_hi, B_lo, bm, bn, GBK, sb + SETB, tid);

    for (int i = 0; i < NKCH; i++) {
        if (i + 1 < NKCH) {
            asm volatile("cp.async.wait_group 1;\n" ::: "memory");
        } else {
            asm volatile("cp.async.wait_group 0;\n" ::: "memory");
        }
        __syncthreads();

        const uint32_t base = sb + (uint32_t)(i & 1) * SETB;
#pragma unroll
        for (int ks = 0; ks < 2; ks++) {
            uint32_t ah[2][4], al[2][4];
#pragma unroll
            for (int mt = 0; mt < 2; mt++) {
                uint32_t aadr = base + a_off + (uint32_t)(mt * 16 * ROWB + ks * 32);
                ldsm_x4(ah[mt], aadr);
                ldsm_x4(al[mt], aadr + TILEB);
            }
            uint32_t b2[8][2];
#pragma unroll
            for (int np = 0; np < 4; np++) {
                uint32_t r4[4];
                ldsm_x4(r4, base + 2 * TILEB + b_off + (uint32_t)(np * 16 * ROWB + ks * 32));
                b2[2*np][0] = r4[0]; b2[2*np][1] = r4[1];
                b2[2*np+1][0] = r4[2]; b2[2*np+1][1] = r4[3];
            }
#pragma unroll
            for (int mt = 0; mt < 2; mt++)
#pragma unroll
                for (int nt = 0; nt < 8; nt++) {
                    mma_16816(acc[mt][nt], ah[mt], b2[nt]);
                    mma_16816(acc[mt][nt], al[mt], b2[nt]);
                }
#pragma unroll
            for (int np = 0; np < 4; np++) {
                uint32_t r4[4];
                ldsm_x4(r4, base + 3 * TILEB + b_off + (uint32_t)(np * 16 * ROWB + ks * 32));
                b2[2*np][0] = r4[0]; b2[2*np][1] = r4[1];
                b2[2*np+1][0] = r4[2]; b2[2*np+1][1] = r4[3];
            }
#pragma unroll
            for (int mt = 0; mt < 2; mt++)
#pragma unroll
                for (int nt = 0; nt < 8; nt++)
                    mma_16816(acc[mt][nt], ah[mt], b2[nt]);
        }
        __syncthreads();

        if (i + 2 < NKCH)
            load_chunk4(A_hi, A_lo, B_hi, B_lo, bm, bn, (i + 2) * GBK, base, tid);
    }
}

// Fused QKV: blockIdx.x in [0,24); sel = bx>>3 routes weight/output.
// Q,K outputs: fp16 hi/lo pairs. V output: fp16 single.
__global__ __launch_bounds__(256, 2) void gemm_qkv_kernel(
    const __nv_bfloat16* __restrict__ A_hi, const __nv_bfloat16* __restrict__ A_lo,
    const __nv_bfloat16* __restrict__ Wqh, const __nv_bfloat16* __restrict__ Wql,
    const __nv_bfloat16* __restrict__ Wkh, const __nv_bfloat16* __restrict__ Wkl,
    const __nv_bfloat16* __restrict__ Wvh, const __nv_bfloat16* __restrict__ Wvl,
    __half* __restrict__ Qh, __half* __restrict__ Ql,
    __half* __restrict__ Kh, __half* __restrict__ Kl,
    __half* __restrict__ Vf)
{
    extern __shared__ __align__(16) char gsm[];
    const uint32_t sb = smem_u32(gsm);
    const int sel = blockIdx.x >> 3;
    const int bn  = (blockIdx.x & 7) * 128;
    const int bm  = blockIdx.y * 128;
    const __nv_bfloat16* Bh = sel == 0 ? Wqh : sel == 1 ? Wkh : Wvh;
    const __nv_bfloat16* Bl = sel == 0 ? Wql : sel == 1 ? Wkl : Wvl;

    float acc[2][8][4];
    gemm_body(A_hi, A_lo, Bh, Bl, bm, bn, sb, acc);

    const int lane = threadIdx.x & 31;
    const int w    = threadIdx.x >> 5;
    const int m_off = (w & 3) * 32;
    const int n_off = (w >> 2) * 64;
    const int g = lane >> 2;
    const int q = lane & 3;

    if (sel < 2) {
        __half* Hh = sel == 0 ? Qh : Kh;
        __half* Hl = sel == 0 ? Ql : Kl;
#pragma unroll
        for (int mt = 0; mt < 2; mt++) {
#pragma unroll
            for (int nt = 0; nt < 8; nt++) {
                int row = bm + m_off + mt * 16 + g;
                int col = bn + n_off + nt * 8 + q * 2;
                uint32_t h0 = pack_f16(acc[mt][nt][0], acc[mt][nt][1]);
                uint32_t l0 = pack_f16(acc[mt][nt][0] - f16_lo(h0),
                                       acc[mt][nt][1] - f16_hi(h0));
                *(uint32_t*)(Hh + (size_t)row * D_MODEL + col) = h0;
                *(uint32_t*)(Hl + (size_t)row * D_MODEL + col) = l0;
                uint32_t h1 = pack_f16(acc[mt][nt][2], acc[mt][nt][3]);
                uint32_t l1 = pack_f16(acc[mt][nt][2] - f16_lo(h1),
                                       acc[mt][nt][3] - f16_hi(h1));
                *(uint32_t*)(Hh + (size_t)(row + 8) * D_MODEL + col) = h1;
                *(uint32_t*)(Hl + (size_t)(row + 8) * D_MODEL + col) = l1;
            }
        }
    } else {
#pragma unroll
        for (int mt = 0; mt < 2; mt++) {
#pragma unroll
            for (int nt = 0; nt < 8; nt++) {
                int row = bm + m_off + mt * 16 + g;
                int col = bn + n_off + nt * 8 + q * 2;
                *(uint32_t*)(Vf + (size_t)row * D_MODEL + col) =
                    pack_f16(acc[mt][nt][0], acc[mt][nt][1]);
                *(uint32_t*)(Vf + (size_t)(row + 8) * D_MODEL + col) =
                    pack_f16(acc[mt][nt][2], acc[mt][nt][3]);
            }
        }
    }
}

// Output GEMM: fp32 C
__global__ __launch_bounds__(256, 2) void gemm_out_kernel(
    const __nv_bfloat16* __restrict__ A_hi, const __nv_bfloat16* __restrict__ A_lo,
    const __nv_bfloat16* __restrict__ B_hi, const __nv_bfloat16* __restrict__ B_lo,
    float* __restrict__ Cf)
{
    extern __shared__ __align__(16) char gsm[];
    const uint32_t sb = smem_u32(gsm);
    const int bn = blockIdx.x * 128;
    const int bm = blockIdx.y * 128;

    float acc[2][8][4];
    gemm_body(A_hi, A_lo, B_hi, B_lo, bm, bn, sb, acc);

    const int lane = threadIdx.x & 31;
    const int w    = threadIdx.x >> 5;
    const int m_off = (w & 3) * 32;
    const int n_off = (w >> 2) * 64;
    const int g = lane >> 2;
    const int q = lane & 3;
#pragma unroll
    for (int mt = 0; mt < 2; mt++) {
#pragma unroll
        for (int nt = 0; nt < 8; nt++) {
            int row = bm + m_off + mt * 16 + g;
            int col = bn + n_off + nt * 8 + q * 2;
            *(float2*)(Cf + (size_t)row * D_MODEL + col) =
                make_float2(acc[mt][nt][0], acc[mt][nt][1]);
            *(float2*)(Cf + (size_t)(row + 8) * D_MODEL + col) =
                make_float2(acc[mt][nt][2], acc[mt][nt][3]);
        }
    }
}

// ---------------------------------------------------------------------------
// Tensor-core causal flash attention, fp16 datapath:
// scores 3-term fp16 split (near-fp32 accurate), PV single-term fp16
// (P fp16, V fp16: error ~4-6e-4, calibrated from R7's bf16 measurement).
// 64 MMAs per 32-key tile (was 96). Pair-wise pipeline as R10.
// ---------------------------------------------------------------------------
#define AQT 128
#define AKT 32
#define AROWB 144
#define AQ_BYTES   (128 * AROWB)       // 18432
#define AKV_BYTES  (32 * AROWB)        // 4608 per tile component
#define ASET_BYTES (3 * AKV_BYTES)     // 13824 per stage (Kh,Kl,V)
#define ANSTAGE    4
#define ASM_KV0    (2 * AQ_BYTES)      // 36864
#define ASM_TOTAL  (ASM_KV0 + ANSTAGE * ASET_BYTES)   // 92160

#define FA_C1 0.18033688011112042f   // log2(e) / sqrt(64)

__device__ __forceinline__ void load_kv_tile_nc(
    const __half* __restrict__ Kh, const __half* __restrict__ Kl,
    const __half* __restrict__ Vf,
    int k0, int h, uint32_t base, int tid)
{
    int r = tid >> 3, c = tid & 7;
    uint32_t so = (uint32_t)(r * AROWB + c * 16);
    size_t  go = (size_t)(k0 + r) * D_MODEL + h * D_K + c * 8;
    cp_async16(base + 0 * AKV_BYTES + so, Kh + go);
    cp_async16(base + 1 * AKV_BYTES + so, Kl + go);
    cp_async16(base + 2 * AKV_BYTES + so, Vf + go);
}

// scores S[4][4] for one 32-key tile (3-term fp16 split)
__device__ __forceinline__ void fa_scores(
    float S[4][4], uint32_t kvb, uint32_t q_base, uint32_t k_base)
{
#pragma unroll
    for (int nt = 0; nt < 4; nt++)
#pragma unroll
        for (int i = 0; i < 4; i++) S[nt][i] = 0.f;

#pragma unroll
    for (int ks = 0; ks < 4; ks++) {
        uint32_t qa[4], qla[4];
        uint32_t qaddr = q_base + (uint32_t)(ks * 32);
        ldsm_x4(qa, qaddr);
        ldsm_x4(qla, qaddr + AQ_BYTES);

        uint32_t b2[4][2];
#pragma unroll
        for (int np = 0; np < 2; np++) {
            uint32_t r4[4];
            ldsm_x4(r4, kvb + k_base + (uint32_t)(np * 16 * AROWB + ks * 32));
            b2[2*np][0] = r4[0]; b2[2*np][1] = r4[1];
            b2[2*np+1][0] = r4[2]; b2[2*np+1][1] = r4[3];
        }
#pragma unroll
        for (int nt = 0; nt < 4; nt++) {
            mma_16816_f16(S[nt], qa,  b2[nt]);
            mma_16816_f16(S[nt], qla, b2[nt]);
        }
#pragma unroll
        for (int np = 0; np < 2; np++) {
            uint32_t r4[4];
            ldsm_x4(r4, kvb + AKV_BYTES + k_base + (uint32_t)(np * 16 * AROWB + ks * 32));
            b2[2*np][0] = r4[0]; b2[2*np][1] = r4[1];
            b2[2*np+1][0] = r4[2]; b2[2*np+1][1] = r4[3];
        }
#pragma unroll
        for (int nt = 0; nt < 4; nt++)
            mma_16816_f16(S[nt], qa, b2[nt]);
    }
}

// online-softmax stats: updates m_i/l_i, converts S -> P, emits rescale f[2]
__device__ __forceinline__ void fa_stats(
    float S[4][4], float m_i[2], float l_i[2], float f[2])
{
#pragma unroll
    for (int hf = 0; hf < 2; hf++) {
        float mx = -1e30f;
#pragma unroll
        for (int nt = 0; nt < 4; nt++)
            mx = fmaxf(mx, fmaxf(S[nt][2*hf], S[nt][2*hf+1]));
        mx = fmaxf(mx, __shfl_xor_sync(0xffffffffu, mx, 1));
        mx = fmaxf(mx, __shfl_xor_sync(0xffffffffu, mx, 2));
        float mold = m_i[hf];
        float mnew = fmaxf(mold, mx);
        f[hf] = fast_exp2((mold - mnew) * FA_C1);
        float nm = mnew * FA_C1;
        float sum = 0.f;
#pragma unroll
        for (int nt = 0; nt < 4; nt++) {
            float p0 = fast_exp2(fmaf(S[nt][2*hf],   FA_C1, -nm));
            float p1 = fast_exp2(fmaf(S[nt][2*hf+1], FA_C1, -nm));
            S[nt][2*hf] = p0; S[nt][2*hf+1] = p1;
            sum += p0 + p1;
        }
        sum += __shfl_xor_sync(0xffffffffu, sum, 1);
        sum += __shfl_xor_sync(0xffffffffu, sum, 2);
        l_i[hf] = l_i[hf] * f[hf] + sum;
        m_i[hf] = mnew;
    }
}

// O *= f, then O += P*V (single-term fp16)
__device__ __forceinline__ void fa_pv(
    float O[8][4], float S[4][4], const float f[2], uint32_t kvb, uint32_t v_base)
{
#pragma unroll
    for (int no = 0; no < 8; no++) {
        O[no][0] *= f[0]; O[no][1] *= f[0];
        O[no][2] *= f[1]; O[no][3] *= f[1];
    }
#pragma unroll
    for (int j = 0; j < 2; j++) {
        uint32_t ph[4];
        ph[0] = pack_f16(S[2*j][0],   S[2*j][1]);
        ph[1] = pack_f16(S[2*j][2],   S[2*j][3]);
        ph[2] = pack_f16(S[2*j+1][0], S[2*j+1][1]);
        ph[3] = pack_f16(S[2*j+1][2], S[2*j+1][3]);

        uint32_t v2[8][2];
#pragma unroll
        for (int np = 0; np < 4; np++) {
            uint32_t r4[4];
            ldsm_x4_t(r4, kvb + 2 * AKV_BYTES + v_base
                          + (uint32_t)(j * 16 * AROWB + np * 32));
            v2[2*np][0] = r4[0]; v2[2*np][1] = r4[1];
            v2[2*np+1][0] = r4[2]; v2[2*np+1][1] = r4[3];
        }
#pragma unroll
        for (int no = 0; no < 8; no++)
            mma_16816_f16(O[no], ph, v2[no]);
    }
}

__device__ __forceinline__ void fa_mask(
    float S[4][4], int k0, int q0, int m_off, int g, int qd)
{
    if (k0 + AKT > q0) {
        int qg0 = q0 + m_off + g;
#pragma unroll
        for (int nt = 0; nt < 4; nt++) {
            int kg = k0 + nt * 8 + 2 * qd;
            if (kg     > qg0)     S[nt][0] = -1e30f;
            if (kg + 1 > qg0)     S[nt][1] = -1e30f;
            if (kg     > qg0 + 8) S[nt][2] = -1e30f;
            if (kg + 1 > qg0 + 8) S[nt][3] = -1e30f;
        }
    }
}

__global__ __launch_bounds__(256, 2) void flash_mma_kernel(
    const __half* __restrict__ Qh, const __half* __restrict__ Ql,
    const __half* __restrict__ Kh, const __half* __restrict__ Kl,
    const __half* __restrict__ Vf,
    __nv_bfloat16* __restrict__ Ch, __nv_bfloat16* __restrict__ Cl)
{
    extern __shared__ char smem[];
    const uint32_t sb = smem_u32(smem);
    const int tid  = threadIdx.x;
    const int lane = tid & 31;
    const int wid  = tid >> 5;
    const int m_off = wid * 16;          // 8 warps x 16 rows
    const int h  = blockIdx.y;
    const int q0 = (int)(gridDim.x - 1 - blockIdx.x) * AQT;   // heavy blocks first
    const int g  = lane >> 2;
    const int qd = lane & 3;

    // Stage Q (hi at +0, lo at +AQ_BYTES): 8 x 16B per thread
#pragma unroll
    for (int t = 0; t < 8; t++) {
        const __half* src = (t < 4) ? Qh : Ql;
        int v = (t & 3) * 256 + tid;        // 0..1023
        int r = v >> 3, c = v & 7;
        cp_async16(sb + (t >> 2) * AQ_BYTES + r * AROWB + c * 16,
                   src + (size_t)(q0 + r) * D_MODEL + h * D_K + c * 8);
    }
    asm volatile("cp.async.commit_group;\n" ::: "memory");

    const int ntiles = q0 / AKT + AQT / AKT;   // multiple of 4
    const int npairs = ntiles / 2;             // >= 2

    // preload pairs 0 and 1 (one cp.async group each)
    load_kv_tile_nc(Kh, Kl, Vf, 0 * AKT, h, sb + ASM_KV0 + 0 * ASET_BYTES, tid);
    load_kv_tile_nc(Kh, Kl, Vf, 1 * AKT, h, sb + ASM_KV0 + 1 * ASET_BYTES, tid);
    asm volatile("cp.async.commit_group;\n" ::: "memory");
    load_kv_tile_nc(Kh, Kl, Vf, 2 * AKT, h, sb + ASM_KV0 + 2 * ASET_BYTES, tid);
    load_kv_tile_nc(Kh, Kl, Vf, 3 * AKT, h, sb + ASM_KV0 + 3 * ASET_BYTES, tid);
    asm volatile("cp.async.commit_group;\n" ::: "memory");

    float m_i[2] = { -1e30f, -1e30f };
    float l_i[2] = { 0.f, 0.f };
    float O[8][4];
#pragma unroll
    for (int no = 0; no < 8; no++)
#pragma unroll
        for (int i = 0; i < 4; i++) O[no][i] = 0.f;

    // per-thread fragment offsets (tile-invariant)
    const uint32_t q_base = sb + (uint32_t)((m_off + (lane & 15)) * AROWB + 16 * (lane >> 4));
    const uint32_t k_base = (uint32_t)(((lane & 7) + 8 * (lane >> 4)) * AROWB
                                       + 16 * ((lane >> 3) & 1));
    const uint32_t v_base = (uint32_t)(((lane & 7) + 8 * ((lane >> 3) & 1)) * AROWB
                                       + 16 * (lane >> 4));

    for (int p = 0; p < npairs; p++) {
        asm volatile("cp.async.wait_group 0;\n" ::: "memory");
        __syncthreads();

        // issue pair p+1's load into the half freed by pair p-1 (WAR-safe)
        if (p >= 1 && p + 1 < npairs) {
            int t0n = 2 * (p + 1);
            load_kv_tile_nc(Kh, Kl, Vf, t0n * AKT, h,
                            sb + ASM_KV0 + (uint32_t)(t0n & 3) * ASET_BYTES, tid);
            load_kv_tile_nc(Kh, Kl, Vf, (t0n + 1) * AKT, h,
                            sb + ASM_KV0 + (uint32_t)((t0n + 1) & 3) * ASET_BYTES, tid);
            asm volatile("cp.async.commit_group;\n" ::: "memory");
        }

        const int t0 = 2 * p, t1 = 2 * p + 1;
        const uint32_t kvb0 = sb + ASM_KV0 + (uint32_t)(t0 & 3) * ASET_BYTES;
        const uint32_t kvb1 = sb + ASM_KV0 + (uint32_t)(t1 & 3) * ASET_BYTES;

        // ---- back-to-back score MMAs for both tiles ----
        float S0[4][4], S1[4][4];
        fa_scores(S0, kvb0, q_base, k_base);
        fa_scores(S1, kvb1, q_base, k_base);
        fa_mask(S0, t0 * AKT, q0, m_off, g, qd);
        fa_mask(S1, t1 * AKT, q0, m_off, g, qd);

        // ---- stats; PV0's MMAs independent of stats1's ALU ----
        float f0[2], f1[2];
        fa_stats(S0, m_i, l_i, f0);
        fa_stats(S1, m_i, l_i, f1);

        fa_pv(O, S0, f0, kvb0, v_base);
        fa_pv(O, S1, f1, kvb1, v_base);
    }

    // ---- epilogue: normalize + write bf16 hi/lo context ----
    {
        float inv0 = 1.f / l_i[0];
        float inv1 = 1.f / l_i[1];
        int r0 = q0 + m_off + g;
#pragma unroll
        for (int no = 0; no < 8; no++) {
            int col = h * D_K + no * 8 + 2 * qd;
            float o0 = O[no][0] * inv0, o1 = O[no][1] * inv0;
            float o2 = O[no][2] * inv1, o3 = O[no][3] * inv1;
            uint32_t h0 = pack_bf(o0, o1);
            uint32_t l0 = pack_bf(o0 - bf_lo(h0), o1 - bf_hi(h0));
            *(uint32_t*)(Ch + (size_t)r0 * D_MODEL + col) = h0;
            *(uint32_t*)(Cl + (size_t)r0 * D_MODEL + col) = l0;
            uint32_t h1 = pack_bf(o2, o3);
            uint32_t l1 = pack_bf(o2 - bf_lo(h1), o3 - bf_hi(h1));
            *(uint32_t*)(Ch + (size_t)(r0 + 8) * D_MODEL + col) = h1;
            *(uint32_t*)(Cl + (size_t)(r0 + 8) * D_MODEL + col) = l1;
        }
    }
}

// ---------------------------------------------------------------------------
// Launch
// ---------------------------------------------------------------------------
extern "C" void kernel_launch(void* const* d_in, const int* in_sizes, int n_in,
                              void* d_out, int out_size)
{
    const float* x   = (const float*)d_in[0];
    const float* W_q = (const float*)d_in[1];
    const float* W_k = (const float*)d_in[2];
    const float* W_v = (const float*)d_in[3];
    const float* W_o = (const float*)d_in[4];
    float* out = (float*)d_out;

    static __nv_bfloat16* xh = nullptr;
    static __nv_bfloat16 *xl, *ch, *cl;
    static __half *qh, *ql, *kh, *kl, *vf;
    static __nv_bfloat16 *wqh, *wql, *wkh, *wkl, *wvh, *wvl, *woh, *wol;
    if (xh == nullptr) {
        cudaGetSymbolAddress((void**)&xl, g_xl);
        cudaGetSymbolAddress((void**)&ch, g_ch);
        cudaGetSymbolAddress((void**)&cl, g_cl);
        cudaGetSymbolAddress((void**)&qh, g_Qh);
        cudaGetSymbolAddress((void**)&ql, g_Ql);
        cudaGetSymbolAddress((void**)&kh, g_Kh);
        cudaGetSymbolAddress((void**)&kl, g_Kl);
        cudaGetSymbolAddress((void**)&vf, g_Vf);
        cudaGetSymbolAddress((void**)&wqh, g_wqh);
        cudaGetSymbolAddress((void**)&wql, g_wql);
        cudaGetSymbolAddress((void**)&wkh, g_wkh);
        cudaGetSymbolAddress((void**)&wkl, g_wkl);
        cudaGetSymbolAddress((void**)&wvh, g_wvh);
        cudaGetSymbolAddress((void**)&wvl, g_wvl);
        cudaGetSymbolAddress((void**)&woh, g_woh);
        cudaGetSymbolAddress((void**)&wol, g_wol);
        cudaFuncSetAttribute(flash_mma_kernel,
                             cudaFuncAttributeMaxDynamicSharedMemorySize, ASM_TOTAL);
        cudaFuncSetAttribute(gemm_qkv_kernel,
                             cudaFuncAttributeMaxDynamicSharedMemorySize, GSM_TOTAL);
        cudaFuncSetAttribute(gemm_out_kernel,
                             cudaFuncAttributeMaxDynamicSharedMemorySize, GSM_TOTAL);
        cudaGetSymbolAddress((void**)&xh, g_xh);   // last: publishes init
    }

    const int n_x4 = S_LEN * D_MODEL / 4;      // 1M float4s
    split_bf16_kernel<<<(n_x4 + 255) / 256, 256>>>(x, xh, xl, n_x4);
    split_w4_kernel<<<(4 * (1 << 18)) / 256, 256>>>(
        W_q, W_k, W_v, W_o,
        wqh, wql, wkh, wkl, wvh, wvl, woh, wol);

    dim3 qkvgrid(24, 32);
    gemm_qkv_kernel<<<qkvgrid, 256, GSM_TOTAL>>>(
        xh, xl, wqh, wql, wkh, wkl, wvh, wvl,
        qh, ql, kh, kl, vf);

    dim3 agrid(S_LEN / AQT, NHEADS);          // (32, 16)
    flash_mma_kernel<<<agrid, 256, ASM_TOTAL>>>(qh, ql, kh, kl, vf, ch, cl);

    dim3 ogrid(8, 32);
    gemm_out_kernel<<<ogrid, 256, GSM_TOTAL>>>(ch, cl, woh, wol, out);
}

// round 12
// speedup vs baseline: 1.3247x; 1.1043x over previous
#include <cuda_runtime.h>
#include <cuda_bf16.h>
#include <cuda_fp16.h>
#include <math.h>
#include <stdint.h>

// Problem constants (fixed shapes per reference)
#define S_LEN   4096
#define D_MODEL 1024
#define NHEADS  16
#define D_K     64

// ---------------------------------------------------------------------------
// Scratch (device globals; no allocation allowed)
// ---------------------------------------------------------------------------
__device__ __nv_bfloat16 g_xh[S_LEN * D_MODEL];
__device__ __nv_bfloat16 g_xl[S_LEN * D_MODEL];
__device__ __nv_bfloat16 g_ch[S_LEN * D_MODEL];
__device__ __nv_bfloat16 g_cl[S_LEN * D_MODEL];
__device__ __half g_Qh[S_LEN * D_MODEL];
__device__ __half g_Ql[S_LEN * D_MODEL];
__device__ __half g_Kh[S_LEN * D_MODEL];
__device__ __half g_Vf[S_LEN * D_MODEL];
__device__ __nv_bfloat16 g_wqh[D_MODEL * D_MODEL];
__device__ __nv_bfloat16 g_wql[D_MODEL * D_MODEL];
__device__ __nv_bfloat16 g_wkh[D_MODEL * D_MODEL];
__device__ __nv_bfloat16 g_wkl[D_MODEL * D_MODEL];
__device__ __nv_bfloat16 g_wvh[D_MODEL * D_MODEL];
__device__ __nv_bfloat16 g_wvl[D_MODEL * D_MODEL];
__device__ __nv_bfloat16 g_woh[D_MODEL * D_MODEL];
__device__ __nv_bfloat16 g_wol[D_MODEL * D_MODEL];

// ---------------------------------------------------------------------------
// PTX helpers (base sm_80+ features only — build targets plain compute_103)
// ---------------------------------------------------------------------------
__device__ __forceinline__ uint32_t smem_u32(const void* p) {
    uint32_t a;
    asm("{ .reg .u64 t; cvta.to.shared.u64 t, %1; cvt.u32.u64 %0, t; }"
        : "=r"(a) : "l"(p));
    return a;
}

__device__ __forceinline__ void cp_async16(uint32_t smem_dst, const void* gmem_src) {
    asm volatile("cp.async.cg.shared.global [%0], [%1], 16;\n"
                 :: "r"(smem_dst), "l"(gmem_src));
}

__device__ __forceinline__ void ldsm_x4(uint32_t* r, uint32_t addr) {
    asm volatile("ldmatrix.sync.aligned.m8n8.x4.shared.b16 {%0,%1,%2,%3}, [%4];"
                 : "=r"(r[0]), "=r"(r[1]), "=r"(r[2]), "=r"(r[3]) : "r"(addr));
}

__device__ __forceinline__ void ldsm_x4_t(uint32_t* r, uint32_t addr) {
    asm volatile("ldmatrix.sync.aligned.m8n8.x4.trans.shared.b16 {%0,%1,%2,%3}, [%4];"
                 : "=r"(r[0]), "=r"(r[1]), "=r"(r[2]), "=r"(r[3]) : "r"(addr));
}

// bf16 MMA (projection GEMMs)
__device__ __forceinline__ void mma_16816(float* d, const uint32_t* a, const uint32_t* b) {
    asm volatile(
        "mma.sync.aligned.m16n8k16.row.col.f32.bf16.bf16.f32 "
        "{%0,%1,%2,%3}, {%4,%5,%6,%7}, {%8,%9}, {%0,%1,%2,%3};"
        : "+f"(d[0]), "+f"(d[1]), "+f"(d[2]), "+f"(d[3])
        : "r"(a[0]), "r"(a[1]), "r"(a[2]), "r"(a[3]), "r"(b[0]), "r"(b[1]));
}

// fp16 MMA (attention)
__device__ __forceinline__ void mma_16816_f16(float* d, const uint32_t* a, const uint32_t* b) {
    asm volatile(
        "mma.sync.aligned.m16n8k16.row.col.f32.f16.f16.f32 "
        "{%0,%1,%2,%3}, {%4,%5,%6,%7}, {%8,%9}, {%0,%1,%2,%3};"
        : "+f"(d[0]), "+f"(d[1]), "+f"(d[2]), "+f"(d[3])
        : "r"(a[0]), "r"(a[1]), "r"(a[2]), "r"(a[3]), "r"(b[0]), "r"(b[1]));
}

__device__ __forceinline__ float fast_exp2(float x) {
    float r; asm("ex2.approx.f32 %0, %1;" : "=f"(r) : "f"(x)); return r;
}

// pack two fp32 -> bf16x2 (x in low half, y in high half)
__device__ __forceinline__ uint32_t pack_bf(float x, float y) {
    uint32_t r;
    asm("cvt.rn.bf16x2.f32 %0, %1, %2;" : "=r"(r) : "f"(y), "f"(x));
    return r;
}
__device__ __forceinline__ float bf_lo(uint32_t r) { return __uint_as_float(r << 16); }
__device__ __forceinline__ float bf_hi(uint32_t r) { return __uint_as_float(r & 0xffff0000u); }

// pack two fp32 -> fp16x2 (x in low half, y in high half)
__device__ __forceinline__ uint32_t pack_f16(float x, float y) {
    uint32_t r;
    asm("cvt.rn.f16x2.f32 %0, %1, %2;" : "=r"(r) : "f"(y), "f"(x));
    return r;
}
__device__ __forceinline__ float f16_lo(uint32_t r) {
    float f;
    asm("{ .reg .f16 a, b; mov.b32 {a, b}, %1; cvt.f32.f16 %0, a; }" : "=f"(f) : "r"(r));
    return f;
}
__device__ __forceinline__ float f16_hi(uint32_t r) {
    float f;
    asm("{ .reg .f16 a, b; mov.b32 {a, b}, %1; cvt.f32.f16 %0, b; }" : "=f"(f) : "r"(r));
    return f;
}

// ---------------------------------------------------------------------------
// Split fp32 -> bf16 hi/lo  (hi = bf16(x), lo = bf16(x - float(hi)))
// ---------------------------------------------------------------------------
__device__ __forceinline__ void split_one(const float* in, __nv_bfloat16* hi,
                                          __nv_bfloat16* lo, int i)
{
    float4 v = ((const float4*)in)[i];
    uint32_t h01 = pack_bf(v.x, v.y);
    uint32_t h23 = pack_bf(v.z, v.w);
    uint32_t l01 = pack_bf(v.x - bf_lo(h01), v.y - bf_hi(h01));
    uint32_t l23 = pack_bf(v.z - bf_lo(h23), v.w - bf_hi(h23));
    ((uint32_t*)hi)[i * 2 + 0] = h01;
    ((uint32_t*)hi)[i * 2 + 1] = h23;
    ((uint32_t*)lo)[i * 2 + 0] = l01;
    ((uint32_t*)lo)[i * 2 + 1] = l23;
}

__global__ void split_bf16_kernel(const float* __restrict__ in,
                                  __nv_bfloat16* __restrict__ hi,
                                  __nv_bfloat16* __restrict__ lo, int n4)
{
    int i = blockIdx.x * blockDim.x + threadIdx.x;
    if (i >= n4) return;
    split_one(in, hi, lo, i);
}

// All 4 weight matrices in one launch; idx>>18 routes (n_w4 = 2^18).
__global__ void split_w4_kernel(
    const float* __restrict__ w0, const float* __restrict__ w1,
    const float* __restrict__ w2, const float* __restrict__ w3,
    __nv_bfloat16* __restrict__ h0, __nv_bfloat16* __restrict__ l0,
    __nv_bfloat16* __restrict__ h1, __nv_bfloat16* __restrict__ l1,
    __nv_bfloat16* __restrict__ h2, __nv_bfloat16* __restrict__ l2,
    __nv_bfloat16* __restrict__ h3, __nv_bfloat16* __restrict__ l3)
{
    int idx = blockIdx.x * blockDim.x + threadIdx.x;
    int sel = idx >> 18;
    int i   = idx & ((1 << 18) - 1);
    const float* in = sel == 0 ? w0 : sel == 1 ? w1 : sel == 2 ? w2 : w3;
    __nv_bfloat16* hi = sel == 0 ? h0 : sel == 1 ? h1 : sel == 2 ? h2 : h3;
    __nv_bfloat16* lo = sel == 0 ? l0 : sel == 1 ? l1 : sel == 2 ? l2 : l3;
    split_one(in, hi, lo, i);
}

// ---------------------------------------------------------------------------
// Tensor-core GEMM body (HMMA, bf16, fp32 acc):
//   acc = Ahi*Bhi^T + Ahi*Blo^T + Alo*Bhi^T  over K=1024, tile 128x128
// ---------------------------------------------------------------------------
#define GK     1024
#define GBK    32
#define ROWB   80
#define TILEB  (128 * ROWB)     // 10240
#define SETB   (4 * TILEB)      // 40960 per stage
#define GSM_TOTAL (2 * SETB)    // 81920
#define NKCH   32

__device__ __forceinline__ void load_chunk4(
    const __nv_bfloat16* __restrict__ Ah, const __nv_bfloat16* __restrict__ Al,
    const __nv_bfloat16* __restrict__ Bh, const __nv_bfloat16* __restrict__ Bl,
    int bm, int bn, int k0, uint32_t dst, int tid)
{
#pragma unroll
    for (int t = 0; t < 2; t++) {
        int u = tid + t * 256;
        int r = u >> 2;
        int c = (u & 3) * 16;
        size_t ao = (size_t)(bm + r) * GK + k0;
        size_t bo = (size_t)(bn + r) * GK + k0;
        uint32_t so = (uint32_t)(r * ROWB + c);
        cp_async16(dst + so,             (const char*)(Ah + ao) + c);
        cp_async16(dst + TILEB + so,     (const char*)(Al + ao) + c);
        cp_async16(dst + 2 * TILEB + so, (const char*)(Bh + bo) + c);
        cp_async16(dst + 3 * TILEB + so, (const char*)(Bl + bo) + c);
    }
    asm volatile("cp.async.commit_group;\n" ::: "memory");
}

__device__ __forceinline__ void gemm_body(
    const __nv_bfloat16* __restrict__ A_hi, const __nv_bfloat16* __restrict__ A_lo,
    const __nv_bfloat16* __restrict__ B_hi, const __nv_bfloat16* __restrict__ B_lo,
    int bm, int bn, uint32_t sb, float acc[2][8][4])
{
    const int tid  = threadIdx.x;
    const int lane = tid & 31;
    const int w    = tid >> 5;
    const int m_off = (w & 3) * 32;
    const int n_off = (w >> 2) * 64;

#pragma unroll
    for (int mt = 0; mt < 2; mt++)
#pragma unroll
        for (int nt = 0; nt < 8; nt++)
#pragma unroll
            for (int i = 0; i < 4; i++) acc[mt][nt][i] = 0.0f;

    const uint32_t a_off = (uint32_t)((m_off + (lane & 15)) * ROWB + 16 * (lane >> 4));
    const uint32_t b_off = (uint32_t)((n_off + (lane & 7) + 8 * (lane >> 4)) * ROWB
                                      + 16 * ((lane >> 3) & 1));

    load_chunk4(A_hi, A_lo, B_hi, B_lo, bm, bn, 0,   sb,        tid);
    load_chunk4(A_hi, A_lo, B_hi, B_lo, bm, bn, GBK, sb + SETB, tid);

    for (int i = 0; i < NKCH; i++) {
        if (i + 1 < NKCH) {
            asm volatile("cp.async.wait_group 1;\n" ::: "memory");
        } else {
            asm volatile("cp.async.wait_group 0;\n" ::: "memory");
        }
        __syncthreads();

        const uint32_t base = sb + (uint32_t)(i & 1) * SETB;
#pragma unroll
        for (int ks = 0; ks < 2; ks++) {
            uint32_t ah[2][4], al[2][4];
#pragma unroll
            for (int mt = 0; mt < 2; mt++) {
                uint32_t aadr = base + a_off + (uint32_t)(mt * 16 * ROWB + ks * 32);
                ldsm_x4(ah[mt], aadr);
                ldsm_x4(al[mt], aadr + TILEB);
            }
            uint32_t b2[8][2];
#pragma unroll
            for (int np = 0; np < 4; np++) {
                uint32_t r4[4];
                ldsm_x4(r4, base + 2 * TILEB + b_off + (uint32_t)(np * 16 * ROWB + ks * 32));
                b2[2*np][0] = r4[0]; b2[2*np][1] = r4[1];
                b2[2*np+1][0] = r4[2]; b2[2*np+1][1] = r4[3];
            }
#pragma unroll
            for (int mt = 0; mt < 2; mt++)
#pragma unroll
                for (int nt = 0; nt < 8; nt++) {
                    mma_16816(acc[mt][nt], ah[mt], b2[nt]);
                    mma_16816(acc[mt][nt], al[mt], b2[nt]);
                }
#pragma unroll
            for (int np = 0; np < 4; np++) {
                uint32_t r4[4];
                ldsm_x4(r4, base + 3 * TILEB + b_off + (uint32_t)(np * 16 * ROWB + ks * 32));
                b2[2*np][0] = r4[0]; b2[2*np][1] = r4[1];
                b2[2*np+1][0] = r4[2]; b2[2*np+1][1] = r4[3];
            }
#pragma unroll
            for (int mt = 0; mt < 2; mt++)
#pragma unroll
                for (int nt = 0; nt < 8; nt++)
                    mma_16816(acc[mt][nt], ah[mt], b2[nt]);
        }
        __syncthreads();

        if (i + 2 < NKCH)
            load_chunk4(A_hi, A_lo, B_hi, B_lo, bm, bn, (i + 2) * GBK, base, tid);
    }
}

// Fused QKV: blockIdx.x in [0,24); sel = bx>>3 routes weight/output.
// Q output: fp16 hi/lo. K output: fp16 hi only. V output: fp16 single.
__global__ __launch_bounds__(256, 2) void gemm_qkv_kernel(
    const __nv_bfloat16* __restrict__ A_hi, const __nv_bfloat16* __restrict__ A_lo,
    const __nv_bfloat16* __restrict__ Wqh, const __nv_bfloat16* __restrict__ Wql,
    const __nv_bfloat16* __restrict__ Wkh, const __nv_bfloat16* __restrict__ Wkl,
    const __nv_bfloat16* __restrict__ Wvh, const __nv_bfloat16* __restrict__ Wvl,
    __half* __restrict__ Qh, __half* __restrict__ Ql,
    __half* __restrict__ Kh, __half* __restrict__ Vf)
{
    extern __shared__ __align__(16) char gsm[];
    const uint32_t sb = smem_u32(gsm);
    const int sel = blockIdx.x >> 3;
    const int bn  = (blockIdx.x & 7) * 128;
    const int bm  = blockIdx.y * 128;
    const __nv_bfloat16* Bh = sel == 0 ? Wqh : sel == 1 ? Wkh : Wvh;
    const __nv_bfloat16* Bl = sel == 0 ? Wql : sel == 1 ? Wkl : Wvl;

    float acc[2][8][4];
    gemm_body(A_hi, A_lo, Bh, Bl, bm, bn, sb, acc);

    const int lane = threadIdx.x & 31;
    const int w    = threadIdx.x >> 5;
    const int m_off = (w & 3) * 32;
    const int n_off = (w >> 2) * 64;
    const int g = lane >> 2;
    const int q = lane & 3;

    if (sel == 0) {
        // Q: fp16 hi/lo
#pragma unroll
        for (int mt = 0; mt < 2; mt++) {
#pragma unroll
            for (int nt = 0; nt < 8; nt++) {
                int row = bm + m_off + mt * 16 + g;
                int col = bn + n_off + nt * 8 + q * 2;
                uint32_t h0 = pack_f16(acc[mt][nt][0], acc[mt][nt][1]);
                uint32_t l0 = pack_f16(acc[mt][nt][0] - f16_lo(h0),
                                       acc[mt][nt][1] - f16_hi(h0));
                *(uint32_t*)(Qh + (size_t)row * D_MODEL + col) = h0;
                *(uint32_t*)(Ql + (size_t)row * D_MODEL + col) = l0;
                uint32_t h1 = pack_f16(acc[mt][nt][2], acc[mt][nt][3]);
                uint32_t l1 = pack_f16(acc[mt][nt][2] - f16_lo(h1),
                                       acc[mt][nt][3] - f16_hi(h1));
                *(uint32_t*)(Qh + (size_t)(row + 8) * D_MODEL + col) = h1;
                *(uint32_t*)(Ql + (size_t)(row + 8) * D_MODEL + col) = l1;
            }
        }
    } else {
        // K (sel==1) or V (sel==2): single fp16
        __half* Dst = sel == 1 ? Kh : Vf;
#pragma unroll
        for (int mt = 0; mt < 2; mt++) {
#pragma unroll
            for (int nt = 0; nt < 8; nt++) {
                int row = bm + m_off + mt * 16 + g;
                int col = bn + n_off + nt * 8 + q * 2;
                *(uint32_t*)(Dst + (size_t)row * D_MODEL + col) =
                    pack_f16(acc[mt][nt][0], acc[mt][nt][1]);
                *(uint32_t*)(Dst + (size_t)(row + 8) * D_MODEL + col) =
                    pack_f16(acc[mt][nt][2], acc[mt][nt][3]);
            }
        }
    }
}

// Output GEMM: fp32 C
__global__ __launch_bounds__(256, 2) void gemm_out_kernel(
    const __nv_bfloat16* __restrict__ A_hi, const __nv_bfloat16* __restrict__ A_lo,
    const __nv_bfloat16* __restrict__ B_hi, const __nv_bfloat16* __restrict__ B_lo,
    float* __restrict__ Cf)
{
    extern __shared__ __align__(16) char gsm[];
    const uint32_t sb = smem_u32(gsm);
    const int bn = blockIdx.x * 128;
    const int bm = blockIdx.y * 128;

    float acc[2][8][4];
    gemm_body(A_hi, A_lo, B_hi, B_lo, bm, bn, sb, acc);

    const int lane = threadIdx.x & 31;
    const int w    = threadIdx.x >> 5;
    const int m_off = (w & 3) * 32;
    const int n_off = (w >> 2) * 64;
    const int g = lane >> 2;
    const int q = lane & 3;
#pragma unroll
    for (int mt = 0; mt < 2; mt++) {
#pragma unroll
        for (int nt = 0; nt < 8; nt++) {
            int row = bm + m_off + mt * 16 + g;
            int col = bn + n_off + nt * 8 + q * 2;
            *(float2*)(Cf + (size_t)row * D_MODEL + col) =
                make_float2(acc[mt][nt][0], acc[mt][nt][1]);
            *(float2*)(Cf + (size_t)(row + 8) * D_MODEL + col) =
                make_float2(acc[mt][nt][2], acc[mt][nt][3]);
        }
    }
}

// ---------------------------------------------------------------------------
// Tensor-core causal flash attention, fp16 datapath:
// scores 2-term fp16 split (Qh*Kh + Ql*Kh — Kl dropped; logit err ~1.4e-4),
// PV single-term fp16. 48 MMAs per 32-key tile (was 64). KV stage = Kh + V.
// ---------------------------------------------------------------------------
#define AQT 128
#define AKT 32
#define AROWB 144
#define AQ_BYTES   (128 * AROWB)       // 18432
#define AKV_BYTES  (32 * AROWB)        // 4608 per tile component
#define ASET_BYTES (2 * AKV_BYTES)     // 9216 per stage (Kh, V)
#define ANSTAGE    4
#define ASM_KV0    (2 * AQ_BYTES)      // 36864
#define ASM_TOTAL  (ASM_KV0 + ANSTAGE * ASET_BYTES)   // 73728

#define FA_C1 0.18033688011112042f   // log2(e) / sqrt(64)

__device__ __forceinline__ void load_kv_tile_nc(
    const __half* __restrict__ Kh, const __half* __restrict__ Vf,
    int k0, int h, uint32_t base, int tid)
{
    int r = tid >> 3, c = tid & 7;
    uint32_t so = (uint32_t)(r * AROWB + c * 16);
    size_t  go = (size_t)(k0 + r) * D_MODEL + h * D_K + c * 8;
    cp_async16(base + 0 * AKV_BYTES + so, Kh + go);
    cp_async16(base + 1 * AKV_BYTES + so, Vf + go);
}

// scores S[4][4] for one 32-key tile (2-term fp16 split: Qh*Kh + Ql*Kh)
__device__ __forceinline__ void fa_scores(
    float S[4][4], uint32_t kvb, uint32_t q_base, uint32_t k_base)
{
#pragma unroll
    for (int nt = 0; nt < 4; nt++)
#pragma unroll
        for (int i = 0; i < 4; i++) S[nt][i] = 0.f;

#pragma unroll
    for (int ks = 0; ks < 4; ks++) {
        uint32_t qa[4], qla[4];
        uint32_t qaddr = q_base + (uint32_t)(ks * 32);
        ldsm_x4(qa, qaddr);
        ldsm_x4(qla, qaddr + AQ_BYTES);

        uint32_t b2[4][2];
#pragma unroll
        for (int np = 0; np < 2; np++) {
            uint32_t r4[4];
            ldsm_x4(r4, kvb + k_base + (uint32_t)(np * 16 * AROWB + ks * 32));
            b2[2*np][0] = r4[0]; b2[2*np][1] = r4[1];
            b2[2*np+1][0] = r4[2]; b2[2*np+1][1] = r4[3];
        }
#pragma unroll
        for (int nt = 0; nt < 4; nt++) {
            mma_16816_f16(S[nt], qa,  b2[nt]);
            mma_16816_f16(S[nt], qla, b2[nt]);
        }
    }
}

// online-softmax stats: updates m_i/l_i, converts S -> P, emits rescale f[2]
__device__ __forceinline__ void fa_stats(
    float S[4][4], float m_i[2], float l_i[2], float f[2])
{
#pragma unroll
    for (int hf = 0; hf < 2; hf++) {
        float mx = -1e30f;
#pragma unroll
        for (int nt = 0; nt < 4; nt++)
            mx = fmaxf(mx, fmaxf(S[nt][2*hf], S[nt][2*hf+1]));
        mx = fmaxf(mx, __shfl_xor_sync(0xffffffffu, mx, 1));
        mx = fmaxf(mx, __shfl_xor_sync(0xffffffffu, mx, 2));
        float mold = m_i[hf];
        float mnew = fmaxf(mold, mx);
        f[hf] = fast_exp2((mold - mnew) * FA_C1);
        float nm = mnew * FA_C1;
        float sum = 0.f;
#pragma unroll
        for (int nt = 0; nt < 4; nt++) {
            float p0 = fast_exp2(fmaf(S[nt][2*hf],   FA_C1, -nm));
            float p1 = fast_exp2(fmaf(S[nt][2*hf+1], FA_C1, -nm));
            S[nt][2*hf] = p0; S[nt][2*hf+1] = p1;
            sum += p0 + p1;
        }
        sum += __shfl_xor_sync(0xffffffffu, sum, 1);
        sum += __shfl_xor_sync(0xffffffffu, sum, 2);
        l_i[hf] = l_i[hf] * f[hf] + sum;
        m_i[hf] = mnew;
    }
}

// O *= f, then O += P*V (single-term fp16)
__device__ __forceinline__ void fa_pv(
    float O[8][4], float S[4][4], const float f[2], uint32_t kvb, uint32_t v_base)
{
#pragma unroll
    for (int no = 0; no < 8; no++) {
        O[no][0] *= f[0]; O[no][1] *= f[0];
        O[no][2] *= f[1]; O[no][3] *= f[1];
    }
#pragma unroll
    for (int j = 0; j < 2; j++) {
        uint32_t ph[4];
        ph[0] = pack_f16(S[2*j][0],   S[2*j][1]);
        ph[1] = pack_f16(S[2*j][2],   S[2*j][3]);
        ph[2] = pack_f16(S[2*j+1][0], S[2*j+1][1]);
        ph[3] = pack_f16(S[2*j+1][2], S[2*j+1][3]);

        uint32_t v2[8][2];
#pragma unroll
        for (int np = 0; np < 4; np++) {
            uint32_t r4[4];
            ldsm_x4_t(r4, kvb + AKV_BYTES + v_base
                          + (uint32_t)(j * 16 * AROWB + np * 32));
            v2[2*np][0] = r4[0]; v2[2*np][1] = r4[1];
            v2[2*np+1][0] = r4[2]; v2[2*np+1][1] = r4[3];
        }
#pragma unroll
        for (int no = 0; no < 8; no++)
            mma_16816_f16(O[no], ph, v2[no]);
    }
}

__device__ __forceinline__ void fa_mask(
    float S[4][4], int k0, int q0, int m_off, int g, int qd)
{
    if (k0 + AKT > q0) {
        int qg0 = q0 + m_off + g;
#pragma unroll
        for (int nt = 0; nt < 4; nt++) {
            int kg = k0 + nt * 8 + 2 * qd;
            if (kg     > qg0)     S[nt][0] = -1e30f;
            if (kg + 1 > qg0)     S[nt][1] = -1e30f;
            if (kg     > qg0 + 8) S[nt][2] = -1e30f;
            if (kg + 1 > qg0 + 8) S[nt][3] = -1e30f;
        }
    }
}

__global__ __launch_bounds__(256, 2) void flash_mma_kernel(
    const __half* __restrict__ Qh, const __half* __restrict__ Ql,
    const __half* __restrict__ Kh, const __half* __restrict__ Vf,
    __nv_bfloat16* __restrict__ Ch, __nv_bfloat16* __restrict__ Cl)
{
    extern __shared__ char smem[];
    const uint32_t sb = smem_u32(smem);
    const int tid  = threadIdx.x;
    const int lane = tid & 31;
    const int wid  = tid >> 5;
    const int m_off = wid * 16;          // 8 warps x 16 rows
    const int h  = blockIdx.y;
    const int q0 = (int)(gridDim.x - 1 - blockIdx.x) * AQT;   // heavy blocks first
    const int g  = lane >> 2;
    const int qd = lane & 3;

    // Stage Q (hi at +0, lo at +AQ_BYTES): 8 x 16B per thread
#pragma unroll
    for (int t = 0; t < 8; t++) {
        const __half* src = (t < 4) ? Qh : Ql;
        int v = (t & 3) * 256 + tid;        // 0..1023
        int r = v >> 3, c = v & 7;
        cp_async16(sb + (t >> 2) * AQ_BYTES + r * AROWB + c * 16,
                   src + (size_t)(q0 + r) * D_MODEL + h * D_K + c * 8);
    }
    asm volatile("cp.async.commit_group;\n" ::: "memory");

    const int ntiles = q0 / AKT + AQT / AKT;   // multiple of 4
    const int npairs = ntiles / 2;             // >= 2

    // preload pairs 0 and 1 (one cp.async group each)
    load_kv_tile_nc(Kh, Vf, 0 * AKT, h, sb + ASM_KV0 + 0 * ASET_BYTES, tid);
    load_kv_tile_nc(Kh, Vf, 1 * AKT, h, sb + ASM_KV0 + 1 * ASET_BYTES, tid);
    asm volatile("cp.async.commit_group;\n" ::: "memory");
    load_kv_tile_nc(Kh, Vf, 2 * AKT, h, sb + ASM_KV0 + 2 * ASET_BYTES, tid);
    load_kv_tile_nc(Kh, Vf, 3 * AKT, h, sb + ASM_KV0 + 3 * ASET_BYTES, tid);
    asm volatile("cp.async.commit_group;\n" ::: "memory");

    float m_i[2] = { -1e30f, -1e30f };
    float l_i[2] = { 0.f, 0.f };
    float O[8][4];
#pragma unroll
    for (int no = 0; no < 8; no++)
#pragma unroll
        for (int i = 0; i < 4; i++) O[no][i] = 0.f;

    // per-thread fragment offsets (tile-invariant)
    const uint32_t q_base = sb + (uint32_t)((m_off + (lane & 15)) * AROWB + 16 * (lane >> 4));
    const uint32_t k_base = (uint32_t)(((lane & 7) + 8 * (lane >> 4)) * AROWB
                                       + 16 * ((lane >> 3) & 1));
    const uint32_t v_base = (uint32_t)(((lane & 7) + 8 * ((lane >> 3) & 1)) * AROWB
                                       + 16 * (lane >> 4));

    for (int p = 0; p < npairs; p++) {
        asm volatile("cp.async.wait_group 0;\n" ::: "memory");
        __syncthreads();

        // issue pair p+1's load into the half freed by pair p-1 (WAR-safe)
        if (p >= 1 && p + 1 < npairs) {
            int t0n = 2 * (p + 1);
            load_kv_tile_nc(Kh, Vf, t0n * AKT, h,
                            sb + ASM_KV0 + (uint32_t)(t0n & 3) * ASET_BYTES, tid);
            load_kv_tile_nc(Kh, Vf, (t0n + 1) * AKT, h,
                            sb + ASM_KV0 + (uint32_t)((t0n + 1) & 3) * ASET_BYTES, tid);
            asm volatile("cp.async.commit_group;\n" ::: "memory");
        }

        const int t0 = 2 * p, t1 = 2 * p + 1;
        const uint32_t kvb0 = sb + ASM_KV0 + (uint32_t)(t0 & 3) * ASET_BYTES;
        const uint32_t kvb1 = sb + ASM_KV0 + (uint32_t)(t1 & 3) * ASET_BYTES;

        // ---- back-to-back score MMAs for both tiles ----
        float S0[4][4], S1[4][4];
        fa_scores(S0, kvb0, q_base, k_base);
        fa_scores(S1, kvb1, q_base, k_base);
        fa_mask(S0, t0 * AKT, q0, m_off, g, qd);
        fa_mask(S1, t1 * AKT, q0, m_off, g, qd);

        // ---- stats; PV0's MMAs independent of stats1's ALU ----
        float f0[2], f1[2];
        fa_stats(S0, m_i, l_i, f0);
        fa_stats(S1, m_i, l_i, f1);

        fa_pv(O, S0, f0, kvb0, v_base);
        fa_pv(O, S1, f1, kvb1, v_base);
    }

    // ---- epilogue: normalize + write bf16 hi/lo context ----
    {
        float inv0 = 1.f / l_i[0];
        float inv1 = 1.f / l_i[1];
        int r0 = q0 + m_off + g;
#pragma unroll
        for (int no = 0; no < 8; no++) {
            int col = h * D_K + no * 8 + 2 * qd;
            float o0 = O[no][0] * inv0, o1 = O[no][1] * inv0;
            float o2 = O[no][2] * inv1, o3 = O[no][3] * inv1;
            uint32_t h0 = pack_bf(o0, o1);
            uint32_t l0 = pack_bf(o0 - bf_lo(h0), o1 - bf_hi(h0));
            *(uint32_t*)(Ch + (size_t)r0 * D_MODEL + col) = h0;
            *(uint32_t*)(Cl + (size_t)r0 * D_MODEL + col) = l0;
            uint32_t h1 = pack_bf(o2, o3);
            uint32_t l1 = pack_bf(o2 - bf_lo(h1), o3 - bf_hi(h1));
            *(uint32_t*)(Ch + (size_t)(r0 + 8) * D_MODEL + col) = h1;
            *(uint32_t*)(Cl + (size_t)(r0 + 8) * D_MODEL + col) = l1;
        }
    }
}

// ---------------------------------------------------------------------------
// Launch
// ---------------------------------------------------------------------------
extern "C" void kernel_launch(void* const* d_in, const int* in_sizes, int n_in,
                              void* d_out, int out_size)
{
    const float* x   = (const float*)d_in[0];
    const float* W_q = (const float*)d_in[1];
    const float* W_k = (const float*)d_in[2];
    const float* W_v = (const float*)d_in[3];
    const float* W_o = (const float*)d_in[4];
    float* out = (float*)d_out;

    static __nv_bfloat16* xh = nullptr;
    static __nv_bfloat16 *xl, *ch, *cl;
    static __half *qh, *ql, *kh, *vf;
    static __nv_bfloat16 *wqh, *wql, *wkh, *wkl, *wvh, *wvl, *woh, *wol;
    if (xh == nullptr) {
        cudaGetSymbolAddress((void**)&xl, g_xl);
        cudaGetSymbolAddress((void**)&ch, g_ch);
        cudaGetSymbolAddress((void**)&cl, g_cl);
        cudaGetSymbolAddress((void**)&qh, g_Qh);
        cudaGetSymbolAddress((void**)&ql, g_Ql);
        cudaGetSymbolAddress((void**)&kh, g_Kh);
        cudaGetSymbolAddress((void**)&vf, g_Vf);
        cudaGetSymbolAddress((void**)&wqh, g_wqh);
        cudaGetSymbolAddress((void**)&wql, g_wql);
        cudaGetSymbolAddress((void**)&wkh, g_wkh);
        cudaGetSymbolAddress((void**)&wkl, g_wkl);
        cudaGetSymbolAddress((void**)&wvh, g_wvh);
        cudaGetSymbolAddress((void**)&wvl, g_wvl);
        cudaGetSymbolAddress((void**)&woh, g_woh);
        cudaGetSymbolAddress((void**)&wol, g_wol);
        cudaFuncSetAttribute(flash_mma_kernel,
                             cudaFuncAttributeMaxDynamicSharedMemorySize, ASM_TOTAL);
        cudaFuncSetAttribute(gemm_qkv_kernel,
                             cudaFuncAttributeMaxDynamicSharedMemorySize, GSM_TOTAL);
        cudaFuncSetAttribute(gemm_out_kernel,
                             cudaFuncAttributeMaxDynamicSharedMemorySize, GSM_TOTAL);
        cudaGetSymbolAddress((void**)&xh, g_xh);   // last: publishes init
    }

    const int n_x4 = S_LEN * D_MODEL / 4;      // 1M float4s
    split_bf16_kernel<<<(n_x4 + 255) / 256, 256>>>(x, xh, xl, n_x4);
    split_w4_kernel<<<(4 * (1 << 18)) / 256, 256>>>(
        W_q, W_k, W_v, W_o,
        wqh, wql, wkh, wkl, wvh, wvl, woh, wol);

    dim3 qkvgrid(24, 32);
    gemm_qkv_kernel<<<qkvgrid, 256, GSM_TOTAL>>>(
        xh, xl, wqh, wql, wkh, wkl, wvh, wvl,
        qh, ql, kh, vf);

    dim3 agrid(S_LEN / AQT, NHEADS);          // (32, 16)
    flash_mma_kernel<<<agrid, 256, ASM_TOTAL>>>(qh, ql, kh, vf, ch, cl);

    dim3 ogrid(8, 32);
    gemm_out_kernel<<<ogrid, 256, GSM_TOTAL>>>(ch, cl, woh, wol, out);
}

// round 13
// speedup vs baseline: 1.6332x; 1.2329x over previous
#include <cuda_runtime.h>
#include <cuda_bf16.h>
#include <cuda_fp16.h>
#include <math.h>
#include <stdint.h>

// Problem constants (fixed shapes per reference)
#define S_LEN   4096
#define D_MODEL 1024
#define NHEADS  16
#define D_K     64

// ---------------------------------------------------------------------------
// Scratch (device globals; no allocation allowed)
// ---------------------------------------------------------------------------
__device__ __half g_xh[S_LEN * D_MODEL];
__device__ __half g_xl[S_LEN * D_MODEL];
__device__ __half g_ch[S_LEN * D_MODEL];
__device__ __half g_cl[S_LEN * D_MODEL];
__device__ __half g_Qh[S_LEN * D_MODEL];
__device__ __half g_Ql[S_LEN * D_MODEL];
__device__ __half g_Kh[S_LEN * D_MODEL];
__device__ __half g_Vf[S_LEN * D_MODEL];
__device__ __half g_wq[D_MODEL * D_MODEL];
__device__ __half g_wk[D_MODEL * D_MODEL];
__device__ __half g_wv[D_MODEL * D_MODEL];
__device__ __half g_wo[D_MODEL * D_MODEL];

// ---------------------------------------------------------------------------
// PTX helpers (base sm_80+ features only — build targets plain compute_103)
// ---------------------------------------------------------------------------
__device__ __forceinline__ uint32_t smem_u32(const void* p) {
    uint32_t a;
    asm("{ .reg .u64 t; cvta.to.shared.u64 t, %1; cvt.u32.u64 %0, t; }"
        : "=r"(a) : "l"(p));
    return a;
}

__device__ __forceinline__ void cp_async16(uint32_t smem_dst, const void* gmem_src) {
    asm volatile("cp.async.cg.shared.global [%0], [%1], 16;\n"
                 :: "r"(smem_dst), "l"(gmem_src));
}

__device__ __forceinline__ void ldsm_x4(uint32_t* r, uint32_t addr) {
    asm volatile("ldmatrix.sync.aligned.m8n8.x4.shared.b16 {%0,%1,%2,%3}, [%4];"
                 : "=r"(r[0]), "=r"(r[1]), "=r"(r[2]), "=r"(r[3]) : "r"(addr));
}

__device__ __forceinline__ void ldsm_x4_t(uint32_t* r, uint32_t addr) {
    asm volatile("ldmatrix.sync.aligned.m8n8.x4.trans.shared.b16 {%0,%1,%2,%3}, [%4];"
                 : "=r"(r[0]), "=r"(r[1]), "=r"(r[2]), "=r"(r[3]) : "r"(addr));
}

// fp16 MMA, fp32 accumulate
__device__ __forceinline__ void mma_16816_f16(float* d, const uint32_t* a, const uint32_t* b) {
    asm volatile(
        "mma.sync.aligned.m16n8k16.row.col.f32.f16.f16.f32 "
        "{%0,%1,%2,%3}, {%4,%5,%6,%7}, {%8,%9}, {%0,%1,%2,%3};"
        : "+f"(d[0]), "+f"(d[1]), "+f"(d[2]), "+f"(d[3])
        : "r"(a[0]), "r"(a[1]), "r"(a[2]), "r"(a[3]), "r"(b[0]), "r"(b[1]));
}

__device__ __forceinline__ float fast_exp2(float x) {
    float r; asm("ex2.approx.f32 %0, %1;" : "=f"(r) : "f"(x)); return r;
}

// pack two fp32 -> fp16x2 (x in low half, y in high half)
__device__ __forceinline__ uint32_t pack_f16(float x, float y) {
    uint32_t r;
    asm("cvt.rn.f16x2.f32 %0, %1, %2;" : "=r"(r) : "f"(y), "f"(x));
    return r;
}
__device__ __forceinline__ float f16_lo(uint32_t r) {
    float f;
    asm("{ .reg .f16 a, b; mov.b32 {a, b}, %1; cvt.f32.f16 %0, a; }" : "=f"(f) : "r"(r));
    return f;
}
__device__ __forceinline__ float f16_hi(uint32_t r) {
    float f;
    asm("{ .reg .f16 a, b; mov.b32 {a, b}, %1; cvt.f32.f16 %0, b; }" : "=f"(f) : "r"(r));
    return f;
}

// ---------------------------------------------------------------------------
// Split fp32 -> fp16 hi/lo  (hi = fp16(x), lo = fp16(x - float(hi)))
// ---------------------------------------------------------------------------
__global__ void split_f16_kernel(const float* __restrict__ in,
                                 __half* __restrict__ hi,
                                 __half* __restrict__ lo, int n4)
{
    int i = blockIdx.x * blockDim.x + threadIdx.x;
    if (i >= n4) return;
    float4 v = ((const float4*)in)[i];
    uint32_t h01 = pack_f16(v.x, v.y);
    uint32_t h23 = pack_f16(v.z, v.w);
    uint32_t l01 = pack_f16(v.x - f16_lo(h01), v.y - f16_hi(h01));
    uint32_t l23 = pack_f16(v.z - f16_lo(h23), v.w - f16_hi(h23));
    ((uint32_t*)hi)[i * 2 + 0] = h01;
    ((uint32_t*)hi)[i * 2 + 1] = h23;
    ((uint32_t*)lo)[i * 2 + 0] = l01;
    ((uint32_t*)lo)[i * 2 + 1] = l23;
}

// Convert all 4 weight matrices fp32 -> fp16 in one launch (no lo term).
__global__ void conv_w4_kernel(
    const float* __restrict__ w0, const float* __restrict__ w1,
    const float* __restrict__ w2, const float* __restrict__ w3,
    __half* __restrict__ o0, __half* __restrict__ o1,
    __half* __restrict__ o2, __half* __restrict__ o3)
{
    int idx = blockIdx.x * blockDim.x + threadIdx.x;
    int sel = idx >> 18;
    int i   = idx & ((1 << 18) - 1);
    const float* in = sel == 0 ? w0 : sel == 1 ? w1 : sel == 2 ? w2 : w3;
    __half* out = sel == 0 ? o0 : sel == 1 ? o1 : sel == 2 ? o2 : o3;
    float4 v = ((const float4*)in)[i];
    ((uint32_t*)out)[i * 2 + 0] = pack_f16(v.x, v.y);
    ((uint32_t*)out)[i * 2 + 1] = pack_f16(v.z, v.w);
}

// ---------------------------------------------------------------------------
// Tensor-core GEMM body (HMMA fp16, fp32 acc), 2-term split:
//   acc = Ahi*B^T + Alo*B^T  over K=1024, tile 128x128
// 3 smem tiles per chunk (Ah, Al, B), BK=32, 2-stage cp.async.
// ---------------------------------------------------------------------------
#define GK     1024
#define GBK    32
#define ROWB   80
#define TILEB  (128 * ROWB)     // 10240
#define SETB   (3 * TILEB)      // 30720 per stage
#define GSM_TOTAL (2 * SETB)    // 61440
#define NKCH   32

__device__ __forceinline__ void load_chunk3(
    const __half* __restrict__ Ah, const __half* __restrict__ Al,
    const __half* __restrict__ B,
    int bm, int bn, int k0, uint32_t dst, int tid)
{
#pragma unroll
    for (int t = 0; t < 2; t++) {
        int u = tid + t * 256;
        int r = u >> 2;
        int c = (u & 3) * 16;
        size_t ao = (size_t)(bm + r) * GK + k0;
        size_t bo = (size_t)(bn + r) * GK + k0;
        uint32_t so = (uint32_t)(r * ROWB + c);
        cp_async16(dst + so,             (const char*)(Ah + ao) + c);
        cp_async16(dst + TILEB + so,     (const char*)(Al + ao) + c);
        cp_async16(dst + 2 * TILEB + so, (const char*)(B + bo) + c);
    }
    asm volatile("cp.async.commit_group;\n" ::: "memory");
}

__device__ __forceinline__ void gemm_body(
    const __half* __restrict__ A_hi, const __half* __restrict__ A_lo,
    const __half* __restrict__ B,
    int bm, int bn, uint32_t sb, float acc[2][8][4])
{
    const int tid  = threadIdx.x;
    const int lane = tid & 31;
    const int w    = tid >> 5;
    const int m_off = (w & 3) * 32;
    const int n_off = (w >> 2) * 64;

#pragma unroll
    for (int mt = 0; mt < 2; mt++)
#pragma unroll
        for (int nt = 0; nt < 8; nt++)
#pragma unroll
            for (int i = 0; i < 4; i++) acc[mt][nt][i] = 0.0f;

    const uint32_t a_off = (uint32_t)((m_off + (lane & 15)) * ROWB + 16 * (lane >> 4));
    const uint32_t b_off = (uint32_t)((n_off + (lane & 7) + 8 * (lane >> 4)) * ROWB
                                      + 16 * ((lane >> 3) & 1));

    load_chunk3(A_hi, A_lo, B, bm, bn, 0,   sb,        tid);
    load_chunk3(A_hi, A_lo, B, bm, bn, GBK, sb + SETB, tid);

    for (int i = 0; i < NKCH; i++) {
        if (i + 1 < NKCH) {
            asm volatile("cp.async.wait_group 1;\n" ::: "memory");
        } else {
            asm volatile("cp.async.wait_group 0;\n" ::: "memory");
        }
        __syncthreads();

        const uint32_t base = sb + (uint32_t)(i & 1) * SETB;
#pragma unroll
        for (int ks = 0; ks < 2; ks++) {
            uint32_t ah[2][4], al[2][4];
#pragma unroll
            for (int mt = 0; mt < 2; mt++) {
                uint32_t aadr = base + a_off + (uint32_t)(mt * 16 * ROWB + ks * 32);
                ldsm_x4(ah[mt], aadr);
                ldsm_x4(al[mt], aadr + TILEB);
            }
            uint32_t b2[8][2];
#pragma unroll
            for (int np = 0; np < 4; np++) {
                uint32_t r4[4];
                ldsm_x4(r4, base + 2 * TILEB + b_off + (uint32_t)(np * 16 * ROWB + ks * 32));
                b2[2*np][0] = r4[0]; b2[2*np][1] = r4[1];
                b2[2*np+1][0] = r4[2]; b2[2*np+1][1] = r4[3];
            }
#pragma unroll
            for (int mt = 0; mt < 2; mt++)
#pragma unroll
                for (int nt = 0; nt < 8; nt++) {
                    mma_16816_f16(acc[mt][nt], ah[mt], b2[nt]);
                    mma_16816_f16(acc[mt][nt], al[mt], b2[nt]);
                }
        }
        __syncthreads();

        if (i + 2 < NKCH)
            load_chunk3(A_hi, A_lo, B, bm, bn, (i + 2) * GBK, base, tid);
    }
}

// Fused QKV: blockIdx.x in [0,24); sel = bx>>3 routes weight/output.
// Q output: fp16 hi/lo. K output: fp16 hi only. V output: fp16 single.
__global__ __launch_bounds__(256, 2) void gemm_qkv_kernel(
    const __half* __restrict__ A_hi, const __half* __restrict__ A_lo,
    const __half* __restrict__ Wq, const __half* __restrict__ Wk,
    const __half* __restrict__ Wv,
    __half* __restrict__ Qh, __half* __restrict__ Ql,
    __half* __restrict__ Kh, __half* __restrict__ Vf)
{
    extern __shared__ __align__(16) char gsm[];
    const uint32_t sb = smem_u32(gsm);
    const int sel = blockIdx.x >> 3;
    const int bn  = (blockIdx.x & 7) * 128;
    const int bm  = blockIdx.y * 128;
    const __half* B = sel == 0 ? Wq : sel == 1 ? Wk : Wv;

    float acc[2][8][4];
    gemm_body(A_hi, A_lo, B, bm, bn, sb, acc);

    const int lane = threadIdx.x & 31;
    const int w    = threadIdx.x >> 5;
    const int m_off = (w & 3) * 32;
    const int n_off = (w >> 2) * 64;
    const int g = lane >> 2;
    const int q = lane & 3;

    if (sel == 0) {
        // Q: fp16 hi/lo
#pragma unroll
        for (int mt = 0; mt < 2; mt++) {
#pragma unroll
            for (int nt = 0; nt < 8; nt++) {
                int row = bm + m_off + mt * 16 + g;
                int col = bn + n_off + nt * 8 + q * 2;
                uint32_t h0 = pack_f16(acc[mt][nt][0], acc[mt][nt][1]);
                uint32_t l0 = pack_f16(acc[mt][nt][0] - f16_lo(h0),
                                       acc[mt][nt][1] - f16_hi(h0));
                *(uint32_t*)(Qh + (size_t)row * D_MODEL + col) = h0;
                *(uint32_t*)(Ql + (size_t)row * D_MODEL + col) = l0;
                uint32_t h1 = pack_f16(acc[mt][nt][2], acc[mt][nt][3]);
                uint32_t l1 = pack_f16(acc[mt][nt][2] - f16_lo(h1),
                                       acc[mt][nt][3] - f16_hi(h1));
                *(uint32_t*)(Qh + (size_t)(row + 8) * D_MODEL + col) = h1;
                *(uint32_t*)(Ql + (size_t)(row + 8) * D_MODEL + col) = l1;
            }
        }
    } else {
        __half* Dst = sel == 1 ? Kh : Vf;
#pragma unroll
        for (int mt = 0; mt < 2; mt++) {
#pragma unroll
            for (int nt = 0; nt < 8; nt++) {
                int row = bm + m_off + mt * 16 + g;
                int col = bn + n_off + nt * 8 + q * 2;
                *(uint32_t*)(Dst + (size_t)row * D_MODEL + col) =
                    pack_f16(acc[mt][nt][0], acc[mt][nt][1]);
                *(uint32_t*)(Dst + (size_t)(row + 8) * D_MODEL + col) =
                    pack_f16(acc[mt][nt][2], acc[mt][nt][3]);
            }
        }
    }
}

// Output GEMM: fp32 C
__global__ __launch_bounds__(256, 2) void gemm_out_kernel(
    const __half* __restrict__ A_hi, const __half* __restrict__ A_lo,
    const __half* __restrict__ B,
    float* __restrict__ Cf)
{
    extern __shared__ __align__(16) char gsm[];
    const uint32_t sb = smem_u32(gsm);
    const int bn = blockIdx.x * 128;
    const int bm = blockIdx.y * 128;

    float acc[2][8][4];
    gemm_body(A_hi, A_lo, B, bm, bn, sb, acc);

    const int lane = threadIdx.x & 31;
    const int w    = threadIdx.x >> 5;
    const int m_off = (w & 3) * 32;
    const int n_off = (w >> 2) * 64;
    const int g = lane >> 2;
    const int q = lane & 3;
#pragma unroll
    for (int mt = 0; mt < 2; mt++) {
#pragma unroll
        for (int nt = 0; nt < 8; nt++) {
            int row = bm + m_off + mt * 16 + g;
            int col = bn + n_off + nt * 8 + q * 2;
            *(float2*)(Cf + (size_t)row * D_MODEL + col) =
                make_float2(acc[mt][nt][0], acc[mt][nt][1]);
            *(float2*)(Cf + (size_t)(row + 8) * D_MODEL + col) =
                make_float2(acc[mt][nt][2], acc[mt][nt][3]);
        }
    }
}

// ---------------------------------------------------------------------------
// Tensor-core causal flash attention, fp16 datapath (unchanged from R12):
// scores 2-term fp16 split (Qh*Kh + Ql*Kh), PV single-term fp16.
// Context emitted as fp16 hi/lo for the output GEMM.
// ---------------------------------------------------------------------------
#define AQT 128
#define AKT 32
#define AROWB 144
#define AQ_BYTES   (128 * AROWB)       // 18432
#define AKV_BYTES  (32 * AROWB)        // 4608 per tile component
#define ASET_BYTES (2 * AKV_BYTES)     // 9216 per stage (Kh, V)
#define ANSTAGE    4
#define ASM_KV0    (2 * AQ_BYTES)      // 36864
#define ASM_TOTAL  (ASM_KV0 + ANSTAGE * ASET_BYTES)   // 73728

#define FA_C1 0.18033688011112042f   // log2(e) / sqrt(64)

__device__ __forceinline__ void load_kv_tile_nc(
    const __half* __restrict__ Kh, const __half* __restrict__ Vf,
    int k0, int h, uint32_t base, int tid)
{
    int r = tid >> 3, c = tid & 7;
    uint32_t so = (uint32_t)(r * AROWB + c * 16);
    size_t  go = (size_t)(k0 + r) * D_MODEL + h * D_K + c * 8;
    cp_async16(base + 0 * AKV_BYTES + so, Kh + go);
    cp_async16(base + 1 * AKV_BYTES + so, Vf + go);
}

__device__ __forceinline__ void fa_scores(
    float S[4][4], uint32_t kvb, uint32_t q_base, uint32_t k_base)
{
#pragma unroll
    for (int nt = 0; nt < 4; nt++)
#pragma unroll
        for (int i = 0; i < 4; i++) S[nt][i] = 0.f;

#pragma unroll
    for (int ks = 0; ks < 4; ks++) {
        uint32_t qa[4], qla[4];
        uint32_t qaddr = q_base + (uint32_t)(ks * 32);
        ldsm_x4(qa, qaddr);
        ldsm_x4(qla, qaddr + AQ_BYTES);

        uint32_t b2[4][2];
#pragma unroll
        for (int np = 0; np < 2; np++) {
            uint32_t r4[4];
            ldsm_x4(r4, kvb + k_base + (uint32_t)(np * 16 * AROWB + ks * 32));
            b2[2*np][0] = r4[0]; b2[2*np][1] = r4[1];
            b2[2*np+1][0] = r4[2]; b2[2*np+1][1] = r4[3];
        }
#pragma unroll
        for (int nt = 0; nt < 4; nt++) {
            mma_16816_f16(S[nt], qa,  b2[nt]);
            mma_16816_f16(S[nt], qla, b2[nt]);
        }
    }
}

__device__ __forceinline__ void fa_stats(
    float S[4][4], float m_i[2], float l_i[2], float f[2])
{
#pragma unroll
    for (int hf = 0; hf < 2; hf++) {
        float mx = -1e30f;
#pragma unroll
        for (int nt = 0; nt < 4; nt++)
            mx = fmaxf(mx, fmaxf(S[nt][2*hf], S[nt][2*hf+1]));
        mx = fmaxf(mx, __shfl_xor_sync(0xffffffffu, mx, 1));
        mx = fmaxf(mx, __shfl_xor_sync(0xffffffffu, mx, 2));
        float mold = m_i[hf];
        float mnew = fmaxf(mold, mx);
        f[hf] = fast_exp2((mold - mnew) * FA_C1);
        float nm = mnew * FA_C1;
        float sum = 0.f;
#pragma unroll
        for (int nt = 0; nt < 4; nt++) {
            float p0 = fast_exp2(fmaf(S[nt][2*hf],   FA_C1, -nm));
            float p1 = fast_exp2(fmaf(S[nt][2*hf+1], FA_C1, -nm));
            S[nt][2*hf] = p0; S[nt][2*hf+1] = p1;
            sum += p0 + p1;
        }
        sum += __shfl_xor_sync(0xffffffffu, sum, 1);
        sum += __shfl_xor_sync(0xffffffffu, sum, 2);
        l_i[hf] = l_i[hf] * f[hf] + sum;
        m_i[hf] = mnew;
    }
}

__device__ __forceinline__ void fa_pv(
    float O[8][4], float S[4][4], const float f[2], uint32_t kvb, uint32_t v_base)
{
#pragma unroll
    for (int no = 0; no < 8; no++) {
        O[no][0] *= f[0]; O[no][1] *= f[0];
        O[no][2] *= f[1]; O[no][3] *= f[1];
    }
#pragma unroll
    for (int j = 0; j < 2; j++) {
        uint32_t ph[4];
        ph[0] = pack_f16(S[2*j][0],   S[2*j][1]);
        ph[1] = pack_f16(S[2*j][2],   S[2*j][3]);
        ph[2] = pack_f16(S[2*j+1][0], S[2*j+1][1]);
        ph[3] = pack_f16(S[2*j+1][2], S[2*j+1][3]);

        uint32_t v2[8][2];
#pragma unroll
        for (int np = 0; np < 4; np++) {
            uint32_t r4[4];
            ldsm_x4_t(r4, kvb + AKV_BYTES + v_base
                          + (uint32_t)(j * 16 * AROWB + np * 32));
            v2[2*np][0] = r4[0]; v2[2*np][1] = r4[1];
            v2[2*np+1][0] = r4[2]; v2[2*np+1][1] = r4[3];
        }
#pragma unroll
        for (int no = 0; no < 8; no++)
            mma_16816_f16(O[no], ph, v2[no]);
    }
}

__device__ __forceinline__ void fa_mask(
    float S[4][4], int k0, int q0, int m_off, int g, int qd)
{
    if (k0 + AKT > q0) {
        int qg0 = q0 + m_off + g;
#pragma unroll
        for (int nt = 0; nt < 4; nt++) {
            int kg = k0 + nt * 8 + 2 * qd;
            if (kg     > qg0)     S[nt][0] = -1e30f;
            if (kg + 1 > qg0)     S[nt][1] = -1e30f;
            if (kg     > qg0 + 8) S[nt][2] = -1e30f;
            if (kg + 1 > qg0 + 8) S[nt][3] = -1e30f;
        }
    }
}

__global__ __launch_bounds__(256, 2) void flash_mma_kernel(
    const __half* __restrict__ Qh, const __half* __restrict__ Ql,
    const __half* __restrict__ Kh, const __half* __restrict__ Vf,
    __half* __restrict__ Ch, __half* __restrict__ Cl)
{
    extern __shared__ char smem[];
    const uint32_t sb = smem_u32(smem);
    const int tid  = threadIdx.x;
    const int lane = tid & 31;
    const int wid  = tid >> 5;
    const int m_off = wid * 16;          // 8 warps x 16 rows
    const int h  = blockIdx.y;
    const int q0 = (int)(gridDim.x - 1 - blockIdx.x) * AQT;   // heavy blocks first
    const int g  = lane >> 2;
    const int qd = lane & 3;

    // Stage Q (hi at +0, lo at +AQ_BYTES): 8 x 16B per thread
#pragma unroll
    for (int t = 0; t < 8; t++) {
        const __half* src = (t < 4) ? Qh : Ql;
        int v = (t & 3) * 256 + tid;        // 0..1023
        int r = v >> 3, c = v & 7;
        cp_async16(sb + (t >> 2) * AQ_BYTES + r * AROWB + c * 16,
                   src + (size_t)(q0 + r) * D_MODEL + h * D_K + c * 8);
    }
    asm volatile("cp.async.commit_group;\n" ::: "memory");

    const int ntiles = q0 / AKT + AQT / AKT;   // multiple of 4
    const int npairs = ntiles / 2;             // >= 2

    load_kv_tile_nc(Kh, Vf, 0 * AKT, h, sb + ASM_KV0 + 0 * ASET_BYTES, tid);
    load_kv_tile_nc(Kh, Vf, 1 * AKT, h, sb + ASM_KV0 + 1 * ASET_BYTES, tid);
    asm volatile("cp.async.commit_group;\n" ::: "memory");
    load_kv_tile_nc(Kh, Vf, 2 * AKT, h, sb + ASM_KV0 + 2 * ASET_BYTES, tid);
    load_kv_tile_nc(Kh, Vf, 3 * AKT, h, sb + ASM_KV0 + 3 * ASET_BYTES, tid);
    asm volatile("cp.async.commit_group;\n" ::: "memory");

    float m_i[2] = { -1e30f, -1e30f };
    float l_i[2] = { 0.f, 0.f };
    float O[8][4];
#pragma unroll
    for (int no = 0; no < 8; no++)
#pragma unroll
        for (int i = 0; i < 4; i++) O[no][i] = 0.f;

    const uint32_t q_base = sb + (uint32_t)((m_off + (lane & 15)) * AROWB + 16 * (lane >> 4));
    const uint32_t k_base = (uint32_t)(((lane & 7) + 8 * (lane >> 4)) * AROWB
                                       + 16 * ((lane >> 3) & 1));
    const uint32_t v_base = (uint32_t)(((lane & 7) + 8 * ((lane >> 3) & 1)) * AROWB
                                       + 16 * (lane >> 4));

    for (int p = 0; p < npairs; p++) {
        asm volatile("cp.async.wait_group 0;\n" ::: "memory");
        __syncthreads();

        if (p >= 1 && p + 1 < npairs) {
            int t0n = 2 * (p + 1);
            load_kv_tile_nc(Kh, Vf, t0n * AKT, h,
                            sb + ASM_KV0 + (uint32_t)(t0n & 3) * ASET_BYTES, tid);
            load_kv_tile_nc(Kh, Vf, (t0n + 1) * AKT, h,
                            sb + ASM_KV0 + (uint32_t)((t0n + 1) & 3) * ASET_BYTES, tid);
            asm volatile("cp.async.commit_group;\n" ::: "memory");
        }

        const int t0 = 2 * p, t1 = 2 * p + 1;
        const uint32_t kvb0 = sb + ASM_KV0 + (uint32_t)(t0 & 3) * ASET_BYTES;
        const uint32_t kvb1 = sb + ASM_KV0 + (uint32_t)(t1 & 3) * ASET_BYTES;

        float S0[4][4], S1[4][4];
        fa_scores(S0, kvb0, q_base, k_base);
        fa_scores(S1, kvb1, q_base, k_base);
        fa_mask(S0, t0 * AKT, q0, m_off, g, qd);
        fa_mask(S1, t1 * AKT, q0, m_off, g, qd);

        float f0[2], f1[2];
        fa_stats(S0, m_i, l_i, f0);
        fa_stats(S1, m_i, l_i, f1);

        fa_pv(O, S0, f0, kvb0, v_base);
        fa_pv(O, S1, f1, kvb1, v_base);
    }

    // ---- epilogue: normalize + write fp16 hi/lo context ----
    {
        float inv0 = 1.f / l_i[0];
        float inv1 = 1.f / l_i[1];
        int r0 = q0 + m_off + g;
#pragma unroll
        for (int no = 0; no < 8; no++) {
            int col = h * D_K + no * 8 + 2 * qd;
            float o0 = O[no][0] * inv0, o1 = O[no][1] * inv0;
            float o2 = O[no][2] * inv1, o3 = O[no][3] * inv1;
            uint32_t h0 = pack_f16(o0, o1);
            uint32_t l0 = pack_f16(o0 - f16_lo(h0), o1 - f16_hi(h0));
            *(uint32_t*)(Ch + (size_t)r0 * D_MODEL + col) = h0;
            *(uint32_t*)(Cl + (size_t)r0 * D_MODEL + col) = l0;
            uint32_t h1 = pack_f16(o2, o3);
            uint32_t l1 = pack_f16(o2 - f16_lo(h1), o3 - f16_hi(h1));
            *(uint32_t*)(Ch + (size_t)(r0 + 8) * D_MODEL + col) = h1;
            *(uint32_t*)(Cl + (size_t)(r0 + 8) * D_MODEL + col) = l1;
        }
    }
}

// ---------------------------------------------------------------------------
// Launch
// ---------------------------------------------------------------------------
extern "C" void kernel_launch(void* const* d_in, const int* in_sizes, int n_in,
                              void* d_out, int out_size)
{
    const float* x   = (const float*)d_in[0];
    const float* W_q = (const float*)d_in[1];
    const float* W_k = (const float*)d_in[2];
    const float* W_v = (const float*)d_in[3];
    const float* W_o = (const float*)d_in[4];
    float* out = (float*)d_out;

    static __half* xh = nullptr;
    static __half *xl, *ch, *cl, *qh, *ql, *kh, *vf;
    static __half *wq, *wk, *wv, *wo;
    if (xh == nullptr) {
        cudaGetSymbolAddress((void**)&xl, g_xl);
        cudaGetSymbolAddress((void**)&ch, g_ch);
        cudaGetSymbolAddress((void**)&cl, g_cl);
        cudaGetSymbolAddress((void**)&qh, g_Qh);
        cudaGetSymbolAddress((void**)&ql, g_Ql);
        cudaGetSymbolAddress((void**)&kh, g_Kh);
        cudaGetSymbolAddress((void**)&vf, g_Vf);
        cudaGetSymbolAddress((void**)&wq, g_wq);
        cudaGetSymbolAddress((void**)&wk, g_wk);
        cudaGetSymbolAddress((void**)&wv, g_wv);
        cudaGetSymbolAddress((void**)&wo, g_wo);
        cudaFuncSetAttribute(flash_mma_kernel,
                             cudaFuncAttributeMaxDynamicSharedMemorySize, ASM_TOTAL);
        cudaFuncSetAttribute(gemm_qkv_kernel,
                             cudaFuncAttributeMaxDynamicSharedMemorySize, GSM_TOTAL);
        cudaFuncSetAttribute(gemm_out_kernel,
                             cudaFuncAttributeMaxDynamicSharedMemorySize, GSM_TOTAL);
        cudaGetSymbolAddress((void**)&xh, g_xh);   // last: publishes init
    }

    const int n_x4 = S_LEN * D_MODEL / 4;      // 1M float4s
    split_f16_kernel<<<(n_x4 + 255) / 256, 256>>>(x, xh, xl, n_x4);
    conv_w4_kernel<<<(4 * (1 << 18)) / 256, 256>>>(
        W_q, W_k, W_v, W_o, wq, wk, wv, wo);

    dim3 qkvgrid(24, 32);
    gemm_qkv_kernel<<<qkvgrid, 256, GSM_TOTAL>>>(
        xh, xl, wq, wk, wv, qh, ql, kh, vf);

    dim3 agrid(S_LEN / AQT, NHEADS);          // (32, 16)
    flash_mma_kernel<<<agrid, 256, ASM_TOTAL>>>(qh, ql, kh, vf, ch, cl);

    dim3 ogrid(8, 32);
    gemm_out_kernel<<<ogrid, 256, GSM_TOTAL>>>(ch, cl, wo, out);
}

// round 14
// speedup vs baseline: 2.0976x; 1.2844x over previous
#include <cuda_runtime.h>
#include <cuda_bf16.h>
#include <cuda_fp16.h>
#include <math.h>
#include <stdint.h>

// Problem constants (fixed shapes per reference)
#define S_LEN   4096
#define D_MODEL 1024
#define NHEADS  16
#define D_K     64

// ---------------------------------------------------------------------------
// Scratch (device globals; no allocation allowed)
// ---------------------------------------------------------------------------
__device__ __half g_xf[S_LEN * D_MODEL];
__device__ __half g_ch[S_LEN * D_MODEL];
__device__ __half g_cl[S_LEN * D_MODEL];
__device__ __half g_Qf[S_LEN * D_MODEL];
__device__ __half g_Kh[S_LEN * D_MODEL];
__device__ __half g_Vf[S_LEN * D_MODEL];
__device__ __half g_wq[D_MODEL * D_MODEL];
__device__ __half g_wk[D_MODEL * D_MODEL];
__device__ __half g_wv[D_MODEL * D_MODEL];
__device__ __half g_wo[D_MODEL * D_MODEL];

// ---------------------------------------------------------------------------
// PTX helpers (base sm_80+ features only — build targets plain compute_103)
// ---------------------------------------------------------------------------
__device__ __forceinline__ uint32_t smem_u32(const void* p) {
    uint32_t a;
    asm("{ .reg .u64 t; cvta.to.shared.u64 t, %1; cvt.u32.u64 %0, t; }"
        : "=r"(a) : "l"(p));
    return a;
}

__device__ __forceinline__ void cp_async16(uint32_t smem_dst, const void* gmem_src) {
    asm volatile("cp.async.cg.shared.global [%0], [%1], 16;\n"
                 :: "r"(smem_dst), "l"(gmem_src));
}

__device__ __forceinline__ void ldsm_x4(uint32_t* r, uint32_t addr) {
    asm volatile("ldmatrix.sync.aligned.m8n8.x4.shared.b16 {%0,%1,%2,%3}, [%4];"
                 : "=r"(r[0]), "=r"(r[1]), "=r"(r[2]), "=r"(r[3]) : "r"(addr));
}

__device__ __forceinline__ void ldsm_x4_t(uint32_t* r, uint32_t addr) {
    asm volatile("ldmatrix.sync.aligned.m8n8.x4.trans.shared.b16 {%0,%1,%2,%3}, [%4];"
                 : "=r"(r[0]), "=r"(r[1]), "=r"(r[2]), "=r"(r[3]) : "r"(addr));
}

// fp16 MMA, fp32 accumulate
__device__ __forceinline__ void mma_16816_f16(float* d, const uint32_t* a, const uint32_t* b) {
    asm volatile(
        "mma.sync.aligned.m16n8k16.row.col.f32.f16.f16.f32 "
        "{%0,%1,%2,%3}, {%4,%5,%6,%7}, {%8,%9}, {%0,%1,%2,%3};"
        : "+f"(d[0]), "+f"(d[1]), "+f"(d[2]), "+f"(d[3])
        : "r"(a[0]), "r"(a[1]), "r"(a[2]), "r"(a[3]), "r"(b[0]), "r"(b[1]));
}

__device__ __forceinline__ float fast_exp2(float x) {
    float r; asm("ex2.approx.f32 %0, %1;" : "=f"(r) : "f"(x)); return r;
}

// pack two fp32 -> fp16x2 (x in low half, y in high half)
__device__ __forceinline__ uint32_t pack_f16(float x, float y) {
    uint32_t r;
    asm("cvt.rn.f16x2.f32 %0, %1, %2;" : "=r"(r) : "f"(y), "f"(x));
    return r;
}
__device__ __forceinline__ float f16_lo(uint32_t r) {
    float f;
    asm("{ .reg .f16 a, b; mov.b32 {a, b}, %1; cvt.f32.f16 %0, a; }" : "=f"(f) : "r"(r));
    return f;
}
__device__ __forceinline__ float f16_hi(uint32_t r) {
    float f;
    asm("{ .reg .f16 a, b; mov.b32 {a, b}, %1; cvt.f32.f16 %0, b; }" : "=f"(f) : "r"(r));
    return f;
}

// ---------------------------------------------------------------------------
// Convert x + 4 weights fp32 -> fp16 in one launch (5 * 2^18 float4 slots;
// x is 2^20 elems = 2^18 float4s per... x = S*D = 4M elems = 1M float4s).
// Simpler: separate kernels.
// ---------------------------------------------------------------------------
__global__ void conv_f16_kernel(const float* __restrict__ in,
                                __half* __restrict__ out, int n4)
{
    int i = blockIdx.x * blockDim.x + threadIdx.x;
    if (i >= n4) return;
    float4 v = ((const float4*)in)[i];
    ((uint32_t*)out)[i * 2 + 0] = pack_f16(v.x, v.y);
    ((uint32_t*)out)[i * 2 + 1] = pack_f16(v.z, v.w);
}

// Convert all 4 weight matrices fp32 -> fp16 in one launch.
__global__ void conv_w4_kernel(
    const float* __restrict__ w0, const float* __restrict__ w1,
    const float* __restrict__ w2, const float* __restrict__ w3,
    __half* __restrict__ o0, __half* __restrict__ o1,
    __half* __restrict__ o2, __half* __restrict__ o3)
{
    int idx = blockIdx.x * blockDim.x + threadIdx.x;
    int sel = idx >> 18;
    int i   = idx & ((1 << 18) - 1);
    const float* in = sel == 0 ? w0 : sel == 1 ? w1 : sel == 2 ? w2 : w3;
    __half* out = sel == 0 ? o0 : sel == 1 ? o1 : sel == 2 ? o2 : o3;
    float4 v = ((const float4*)in)[i];
    ((uint32_t*)out)[i * 2 + 0] = pack_f16(v.x, v.y);
    ((uint32_t*)out)[i * 2 + 1] = pack_f16(v.z, v.w);
}

// ---------------------------------------------------------------------------
// GEMM tiles/constants (tile 128x128, BK=32, 2-stage cp.async)
// ---------------------------------------------------------------------------
#define GK     1024
#define GBK    32
#define ROWB   80
#define TILEB  (128 * ROWB)     // 10240
#define NKCH   32

// ---- single-term body: acc = A*B^T (2 smem tiles/chunk) ----
#define SETB1  (2 * TILEB)      // 20480
#define GSM1   (2 * SETB1)      // 40960

__device__ __forceinline__ void load_chunk2(
    const __half* __restrict__ A, const __half* __restrict__ B,
    int bm, int bn, int k0, uint32_t dst, int tid)
{
#pragma unroll
    for (int t = 0; t < 2; t++) {
        int u = tid + t * 256;
        int r = u >> 2;
        int c = (u & 3) * 16;
        uint32_t so = (uint32_t)(r * ROWB + c);
        cp_async16(dst + so,         (const char*)(A + (size_t)(bm + r) * GK + k0) + c);
        cp_async16(dst + TILEB + so, (const char*)(B + (size_t)(bn + r) * GK + k0) + c);
    }
    asm volatile("cp.async.commit_group;\n" ::: "memory");
}

__device__ __forceinline__ void gemm_body1(
    const __half* __restrict__ A, const __half* __restrict__ B,
    int bm, int bn, uint32_t sb, float acc[2][8][4])
{
    const int tid  = threadIdx.x;
    const int lane = tid & 31;
    const int w    = tid >> 5;
    const int m_off = (w & 3) * 32;
    const int n_off = (w >> 2) * 64;

#pragma unroll
    for (int mt = 0; mt < 2; mt++)
#pragma unroll
        for (int nt = 0; nt < 8; nt++)
#pragma unroll
            for (int i = 0; i < 4; i++) acc[mt][nt][i] = 0.0f;

    const uint32_t a_off = (uint32_t)((m_off + (lane & 15)) * ROWB + 16 * (lane >> 4));
    const uint32_t b_off = (uint32_t)((n_off + (lane & 7) + 8 * (lane >> 4)) * ROWB
                                      + 16 * ((lane >> 3) & 1));

    load_chunk2(A, B, bm, bn, 0,   sb,         tid);
    load_chunk2(A, B, bm, bn, GBK, sb + SETB1, tid);

    for (int i = 0; i < NKCH; i++) {
        if (i + 1 < NKCH) {
            asm volatile("cp.async.wait_group 1;\n" ::: "memory");
        } else {
            asm volatile("cp.async.wait_group 0;\n" ::: "memory");
        }
        __syncthreads();

        const uint32_t base = sb + (uint32_t)(i & 1) * SETB1;
#pragma unroll
        for (int ks = 0; ks < 2; ks++) {
            uint32_t a2[2][4];
#pragma unroll
            for (int mt = 0; mt < 2; mt++)
                ldsm_x4(a2[mt], base + a_off + (uint32_t)(mt * 16 * ROWB + ks * 32));
            uint32_t b2[8][2];
#pragma unroll
            for (int np = 0; np < 4; np++) {
                uint32_t r4[4];
                ldsm_x4(r4, base + TILEB + b_off + (uint32_t)(np * 16 * ROWB + ks * 32));
                b2[2*np][0] = r4[0]; b2[2*np][1] = r4[1];
                b2[2*np+1][0] = r4[2]; b2[2*np+1][1] = r4[3];
            }
#pragma unroll
            for (int mt = 0; mt < 2; mt++)
#pragma unroll
                for (int nt = 0; nt < 8; nt++)
                    mma_16816_f16(acc[mt][nt], a2[mt], b2[nt]);
        }
        __syncthreads();

        if (i + 2 < NKCH)
            load_chunk2(A, B, bm, bn, (i + 2) * GBK, base, tid);
    }
}

// ---- 2-term body: acc = (Ah + Al)*B^T (3 smem tiles/chunk) ----
#define SETB2  (3 * TILEB)      // 30720
#define GSM2   (2 * SETB2)      // 61440

__device__ __forceinline__ void load_chunk3(
    const __half* __restrict__ Ah, const __half* __restrict__ Al,
    const __half* __restrict__ B,
    int bm, int bn, int k0, uint32_t dst, int tid)
{
#pragma unroll
    for (int t = 0; t < 2; t++) {
        int u = tid + t * 256;
        int r = u >> 2;
        int c = (u & 3) * 16;
        size_t ao = (size_t)(bm + r) * GK + k0;
        uint32_t so = (uint32_t)(r * ROWB + c);
        cp_async16(dst + so,             (const char*)(Ah + ao) + c);
        cp_async16(dst + TILEB + so,     (const char*)(Al + ao) + c);
        cp_async16(dst + 2 * TILEB + so, (const char*)(B + (size_t)(bn + r) * GK + k0) + c);
    }
    asm volatile("cp.async.commit_group;\n" ::: "memory");
}

__device__ __forceinline__ void gemm_body2(
    const __half* __restrict__ A_hi, const __half* __restrict__ A_lo,
    const __half* __restrict__ B,
    int bm, int bn, uint32_t sb, float acc[2][8][4])
{
    const int tid  = threadIdx.x;
    const int lane = tid & 31;
    const int w    = tid >> 5;
    const int m_off = (w & 3) * 32;
    const int n_off = (w >> 2) * 64;

#pragma unroll
    for (int mt = 0; mt < 2; mt++)
#pragma unroll
        for (int nt = 0; nt < 8; nt++)
#pragma unroll
            for (int i = 0; i < 4; i++) acc[mt][nt][i] = 0.0f;

    const uint32_t a_off = (uint32_t)((m_off + (lane & 15)) * ROWB + 16 * (lane >> 4));
    const uint32_t b_off = (uint32_t)((n_off + (lane & 7) + 8 * (lane >> 4)) * ROWB
                                      + 16 * ((lane >> 3) & 1));

    load_chunk3(A_hi, A_lo, B, bm, bn, 0,   sb,         tid);
    load_chunk3(A_hi, A_lo, B, bm, bn, GBK, sb + SETB2, tid);

    for (int i = 0; i < NKCH; i++) {
        if (i + 1 < NKCH) {
            asm volatile("cp.async.wait_group 1;\n" ::: "memory");
        } else {
            asm volatile("cp.async.wait_group 0;\n" ::: "memory");
        }
        __syncthreads();

        const uint32_t base = sb + (uint32_t)(i & 1) * SETB2;
#pragma unroll
        for (int ks = 0; ks < 2; ks++) {
            uint32_t ah[2][4], al[2][4];
#pragma unroll
            for (int mt = 0; mt < 2; mt++) {
                uint32_t aadr = base + a_off + (uint32_t)(mt * 16 * ROWB + ks * 32);
                ldsm_x4(ah[mt], aadr);
                ldsm_x4(al[mt], aadr + TILEB);
            }
            uint32_t b2[8][2];
#pragma unroll
            for (int np = 0; np < 4; np++) {
                uint32_t r4[4];
                ldsm_x4(r4, base + 2 * TILEB + b_off + (uint32_t)(np * 16 * ROWB + ks * 32));
                b2[2*np][0] = r4[0]; b2[2*np][1] = r4[1];
                b2[2*np+1][0] = r4[2]; b2[2*np+1][1] = r4[3];
            }
#pragma unroll
            for (int mt = 0; mt < 2; mt++)
#pragma unroll
                for (int nt = 0; nt < 8; nt++) {
                    mma_16816_f16(acc[mt][nt], ah[mt], b2[nt]);
                    mma_16816_f16(acc[mt][nt], al[mt], b2[nt]);
                }
        }
        __syncthreads();

        if (i + 2 < NKCH)
            load_chunk3(A_hi, A_lo, B, bm, bn, (i + 2) * GBK, base, tid);
    }
}

// Fused QKV (single-term x * W): blockIdx.x in [0,24); sel routes.
// All outputs single fp16.
__global__ __launch_bounds__(256, 2) void gemm_qkv_kernel(
    const __half* __restrict__ Xf,
    const __half* __restrict__ Wq, const __half* __restrict__ Wk,
    const __half* __restrict__ Wv,
    __half* __restrict__ Qf, __half* __restrict__ Kh, __half* __restrict__ Vf)
{
    extern __shared__ __align__(16) char gsm[];
    const uint32_t sb = smem_u32(gsm);
    const int sel = blockIdx.x >> 3;
    const int bn  = (blockIdx.x & 7) * 128;
    const int bm  = blockIdx.y * 128;
    const __half* B = sel == 0 ? Wq : sel == 1 ? Wk : Wv;
    __half* Dst = sel == 0 ? Qf : sel == 1 ? Kh : Vf;

    float acc[2][8][4];
    gemm_body1(Xf, B, bm, bn, sb, acc);

    const int lane = threadIdx.x & 31;
    const int w    = threadIdx.x >> 5;
    const int m_off = (w & 3) * 32;
    const int n_off = (w >> 2) * 64;
    const int g = lane >> 2;
    const int q = lane & 3;
#pragma unroll
    for (int mt = 0; mt < 2; mt++) {
#pragma unroll
        for (int nt = 0; nt < 8; nt++) {
            int row = bm + m_off + mt * 16 + g;
            int col = bn + n_off + nt * 8 + q * 2;
            *(uint32_t*)(Dst + (size_t)row * D_MODEL + col) =
                pack_f16(acc[mt][nt][0], acc[mt][nt][1]);
            *(uint32_t*)(Dst + (size_t)(row + 8) * D_MODEL + col) =
                pack_f16(acc[mt][nt][2], acc[mt][nt][3]);
        }
    }
}

// Output GEMM: 2-term context (ch + cl) * Wo^T -> fp32
__global__ __launch_bounds__(256, 2) void gemm_out_kernel(
    const __half* __restrict__ A_hi, const __half* __restrict__ A_lo,
    const __half* __restrict__ B,
    float* __restrict__ Cf)
{
    extern __shared__ __align__(16) char gsm[];
    const uint32_t sb = smem_u32(gsm);
    const int bn = blockIdx.x * 128;
    const int bm = blockIdx.y * 128;

    float acc[2][8][4];
    gemm_body2(A_hi, A_lo, B, bm, bn, sb, acc);

    const int lane = threadIdx.x & 31;
    const int w    = threadIdx.x >> 5;
    const int m_off = (w & 3) * 32;
    const int n_off = (w >> 2) * 64;
    const int g = lane >> 2;
    const int q = lane & 3;
#pragma unroll
    for (int mt = 0; mt < 2; mt++) {
#pragma unroll
        for (int nt = 0; nt < 8; nt++) {
            int row = bm + m_off + mt * 16 + g;
            int col = bn + n_off + nt * 8 + q * 2;
            *(float2*)(Cf + (size_t)row * D_MODEL + col) =
                make_float2(acc[mt][nt][0], acc[mt][nt][1]);
            *(float2*)(Cf + (size_t)(row + 8) * D_MODEL + col) =
                make_float2(acc[mt][nt][2], acc[mt][nt][3]);
        }
    }
}

// ---------------------------------------------------------------------------
// Tensor-core causal flash attention, fp16 datapath:
// scores single-term fp16 (Qf*Kh), PV single-term fp16 (P*V).
// 32 MMAs per 32-key tile. Context emitted fp16 hi/lo for the out GEMM.
// ---------------------------------------------------------------------------
#define AQT 128
#define AKT 32
#define AROWB 144
#define AQ_BYTES   (128 * AROWB)       // 18432
#define AKV_BYTES  (32 * AROWB)        // 4608 per tile component
#define ASET_BYTES (2 * AKV_BYTES)     // 9216 per stage (Kh, V)
#define ANSTAGE    4
#define ASM_KV0    AQ_BYTES            // 18432 (single Q buffer)
#define ASM_TOTAL  (ASM_KV0 + ANSTAGE * ASET_BYTES)   // 55296

#define FA_C1 0.18033688011112042f   // log2(e) / sqrt(64)

__device__ __forceinline__ void load_kv_tile_nc(
    const __half* __restrict__ Kh, const __half* __restrict__ Vf,
    int k0, int h, uint32_t base, int tid)
{
    int r = tid >> 3, c = tid & 7;
    uint32_t so = (uint32_t)(r * AROWB + c * 16);
    size_t  go = (size_t)(k0 + r) * D_MODEL + h * D_K + c * 8;
    cp_async16(base + 0 * AKV_BYTES + so, Kh + go);
    cp_async16(base + 1 * AKV_BYTES + so, Vf + go);
}

// scores S[4][4] for one 32-key tile (single-term fp16)
__device__ __forceinline__ void fa_scores(
    float S[4][4], uint32_t kvb, uint32_t q_base, uint32_t k_base)
{
#pragma unroll
    for (int nt = 0; nt < 4; nt++)
#pragma unroll
        for (int i = 0; i < 4; i++) S[nt][i] = 0.f;

#pragma unroll
    for (int ks = 0; ks < 4; ks++) {
        uint32_t qa[4];
        ldsm_x4(qa, q_base + (uint32_t)(ks * 32));

        uint32_t b2[4][2];
#pragma unroll
        for (int np = 0; np < 2; np++) {
            uint32_t r4[4];
            ldsm_x4(r4, kvb + k_base + (uint32_t)(np * 16 * AROWB + ks * 32));
            b2[2*np][0] = r4[0]; b2[2*np][1] = r4[1];
            b2[2*np+1][0] = r4[2]; b2[2*np+1][1] = r4[3];
        }
#pragma unroll
        for (int nt = 0; nt < 4; nt++)
            mma_16816_f16(S[nt], qa, b2[nt]);
    }
}

__device__ __forceinline__ void fa_stats(
    float S[4][4], float m_i[2], float l_i[2], float f[2])
{
#pragma unroll
    for (int hf = 0; hf < 2; hf++) {
        float mx = -1e30f;
#pragma unroll
        for (int nt = 0; nt < 4; nt++)
            mx = fmaxf(mx, fmaxf(S[nt][2*hf], S[nt][2*hf+1]));
        mx = fmaxf(mx, __shfl_xor_sync(0xffffffffu, mx, 1));
        mx = fmaxf(mx, __shfl_xor_sync(0xffffffffu, mx, 2));
        float mold = m_i[hf];
        float mnew = fmaxf(mold, mx);
        f[hf] = fast_exp2((mold - mnew) * FA_C1);
        float nm = mnew * FA_C1;
        float sum = 0.f;
#pragma unroll
        for (int nt = 0; nt < 4; nt++) {
            float p0 = fast_exp2(fmaf(S[nt][2*hf],   FA_C1, -nm));
            float p1 = fast_exp2(fmaf(S[nt][2*hf+1], FA_C1, -nm));
            S[nt][2*hf] = p0; S[nt][2*hf+1] = p1;
            sum += p0 + p1;
        }
        sum += __shfl_xor_sync(0xffffffffu, sum, 1);
        sum += __shfl_xor_sync(0xffffffffu, sum, 2);
        l_i[hf] = l_i[hf] * f[hf] + sum;
        m_i[hf] = mnew;
    }
}

__device__ __forceinline__ void fa_pv(
    float O[8][4], float S[4][4], const float f[2], uint32_t kvb, uint32_t v_base)
{
#pragma unroll
    for (int no = 0; no < 8; no++) {
        O[no][0] *= f[0]; O[no][1] *= f[0];
        O[no][2] *= f[1]; O[no][3] *= f[1];
    }
#pragma unroll
    for (int j = 0; j < 2; j++) {
        uint32_t ph[4];
        ph[0] = pack_f16(S[2*j][0],   S[2*j][1]);
        ph[1] = pack_f16(S[2*j][2],   S[2*j][3]);
        ph[2] = pack_f16(S[2*j+1][0], S[2*j+1][1]);
        ph[3] = pack_f16(S[2*j+1][2], S[2*j+1][3]);

        uint32_t v2[8][2];
#pragma unroll
        for (int np = 0; np < 4; np++) {
            uint32_t r4[4];
            ldsm_x4_t(r4, kvb + AKV_BYTES + v_base
                          + (uint32_t)(j * 16 * AROWB + np * 32));
            v2[2*np][0] = r4[0]; v2[2*np][1] = r4[1];
            v2[2*np+1][0] = r4[2]; v2[2*np+1][1] = r4[3];
        }
#pragma unroll
        for (int no = 0; no < 8; no++)
            mma_16816_f16(O[no], ph, v2[no]);
    }
}

__device__ __forceinline__ void fa_mask(
    float S[4][4], int k0, int q0, int m_off, int g, int qd)
{
    if (k0 + AKT > q0) {
        int qg0 = q0 + m_off + g;
#pragma unroll
        for (int nt = 0; nt < 4; nt++) {
            int kg = k0 + nt * 8 + 2 * qd;
            if (kg     > qg0)     S[nt][0] = -1e30f;
            if (kg + 1 > qg0)     S[nt][1] = -1e30f;
            if (kg     > qg0 + 8) S[nt][2] = -1e30f;
            if (kg + 1 > qg0 + 8) S[nt][3] = -1e30f;
        }
    }
}

__global__ __launch_bounds__(256, 2) void flash_mma_kernel(
    const __half* __restrict__ Qf,
    const __half* __restrict__ Kh, const __half* __restrict__ Vf,
    __half* __restrict__ Ch, __half* __restrict__ Cl)
{
    extern __shared__ char smem[];
    const uint32_t sb = smem_u32(smem);
    const int tid  = threadIdx.x;
    const int lane = tid & 31;
    const int wid  = tid >> 5;
    const int m_off = wid * 16;          // 8 warps x 16 rows
    const int h  = blockIdx.y;
    const int q0 = (int)(gridDim.x - 1 - blockIdx.x) * AQT;   // heavy blocks first
    const int g  = lane >> 2;
    const int qd = lane & 3;

    // Stage Q (single): 4 x 16B per thread
#pragma unroll
    for (int t = 0; t < 4; t++) {
        int v = t * 256 + tid;              // 0..1023
        int r = v >> 3, c = v & 7;
        cp_async16(sb + r * AROWB + c * 16,
                   Qf + (size_t)(q0 + r) * D_MODEL + h * D_K + c * 8);
    }
    asm volatile("cp.async.commit_group;\n" ::: "memory");

    const int ntiles = q0 / AKT + AQT / AKT;   // multiple of 4
    const int npairs = ntiles / 2;             // >= 2

    load_kv_tile_nc(Kh, Vf, 0 * AKT, h, sb + ASM_KV0 + 0 * ASET_BYTES, tid);
    load_kv_tile_nc(Kh, Vf, 1 * AKT, h, sb + ASM_KV0 + 1 * ASET_BYTES, tid);
    asm volatile("cp.async.commit_group;\n" ::: "memory");
    load_kv_tile_nc(Kh, Vf, 2 * AKT, h, sb + ASM_KV0 + 2 * ASET_BYTES, tid);
    load_kv_tile_nc(Kh, Vf, 3 * AKT, h, sb + ASM_KV0 + 3 * ASET_BYTES, tid);
    asm volatile("cp.async.commit_group;\n" ::: "memory");

    float m_i[2] = { -1e30f, -1e30f };
    float l_i[2] = { 0.f, 0.f };
    float O[8][4];
#pragma unroll
    for (int no = 0; no < 8; no++)
#pragma unroll
        for (int i = 0; i < 4; i++) O[no][i] = 0.f;

    const uint32_t q_base = sb + (uint32_t)((m_off + (lane & 15)) * AROWB + 16 * (lane >> 4));
    const uint32_t k_base = (uint32_t)(((lane & 7) + 8 * (lane >> 4)) * AROWB
                                       + 16 * ((lane >> 3) & 1));
    const uint32_t v_base = (uint32_t)(((lane & 7) + 8 * ((lane >> 3) & 1)) * AROWB
                                       + 16 * (lane >> 4));

    for (int p = 0; p < npairs; p++) {
        asm volatile("cp.async.wait_group 0;\n" ::: "memory");
        __syncthreads();

        if (p >= 1 && p + 1 < npairs) {
            int t0n = 2 * (p + 1);
            load_kv_tile_nc(Kh, Vf, t0n * AKT, h,
                            sb + ASM_KV0 + (uint32_t)(t0n & 3) * ASET_BYTES, tid);
            load_kv_tile_nc(Kh, Vf, (t0n + 1) * AKT, h,
                            sb + ASM_KV0 + (uint32_t)((t0n + 1) & 3) * ASET_BYTES, tid);
            asm volatile("cp.async.commit_group;\n" ::: "memory");
        }

        const int t0 = 2 * p, t1 = 2 * p + 1;
        const uint32_t kvb0 = sb + ASM_KV0 + (uint32_t)(t0 & 3) * ASET_BYTES;
        const uint32_t kvb1 = sb + ASM_KV0 + (uint32_t)(t1 & 3) * ASET_BYTES;

        float S0[4][4], S1[4][4];
        fa_scores(S0, kvb0, q_base, k_base);
        fa_scores(S1, kvb1, q_base, k_base);
        fa_mask(S0, t0 * AKT, q0, m_off, g, qd);
        fa_mask(S1, t1 * AKT, q0, m_off, g, qd);

        float f0[2], f1[2];
        fa_stats(S0, m_i, l_i, f0);
        fa_stats(S1, m_i, l_i, f1);

        fa_pv(O, S0, f0, kvb0, v_base);
        fa_pv(O, S1, f1, kvb1, v_base);
    }

    // ---- epilogue: normalize + write fp16 hi/lo context ----
    {
        float inv0 = 1.f / l_i[0];
        float inv1 = 1.f / l_i[1];
        int r0 = q0 + m_off + g;
#pragma unroll
        for (int no = 0; no < 8; no++) {
            int col = h * D_K + no * 8 + 2 * qd;
            float o0 = O[no][0] * inv0, o1 = O[no][1] * inv0;
            float o2 = O[no][2] * inv1, o3 = O[no][3] * inv1;
            uint32_t h0 = pack_f16(o0, o1);
            uint32_t l0 = pack_f16(o0 - f16_lo(h0), o1 - f16_hi(h0));
            *(uint32_t*)(Ch + (size_t)r0 * D_MODEL + col) = h0;
            *(uint32_t*)(Cl + (size_t)r0 * D_MODEL + col) = l0;
            uint32_t h1 = pack_f16(o2, o3);
            uint32_t l1 = pack_f16(o2 - f16_lo(h1), o3 - f16_hi(h1));
            *(uint32_t*)(Ch + (size_t)(r0 + 8) * D_MODEL + col) = h1;
            *(uint32_t*)(Cl + (size_t)(r0 + 8) * D_MODEL + col) = l1;
        }
    }
}

// ---------------------------------------------------------------------------
// Launch
// ---------------------------------------------------------------------------
extern "C" void kernel_launch(void* const* d_in, const int* in_sizes, int n_in,
                              void* d_out, int out_size)
{
    const float* x   = (const float*)d_in[0];
    const float* W_q = (const float*)d_in[1];
    const float* W_k = (const float*)d_in[2];
    const float* W_v = (const float*)d_in[3];
    const float* W_o = (const float*)d_in[4];
    float* out = (float*)d_out;

    static __half* xf = nullptr;
    static __half *ch, *cl, *qf, *kh, *vf;
    static __half *wq, *wk, *wv, *wo;
    if (xf == nullptr) {
        cudaGetSymbolAddress((void**)&ch, g_ch);
        cudaGetSymbolAddress((void**)&cl, g_cl);
        cudaGetSymbolAddress((void**)&qf, g_Qf);
        cudaGetSymbolAddress((void**)&kh, g_Kh);
        cudaGetSymbolAddress((void**)&vf, g_Vf);
        cudaGetSymbolAddress((void**)&wq, g_wq);
        cudaGetSymbolAddress((void**)&wk, g_wk);
        cudaGetSymbolAddress((void**)&wv, g_wv);
        cudaGetSymbolAddress((void**)&wo, g_wo);
        cudaFuncSetAttribute(flash_mma_kernel,
                             cudaFuncAttributeMaxDynamicSharedMemorySize, ASM_TOTAL);
        cudaFuncSetAttribute(gemm_qkv_kernel,
                             cudaFuncAttributeMaxDynamicSharedMemorySize, GSM1);
        cudaFuncSetAttribute(gemm_out_kernel,
                             cudaFuncAttributeMaxDynamicSharedMemorySize, GSM2);
        cudaGetSymbolAddress((void**)&xf, g_xf);   // last: publishes init
    }

    const int n_x4 = S_LEN * D_MODEL / 4;      // 1M float4s
    conv_f16_kernel<<<(n_x4 + 255) / 256, 256>>>(x, xf, n_x4);
    conv_w4_kernel<<<(4 * (1 << 18)) / 256, 256>>>(
        W_q, W_k, W_v, W_o, wq, wk, wv, wo);

    dim3 qkvgrid(24, 32);
    gemm_qkv_kernel<<<qkvgrid, 256, GSM1>>>(xf, wq, wk, wv, qf, kh, vf);

    dim3 agrid(S_LEN / AQT, NHEADS);          // (32, 16)
    flash_mma_kernel<<<agrid, 256, ASM_TOTAL>>>(qf, kh, vf, ch, cl);

    dim3 ogrid(8, 32);
    gemm_out_kernel<<<ogrid, 256, GSM2>>>(ch, cl, wo, out);
}

// round 15
// speedup vs baseline: 2.2940x; 1.0936x over previous
#include <cuda_runtime.h>
#include <cuda_bf16.h>
#include <cuda_fp16.h>
#include <math.h>
#include <stdint.h>

// Problem constants (fixed shapes per reference)
#define S_LEN   4096
#define D_MODEL 1024
#define NHEADS  16
#define D_K     64

// ---------------------------------------------------------------------------
// Scratch (device globals; no allocation allowed)
// ---------------------------------------------------------------------------
__device__ __half g_xf[S_LEN * D_MODEL];
__device__ __half g_cf[S_LEN * D_MODEL];
__device__ __half g_Qf[S_LEN * D_MODEL];
__device__ __half g_Kh[S_LEN * D_MODEL];
__device__ __half g_Vf[S_LEN * D_MODEL];
__device__ __half g_wq[D_MODEL * D_MODEL];
__device__ __half g_wk[D_MODEL * D_MODEL];
__device__ __half g_wv[D_MODEL * D_MODEL];
__device__ __half g_wo[D_MODEL * D_MODEL];

// ---------------------------------------------------------------------------
// PTX helpers (base sm_80+ features only — build targets plain compute_103)
// ---------------------------------------------------------------------------
__device__ __forceinline__ uint32_t smem_u32(const void* p) {
    uint32_t a;
    asm("{ .reg .u64 t; cvta.to.shared.u64 t, %1; cvt.u32.u64 %0, t; }"
        : "=r"(a) : "l"(p));
    return a;
}

__device__ __forceinline__ void cp_async16(uint32_t smem_dst, const void* gmem_src) {
    asm volatile("cp.async.cg.shared.global [%0], [%1], 16;\n"
                 :: "r"(smem_dst), "l"(gmem_src));
}

__device__ __forceinline__ void ldsm_x4(uint32_t* r, uint32_t addr) {
    asm volatile("ldmatrix.sync.aligned.m8n8.x4.shared.b16 {%0,%1,%2,%3}, [%4];"
                 : "=r"(r[0]), "=r"(r[1]), "=r"(r[2]), "=r"(r[3]) : "r"(addr));
}

__device__ __forceinline__ void ldsm_x4_t(uint32_t* r, uint32_t addr) {
    asm volatile("ldmatrix.sync.aligned.m8n8.x4.trans.shared.b16 {%0,%1,%2,%3}, [%4];"
                 : "=r"(r[0]), "=r"(r[1]), "=r"(r[2]), "=r"(r[3]) : "r"(addr));
}

// fp16 MMA, fp32 accumulate
__device__ __forceinline__ void mma_16816_f16(float* d, const uint32_t* a, const uint32_t* b) {
    asm volatile(
        "mma.sync.aligned.m16n8k16.row.col.f32.f16.f16.f32 "
        "{%0,%1,%2,%3}, {%4,%5,%6,%7}, {%8,%9}, {%0,%1,%2,%3};"
        : "+f"(d[0]), "+f"(d[1]), "+f"(d[2]), "+f"(d[3])
        : "r"(a[0]), "r"(a[1]), "r"(a[2]), "r"(a[3]), "r"(b[0]), "r"(b[1]));
}

__device__ __forceinline__ float fast_exp2(float x) {
    float r; asm("ex2.approx.f32 %0, %1;" : "=f"(r) : "f"(x)); return r;
}

// pack two fp32 -> fp16x2 (x in low half, y in high half)
__device__ __forceinline__ uint32_t pack_f16(float x, float y) {
    uint32_t r;
    asm("cvt.rn.f16x2.f32 %0, %1, %2;" : "=r"(r) : "f"(y), "f"(x));
    return r;
}

// ---------------------------------------------------------------------------
// Fused conversion: x (1M float4) + 4 weights (256K float4 each) -> fp16.
// idx in [0, 2M); idx < 1M -> x; else weight segment (sel-4).
// ---------------------------------------------------------------------------
__global__ void conv_all_kernel(
    const float* __restrict__ x,
    const float* __restrict__ w0, const float* __restrict__ w1,
    const float* __restrict__ w2, const float* __restrict__ w3,
    __half* __restrict__ xo,
    __half* __restrict__ o0, __half* __restrict__ o1,
    __half* __restrict__ o2, __half* __restrict__ o3)
{
    int idx = blockIdx.x * blockDim.x + threadIdx.x;
    int sel = idx >> 18;          // 0..7
    const float* in;
    __half* out;
    int i;
    if (sel < 4) { in = x; out = xo; i = idx; }
    else {
        i = idx & ((1 << 18) - 1);
        in  = sel == 4 ? w0 : sel == 5 ? w1 : sel == 6 ? w2 : w3;
        out = sel == 4 ? o0 : sel == 5 ? o1 : sel == 6 ? o2 : o3;
    }
    float4 v = ((const float4*)in)[i];
    ((uint32_t*)out)[i * 2 + 0] = pack_f16(v.x, v.y);
    ((uint32_t*)out)[i * 2 + 1] = pack_f16(v.z, v.w);
}

// ---------------------------------------------------------------------------
// GEMM (single-term fp16): acc = A*B^T, tile 128x128, BK=32, 2-stage cp.async
// ---------------------------------------------------------------------------
#define GK     1024
#define GBK    32
#define ROWB   80
#define TILEB  (128 * ROWB)     // 10240
#define NKCH   32
#define SETB1  (2 * TILEB)      // 20480
#define GSM1   (2 * SETB1)      // 40960

__device__ __forceinline__ void load_chunk2(
    const __half* __restrict__ A, const __half* __restrict__ B,
    int bm, int bn, int k0, uint32_t dst, int tid)
{
#pragma unroll
    for (int t = 0; t < 2; t++) {
        int u = tid + t * 256;
        int r = u >> 2;
        int c = (u & 3) * 16;
        uint32_t so = (uint32_t)(r * ROWB + c);
        cp_async16(dst + so,         (const char*)(A + (size_t)(bm + r) * GK + k0) + c);
        cp_async16(dst + TILEB + so, (const char*)(B + (size_t)(bn + r) * GK + k0) + c);
    }
    asm volatile("cp.async.commit_group;\n" ::: "memory");
}

__device__ __forceinline__ void gemm_body1(
    const __half* __restrict__ A, const __half* __restrict__ B,
    int bm, int bn, uint32_t sb, float acc[2][8][4])
{
    const int tid  = threadIdx.x;
    const int lane = tid & 31;
    const int w    = tid >> 5;
    const int m_off = (w & 3) * 32;
    const int n_off = (w >> 2) * 64;

#pragma unroll
    for (int mt = 0; mt < 2; mt++)
#pragma unroll
        for (int nt = 0; nt < 8; nt++)
#pragma unroll
            for (int i = 0; i < 4; i++) acc[mt][nt][i] = 0.0f;

    const uint32_t a_off = (uint32_t)((m_off + (lane & 15)) * ROWB + 16 * (lane >> 4));
    const uint32_t b_off = (uint32_t)((n_off + (lane & 7) + 8 * (lane >> 4)) * ROWB
                                      + 16 * ((lane >> 3) & 1));

    load_chunk2(A, B, bm, bn, 0,   sb,         tid);
    load_chunk2(A, B, bm, bn, GBK, sb + SETB1, tid);

    for (int i = 0; i < NKCH; i++) {
        if (i + 1 < NKCH) {
            asm volatile("cp.async.wait_group 1;\n" ::: "memory");
        } else {
            asm volatile("cp.async.wait_group 0;\n" ::: "memory");
        }
        __syncthreads();

        const uint32_t base = sb + (uint32_t)(i & 1) * SETB1;
#pragma unroll
        for (int ks = 0; ks < 2; ks++) {
            uint32_t a2[2][4];
#pragma unroll
            for (int mt = 0; mt < 2; mt++)
                ldsm_x4(a2[mt], base + a_off + (uint32_t)(mt * 16 * ROWB + ks * 32));
            uint32_t b2[8][2];
#pragma unroll
            for (int np = 0; np < 4; np++) {
                uint32_t r4[4];
                ldsm_x4(r4, base + TILEB + b_off + (uint32_t)(np * 16 * ROWB + ks * 32));
                b2[2*np][0] = r4[0]; b2[2*np][1] = r4[1];
                b2[2*np+1][0] = r4[2]; b2[2*np+1][1] = r4[3];
            }
#pragma unroll
            for (int mt = 0; mt < 2; mt++)
#pragma unroll
                for (int nt = 0; nt < 8; nt++)
                    mma_16816_f16(acc[mt][nt], a2[mt], b2[nt]);
        }
        __syncthreads();

        if (i + 2 < NKCH)
            load_chunk2(A, B, bm, bn, (i + 2) * GBK, base, tid);
    }
}

// Fused QKV (single-term x * W): blockIdx.x in [0,24); sel routes.
__global__ __launch_bounds__(256, 2) void gemm_qkv_kernel(
    const __half* __restrict__ Xf,
    const __half* __restrict__ Wq, const __half* __restrict__ Wk,
    const __half* __restrict__ Wv,
    __half* __restrict__ Qf, __half* __restrict__ Kh, __half* __restrict__ Vf)
{
    extern __shared__ __align__(16) char gsm[];
    const uint32_t sb = smem_u32(gsm);
    const int sel = blockIdx.x >> 3;
    const int bn  = (blockIdx.x & 7) * 128;
    const int bm  = blockIdx.y * 128;
    const __half* B = sel == 0 ? Wq : sel == 1 ? Wk : Wv;
    __half* Dst = sel == 0 ? Qf : sel == 1 ? Kh : Vf;

    float acc[2][8][4];
    gemm_body1(Xf, B, bm, bn, sb, acc);

    const int lane = threadIdx.x & 31;
    const int w    = threadIdx.x >> 5;
    const int m_off = (w & 3) * 32;
    const int n_off = (w >> 2) * 64;
    const int g = lane >> 2;
    const int q = lane & 3;
#pragma unroll
    for (int mt = 0; mt < 2; mt++) {
#pragma unroll
        for (int nt = 0; nt < 8; nt++) {
            int row = bm + m_off + mt * 16 + g;
            int col = bn + n_off + nt * 8 + q * 2;
            *(uint32_t*)(Dst + (size_t)row * D_MODEL + col) =
                pack_f16(acc[mt][nt][0], acc[mt][nt][1]);
            *(uint32_t*)(Dst + (size_t)(row + 8) * D_MODEL + col) =
                pack_f16(acc[mt][nt][2], acc[mt][nt][3]);
        }
    }
}

// Output GEMM: single-term context * Wo^T -> fp32
__global__ __launch_bounds__(256, 2) void gemm_out_kernel(
    const __half* __restrict__ Cx, const __half* __restrict__ B,
    float* __restrict__ Cf)
{
    extern __shared__ __align__(16) char gsm[];
    const uint32_t sb = smem_u32(gsm);
    const int bn = blockIdx.x * 128;
    const int bm = blockIdx.y * 128;

    float acc[2][8][4];
    gemm_body1(Cx, B, bm, bn, sb, acc);

    const int lane = threadIdx.x & 31;
    const int w    = threadIdx.x >> 5;
    const int m_off = (w & 3) * 32;
    const int n_off = (w >> 2) * 64;
    const int g = lane >> 2;
    const int q = lane & 3;
#pragma unroll
    for (int mt = 0; mt < 2; mt++) {
#pragma unroll
        for (int nt = 0; nt < 8; nt++) {
            int row = bm + m_off + mt * 16 + g;
            int col = bn + n_off + nt * 8 + q * 2;
            *(float2*)(Cf + (size_t)row * D_MODEL + col) =
                make_float2(acc[mt][nt][0], acc[mt][nt][1]);
            *(float2*)(Cf + (size_t)(row + 8) * D_MODEL + col) =
                make_float2(acc[mt][nt][2], acc[mt][nt][3]);
        }
    }
}

// ---------------------------------------------------------------------------
// Tensor-core causal flash attention, fp16 single-term, 64-key softmax tiles:
// one stats pass + one O-rescale per 64 keys (halved softmax fixed costs).
// 2-stage cp.async ring of (K,V) 64-row tiles.
// ---------------------------------------------------------------------------
#define AQT 128
#define AKT 64
#define AROWB 144
#define AQ_BYTES   (128 * AROWB)       // 18432
#define AKV_BYTES  (64 * AROWB)        // 9216 per component
#define ASET_BYTES (2 * AKV_BYTES)     // 18432 per stage (Kh, V)
#define ASM_KV0    AQ_BYTES            // 18432 (single Q buffer)
#define ASM_TOTAL  (ASM_KV0 + 2 * ASET_BYTES)   // 55296

#define FA_C1 0.18033688011112042f   // log2(e) / sqrt(64)

__device__ __forceinline__ void load_kv_tile(
    const __half* __restrict__ Kh, const __half* __restrict__ Vf,
    int k0, int h, uint32_t base, int tid)
{
#pragma unroll
    for (int t = 0; t < 2; t++) {
        int v = t * 256 + tid;              // 0..511
        int r = v >> 3, c = v & 7;
        uint32_t so = (uint32_t)(r * AROWB + c * 16);
        size_t  go = (size_t)(k0 + r) * D_MODEL + h * D_K + c * 8;
        cp_async16(base + so,             Kh + go);
        cp_async16(base + AKV_BYTES + so, Vf + go);
    }
    asm volatile("cp.async.commit_group;\n" ::: "memory");
}

__global__ __launch_bounds__(256, 2) void flash_mma_kernel(
    const __half* __restrict__ Qf,
    const __half* __restrict__ Kh, const __half* __restrict__ Vf,
    __half* __restrict__ Cx)
{
    extern __shared__ char smem[];
    const uint32_t sb = smem_u32(smem);
    const int tid  = threadIdx.x;
    const int lane = tid & 31;
    const int wid  = tid >> 5;
    const int m_off = wid * 16;          // 8 warps x 16 rows
    const int h  = blockIdx.y;
    const int q0 = (int)(gridDim.x - 1 - blockIdx.x) * AQT;   // heavy blocks first
    const int g  = lane >> 2;
    const int qd = lane & 3;

    // Stage Q (single): 4 x 16B per thread
#pragma unroll
    for (int t = 0; t < 4; t++) {
        int v = t * 256 + tid;              // 0..1023
        int r = v >> 3, c = v & 7;
        cp_async16(sb + r * AROWB + c * 16,
                   Qf + (size_t)(q0 + r) * D_MODEL + h * D_K + c * 8);
    }
    asm volatile("cp.async.commit_group;\n" ::: "memory");

    const int ntiles = q0 / AKT + AQT / AKT;   // >= 2

    load_kv_tile(Kh, Vf, 0 * AKT, h, sb + ASM_KV0, tid);
    load_kv_tile(Kh, Vf, 1 * AKT, h, sb + ASM_KV0 + ASET_BYTES, tid);

    float m_i[2] = { -1e30f, -1e30f };
    float l_i[2] = { 0.f, 0.f };
    float O[8][4];
#pragma unroll
    for (int no = 0; no < 8; no++)
#pragma unroll
        for (int i = 0; i < 4; i++) O[no][i] = 0.f;

    const uint32_t q_base = sb + (uint32_t)((m_off + (lane & 15)) * AROWB + 16 * (lane >> 4));
    const uint32_t k_base = (uint32_t)(((lane & 7) + 8 * (lane >> 4)) * AROWB
                                       + 16 * ((lane >> 3) & 1));
    const uint32_t v_base = (uint32_t)(((lane & 7) + 8 * ((lane >> 3) & 1)) * AROWB
                                       + 16 * (lane >> 4));

    for (int t = 0; t < ntiles; t++) {
        if (t + 1 < ntiles) {
            asm volatile("cp.async.wait_group 1;\n" ::: "memory");
        } else {
            asm volatile("cp.async.wait_group 0;\n" ::: "memory");
        }
        __syncthreads();

        const uint32_t kvb = sb + ASM_KV0 + (uint32_t)(t & 1) * ASET_BYTES;
        const int k0 = t * AKT;

        // ---- scores S[8][4] (16 q-rows x 64 keys), single-term fp16 ----
        float S[8][4];
#pragma unroll
        for (int nt = 0; nt < 8; nt++)
#pragma unroll
            for (int i = 0; i < 4; i++) S[nt][i] = 0.f;

#pragma unroll
        for (int ks = 0; ks < 4; ks++) {
            uint32_t qa[4];
            ldsm_x4(qa, q_base + (uint32_t)(ks * 32));

            uint32_t b2[8][2];
#pragma unroll
            for (int np = 0; np < 4; np++) {
                uint32_t r4[4];
                ldsm_x4(r4, kvb + k_base + (uint32_t)(np * 16 * AROWB + ks * 32));
                b2[2*np][0] = r4[0]; b2[2*np][1] = r4[1];
                b2[2*np+1][0] = r4[2]; b2[2*np+1][1] = r4[3];
            }
#pragma unroll
            for (int nt = 0; nt < 8; nt++)
                mma_16816_f16(S[nt], qa, b2[nt]);
        }

        // ---- causal mask (boundary tiles only) ----
        if (k0 + AKT > q0) {
            int qg0 = q0 + m_off + g;
#pragma unroll
            for (int nt = 0; nt < 8; nt++) {
                int kg = k0 + nt * 8 + 2 * qd;
                if (kg     > qg0)     S[nt][0] = -1e30f;
                if (kg + 1 > qg0)     S[nt][1] = -1e30f;
                if (kg     > qg0 + 8) S[nt][2] = -1e30f;
                if (kg + 1 > qg0 + 8) S[nt][3] = -1e30f;
            }
        }

        // ---- online softmax per row half (rows g and g+8), once per 64 keys ----
        float f[2];
#pragma unroll
        for (int hf = 0; hf < 2; hf++) {
            float mx = -1e30f;
#pragma unroll
            for (int nt = 0; nt < 8; nt++)
                mx = fmaxf(mx, fmaxf(S[nt][2*hf], S[nt][2*hf+1]));
            mx = fmaxf(mx, __shfl_xor_sync(0xffffffffu, mx, 1));
            mx = fmaxf(mx, __shfl_xor_sync(0xffffffffu, mx, 2));
            float mold = m_i[hf];
            float mnew = fmaxf(mold, mx);
            f[hf] = fast_exp2((mold - mnew) * FA_C1);
            float nm = mnew * FA_C1;
            float sum = 0.f;
#pragma unroll
            for (int nt = 0; nt < 8; nt++) {
                float p0 = fast_exp2(fmaf(S[nt][2*hf],   FA_C1, -nm));
                float p1 = fast_exp2(fmaf(S[nt][2*hf+1], FA_C1, -nm));
                S[nt][2*hf] = p0; S[nt][2*hf+1] = p1;
                sum += p0 + p1;
            }
            sum += __shfl_xor_sync(0xffffffffu, sum, 1);
            sum += __shfl_xor_sync(0xffffffffu, sum, 2);
            l_i[hf] = l_i[hf] * f[hf] + sum;
            m_i[hf] = mnew;
        }

        // ---- P·V (single-term fp16); O rescaled once per 64 keys ----
#pragma unroll
        for (int no = 0; no < 8; no++) {
            O[no][0] *= f[0]; O[no][1] *= f[0];
            O[no][2] *= f[1]; O[no][3] *= f[1];
        }
#pragma unroll
        for (int j = 0; j < 4; j++) {
            uint32_t ph[4];
            ph[0] = pack_f16(S[2*j][0],   S[2*j][1]);
            ph[1] = pack_f16(S[2*j][2],   S[2*j][3]);
            ph[2] = pack_f16(S[2*j+1][0], S[2*j+1][1]);
            ph[3] = pack_f16(S[2*j+1][2], S[2*j+1][3]);

            uint32_t v2[8][2];
#pragma unroll
            for (int np = 0; np < 4; np++) {
                uint32_t r4[4];
                ldsm_x4_t(r4, kvb + AKV_BYTES + v_base
                              + (uint32_t)(j * 16 * AROWB + np * 32));
                v2[2*np][0] = r4[0]; v2[2*np][1] = r4[1];
                v2[2*np+1][0] = r4[2]; v2[2*np+1][1] = r4[3];
            }
#pragma unroll
            for (int no = 0; no < 8; no++)
                mma_16816_f16(O[no], ph, v2[no]);
        }
        __syncthreads();

        if (t + 2 < ntiles)
            load_kv_tile(Kh, Vf, (t + 2) * AKT, h, kvb, tid);
    }

    // ---- epilogue: normalize + write single fp16 context ----
    {
        float inv0 = 1.f / l_i[0];
        float inv1 = 1.f / l_i[1];
        int r0 = q0 + m_off + g;
#pragma unroll
        for (int no = 0; no < 8; no++) {
            int col = h * D_K + no * 8 + 2 * qd;
            *(uint32_t*)(Cx + (size_t)r0 * D_MODEL + col) =
                pack_f16(O[no][0] * inv0, O[no][1] * inv0);
            *(uint32_t*)(Cx + (size_t)(r0 + 8) * D_MODEL + col) =
                pack_f16(O[no][2] * inv1, O[no][3] * inv1);
        }
    }
}

// ---------------------------------------------------------------------------
// Launch
// ---------------------------------------------------------------------------
extern "C" void kernel_launch(void* const* d_in, const int* in_sizes, int n_in,
                              void* d_out, int out_size)
{
    const float* x   = (const float*)d_in[0];
    const float* W_q = (const float*)d_in[1];
    const float* W_k = (const float*)d_in[2];
    const float* W_v = (const float*)d_in[3];
    const float* W_o = (const float*)d_in[4];
    float* out = (float*)d_out;

    static __half* xf = nullptr;
    static __half *cf, *qf, *kh, *vf;
    static __half *wq, *wk, *wv, *wo;
    if (xf == nullptr) {
        cudaGetSymbolAddress((void**)&cf, g_cf);
        cudaGetSymbolAddress((void**)&qf, g_Qf);
        cudaGetSymbolAddress((void**)&kh, g_Kh);
        cudaGetSymbolAddress((void**)&vf, g_Vf);
        cudaGetSymbolAddress((void**)&wq, g_wq);
        cudaGetSymbolAddress((void**)&wk, g_wk);
        cudaGetSymbolAddress((void**)&wv, g_wv);
        cudaGetSymbolAddress((void**)&wo, g_wo);
        cudaFuncSetAttribute(flash_mma_kernel,
                             cudaFuncAttributeMaxDynamicSharedMemorySize, ASM_TOTAL);
        cudaFuncSetAttribute(gemm_qkv_kernel,
                             cudaFuncAttributeMaxDynamicSharedMemorySize, GSM1);
        cudaFuncSetAttribute(gemm_out_kernel,
                             cudaFuncAttributeMaxDynamicSharedMemorySize, GSM1);
        cudaGetSymbolAddress((void**)&xf, g_xf);   // last: publishes init
    }

    // x: 1M float4s (4 * 2^18), 4 weights: 2^18 each -> 8 * 2^18 total
    conv_all_kernel<<<(8 * (1 << 18)) / 256, 256>>>(
        x, W_q, W_k, W_v, W_o, xf, wq, wk, wv, wo);

    dim3 qkvgrid(24, 32);
    gemm_qkv_kernel<<<qkvgrid, 256, GSM1>>>(xf, wq, wk, wv, qf, kh, vf);

    dim3 agrid(S_LEN / AQT, NHEADS);          // (32, 16)
    flash_mma_kernel<<<agrid, 256, ASM_TOTAL>>>(qf, kh, vf, cf);

    dim3 ogrid(8, 32);
    gemm_out_kernel<<<ogrid, 256, GSM1>>>(cf, wo, out);
}

// round 16
// speedup vs baseline: 2.4485x; 1.0674x over previous
#include <cuda_runtime.h>
#include <cuda_bf16.h>
#include <cuda_fp16.h>
#include <math.h>
#include <stdint.h>

// Problem constants (fixed shapes per reference)
#define S_LEN   4096
#define D_MODEL 1024
#define NHEADS  16
#define D_K     64

// ---------------------------------------------------------------------------
// Scratch (device globals; no allocation allowed)
// ---------------------------------------------------------------------------
__device__ __half g_xf[S_LEN * D_MODEL];
__device__ __half g_cf[S_LEN * D_MODEL];
__device__ __half g_Qf[S_LEN * D_MODEL];
__device__ __half g_Kh[S_LEN * D_MODEL];
__device__ __half g_Vf[S_LEN * D_MODEL];
__device__ __half g_wq[D_MODEL * D_MODEL];
__device__ __half g_wk[D_MODEL * D_MODEL];
__device__ __half g_wv[D_MODEL * D_MODEL];
__device__ __half g_wo[D_MODEL * D_MODEL];

// ---------------------------------------------------------------------------
// PTX helpers (base sm_80+ features only — build targets plain compute_103)
// ---------------------------------------------------------------------------
__device__ __forceinline__ uint32_t smem_u32(const void* p) {
    uint32_t a;
    asm("{ .reg .u64 t; cvta.to.shared.u64 t, %1; cvt.u32.u64 %0, t; }"
        : "=r"(a) : "l"(p));
    return a;
}

__device__ __forceinline__ void cp_async16(uint32_t smem_dst, const void* gmem_src) {
    asm volatile("cp.async.cg.shared.global [%0], [%1], 16;\n"
                 :: "r"(smem_dst), "l"(gmem_src));
}

__device__ __forceinline__ void ldsm_x4(uint32_t* r, uint32_t addr) {
    asm volatile("ldmatrix.sync.aligned.m8n8.x4.shared.b16 {%0,%1,%2,%3}, [%4];"
                 : "=r"(r[0]), "=r"(r[1]), "=r"(r[2]), "=r"(r[3]) : "r"(addr));
}

__device__ __forceinline__ void ldsm_x4_t(uint32_t* r, uint32_t addr) {
    asm volatile("ldmatrix.sync.aligned.m8n8.x4.trans.shared.b16 {%0,%1,%2,%3}, [%4];"
                 : "=r"(r[0]), "=r"(r[1]), "=r"(r[2]), "=r"(r[3]) : "r"(addr));
}

// fp16 MMA, fp32 accumulate
__device__ __forceinline__ void mma_16816_f16(float* d, const uint32_t* a, const uint32_t* b) {
    asm volatile(
        "mma.sync.aligned.m16n8k16.row.col.f32.f16.f16.f32 "
        "{%0,%1,%2,%3}, {%4,%5,%6,%7}, {%8,%9}, {%0,%1,%2,%3};"
        : "+f"(d[0]), "+f"(d[1]), "+f"(d[2]), "+f"(d[3])
        : "r"(a[0]), "r"(a[1]), "r"(a[2]), "r"(a[3]), "r"(b[0]), "r"(b[1]));
}

__device__ __forceinline__ float fast_exp2(float x) {
    float r; asm("ex2.approx.f32 %0, %1;" : "=f"(r) : "f"(x)); return r;
}

// pack two fp32 -> fp16x2 (x in low half, y in high half)
__device__ __forceinline__ uint32_t pack_f16(float x, float y) {
    uint32_t r;
    asm("cvt.rn.f16x2.f32 %0, %1, %2;" : "=r"(r) : "f"(y), "f"(x));
    return r;
}

// ---------------------------------------------------------------------------
// Fused conversion: x (1M float4) + 4 weights (256K float4 each) -> fp16.
// ---------------------------------------------------------------------------
__global__ void conv_all_kernel(
    const float* __restrict__ x,
    const float* __restrict__ w0, const float* __restrict__ w1,
    const float* __restrict__ w2, const float* __restrict__ w3,
    __half* __restrict__ xo,
    __half* __restrict__ o0, __half* __restrict__ o1,
    __half* __restrict__ o2, __half* __restrict__ o3)
{
    int idx = blockIdx.x * blockDim.x + threadIdx.x;
    int sel = idx >> 18;          // 0..7
    const float* in;
    __half* out;
    int i;
    if (sel < 4) { in = x; out = xo; i = idx; }
    else {
        i = idx & ((1 << 18) - 1);
        in  = sel == 4 ? w0 : sel == 5 ? w1 : sel == 6 ? w2 : w3;
        out = sel == 4 ? o0 : sel == 5 ? o1 : sel == 6 ? o2 : o3;
    }
    float4 v = ((const float4*)in)[i];
    ((uint32_t*)out)[i * 2 + 0] = pack_f16(v.x, v.y);
    ((uint32_t*)out)[i * 2 + 1] = pack_f16(v.z, v.w);
}

// ---------------------------------------------------------------------------
// GEMM (single-term fp16): acc = A*B^T, tile 128x128, BK=64 (one barrier pair
// per 64 K-elements), 2-stage cp.async.
// ---------------------------------------------------------------------------
#define GK     1024
#define GBK    64
#define ROWB   144              // 128B payload + 16B pad
#define TILEB  (128 * ROWB)     // 18432
#define NKCH   16
#define SETB1  (2 * TILEB)      // 36864 per stage (A, B)
#define GSM1   (2 * SETB1)      // 73728

__device__ __forceinline__ void load_chunk2(
    const __half* __restrict__ A, const __half* __restrict__ B,
    int bm, int bn, int k0, uint32_t dst, int tid)
{
#pragma unroll
    for (int t = 0; t < 4; t++) {
        int u = tid + t * 256;          // 0..1023
        int r = u >> 3;
        int c = (u & 7) * 16;           // byte offset in 128B row
        uint32_t so = (uint32_t)(r * ROWB + c);
        cp_async16(dst + so,         (const char*)(A + (size_t)(bm + r) * GK + k0) + c);
        cp_async16(dst + TILEB + so, (const char*)(B + (size_t)(bn + r) * GK + k0) + c);
    }
    asm volatile("cp.async.commit_group;\n" ::: "memory");
}

__device__ __forceinline__ void gemm_body1(
    const __half* __restrict__ A, const __half* __restrict__ B,
    int bm, int bn, uint32_t sb, float acc[2][8][4])
{
    const int tid  = threadIdx.x;
    const int lane = tid & 31;
    const int w    = tid >> 5;
    const int m_off = (w & 3) * 32;
    const int n_off = (w >> 2) * 64;

#pragma unroll
    for (int mt = 0; mt < 2; mt++)
#pragma unroll
        for (int nt = 0; nt < 8; nt++)
#pragma unroll
            for (int i = 0; i < 4; i++) acc[mt][nt][i] = 0.0f;

    const uint32_t a_off = (uint32_t)((m_off + (lane & 15)) * ROWB + 16 * (lane >> 4));
    const uint32_t b_off = (uint32_t)((n_off + (lane & 7) + 8 * (lane >> 4)) * ROWB
                                      + 16 * ((lane >> 3) & 1));

    load_chunk2(A, B, bm, bn, 0,   sb,         tid);
    load_chunk2(A, B, bm, bn, GBK, sb + SETB1, tid);

    for (int i = 0; i < NKCH; i++) {
        if (i + 1 < NKCH) {
            asm volatile("cp.async.wait_group 1;\n" ::: "memory");
        } else {
            asm volatile("cp.async.wait_group 0;\n" ::: "memory");
        }
        __syncthreads();

        const uint32_t base = sb + (uint32_t)(i & 1) * SETB1;
#pragma unroll
        for (int ks = 0; ks < 4; ks++) {
            uint32_t a2[2][4];
#pragma unroll
            for (int mt = 0; mt < 2; mt++)
                ldsm_x4(a2[mt], base + a_off + (uint32_t)(mt * 16 * ROWB + ks * 32));
            uint32_t b2[8][2];
#pragma unroll
            for (int np = 0; np < 4; np++) {
                uint32_t r4[4];
                ldsm_x4(r4, base + TILEB + b_off + (uint32_t)(np * 16 * ROWB + ks * 32));
                b2[2*np][0] = r4[0]; b2[2*np][1] = r4[1];
                b2[2*np+1][0] = r4[2]; b2[2*np+1][1] = r4[3];
            }
#pragma unroll
            for (int mt = 0; mt < 2; mt++)
#pragma unroll
                for (int nt = 0; nt < 8; nt++)
                    mma_16816_f16(acc[mt][nt], a2[mt], b2[nt]);
        }
        __syncthreads();

        if (i + 2 < NKCH)
            load_chunk2(A, B, bm, bn, (i + 2) * GBK, base, tid);
    }
}

// Fused QKV (single-term x * W): blockIdx.x in [0,24); sel routes.
__global__ __launch_bounds__(256, 2) void gemm_qkv_kernel(
    const __half* __restrict__ Xf,
    const __half* __restrict__ Wq, const __half* __restrict__ Wk,
    const __half* __restrict__ Wv,
    __half* __restrict__ Qf, __half* __restrict__ Kh, __half* __restrict__ Vf)
{
    extern __shared__ __align__(16) char gsm[];
    const uint32_t sb = smem_u32(gsm);
    const int sel = blockIdx.x >> 3;
    const int bn  = (blockIdx.x & 7) * 128;
    const int bm  = blockIdx.y * 128;
    const __half* B = sel == 0 ? Wq : sel == 1 ? Wk : Wv;
    __half* Dst = sel == 0 ? Qf : sel == 1 ? Kh : Vf;

    float acc[2][8][4];
    gemm_body1(Xf, B, bm, bn, sb, acc);

    const int lane = threadIdx.x & 31;
    const int w    = threadIdx.x >> 5;
    const int m_off = (w & 3) * 32;
    const int n_off = (w >> 2) * 64;
    const int g = lane >> 2;
    const int q = lane & 3;
#pragma unroll
    for (int mt = 0; mt < 2; mt++) {
#pragma unroll
        for (int nt = 0; nt < 8; nt++) {
            int row = bm + m_off + mt * 16 + g;
            int col = bn + n_off + nt * 8 + q * 2;
            *(uint32_t*)(Dst + (size_t)row * D_MODEL + col) =
                pack_f16(acc[mt][nt][0], acc[mt][nt][1]);
            *(uint32_t*)(Dst + (size_t)(row + 8) * D_MODEL + col) =
                pack_f16(acc[mt][nt][2], acc[mt][nt][3]);
        }
    }
}

// Output GEMM: single-term context * Wo^T -> fp32
__global__ __launch_bounds__(256, 2) void gemm_out_kernel(
    const __half* __restrict__ Cx, const __half* __restrict__ B,
    float* __restrict__ Cf)
{
    extern __shared__ __align__(16) char gsm[];
    const uint32_t sb = smem_u32(gsm);
    const int bn = blockIdx.x * 128;
    const int bm = blockIdx.y * 128;

    float acc[2][8][4];
    gemm_body1(Cx, B, bm, bn, sb, acc);

    const int lane = threadIdx.x & 31;
    const int w    = threadIdx.x >> 5;
    const int m_off = (w & 3) * 32;
    const int n_off = (w >> 2) * 64;
    const int g = lane >> 2;
    const int q = lane & 3;
#pragma unroll
    for (int mt = 0; mt < 2; mt++) {
#pragma unroll
        for (int nt = 0; nt < 8; nt++) {
            int row = bm + m_off + mt * 16 + g;
            int col = bn + n_off + nt * 8 + q * 2;
            *(float2*)(Cf + (size_t)row * D_MODEL + col) =
                make_float2(acc[mt][nt][0], acc[mt][nt][1]);
            *(float2*)(Cf + (size_t)(row + 8) * D_MODEL + col) =
                make_float2(acc[mt][nt][2], acc[mt][nt][3]);
        }
    }
}

// ---------------------------------------------------------------------------
// Tensor-core causal flash attention, fp16 single-term, 64-key tiles in a
// 3-stage cp.async ring with ONE __syncthreads per tile: wait -> sync ->
// issue load(t+2) into the buffer freed by tile t-1 (WAR-safe: all warps
// passed this barrier after reading t-1) -> compute.
// ---------------------------------------------------------------------------
#define AQT 128
#define AKT 64
#define AROWB 144
#define AQ_BYTES   (128 * AROWB)       // 18432
#define AKV_BYTES  (64 * AROWB)        // 9216 per component
#define ASET_BYTES (2 * AKV_BYTES)     // 18432 per stage (Kh, V)
#define ANSTAGE    3
#define ASM_KV0    AQ_BYTES            // 18432 (single Q buffer)
#define ASM_TOTAL  (ASM_KV0 + ANSTAGE * ASET_BYTES)   // 73728

#define FA_C1 0.18033688011112042f   // log2(e) / sqrt(64)

__device__ __forceinline__ void load_kv_tile(
    const __half* __restrict__ Kh, const __half* __restrict__ Vf,
    int k0, int h, uint32_t base, int tid)
{
#pragma unroll
    for (int t = 0; t < 2; t++) {
        int v = t * 256 + tid;              // 0..511
        int r = v >> 3, c = v & 7;
        uint32_t so = (uint32_t)(r * AROWB + c * 16);
        size_t  go = (size_t)(k0 + r) * D_MODEL + h * D_K + c * 8;
        cp_async16(base + so,             Kh + go);
        cp_async16(base + AKV_BYTES + so, Vf + go);
    }
    asm volatile("cp.async.commit_group;\n" ::: "memory");
}

__global__ __launch_bounds__(256, 2) void flash_mma_kernel(
    const __half* __restrict__ Qf,
    const __half* __restrict__ Kh, const __half* __restrict__ Vf,
    __half* __restrict__ Cx)
{
    extern __shared__ char smem[];
    const uint32_t sb = smem_u32(smem);
    const int tid  = threadIdx.x;
    const int lane = tid & 31;
    const int wid  = tid >> 5;
    const int m_off = wid * 16;          // 8 warps x 16 rows
    const int h  = blockIdx.y;
    const int q0 = (int)(gridDim.x - 1 - blockIdx.x) * AQT;   // heavy blocks first
    const int g  = lane >> 2;
    const int qd = lane & 3;

    // Stage Q (group 0): 4 x 16B per thread
#pragma unroll
    for (int t = 0; t < 4; t++) {
        int v = t * 256 + tid;              // 0..1023
        int r = v >> 3, c = v & 7;
        cp_async16(sb + r * AROWB + c * 16,
                   Qf + (size_t)(q0 + r) * D_MODEL + h * D_K + c * 8);
    }
    asm volatile("cp.async.commit_group;\n" ::: "memory");

    const int ntiles = q0 / AKT + AQT / AKT;   // >= 2

    // preload tiles 0 and 1 (one group each)
    load_kv_tile(Kh, Vf, 0 * AKT, h, sb + ASM_KV0 + 0 * ASET_BYTES, tid);
    load_kv_tile(Kh, Vf, 1 * AKT, h, sb + ASM_KV0 + 1 * ASET_BYTES, tid);

    float m_i[2] = { -1e30f, -1e30f };
    float l_i[2] = { 0.f, 0.f };
    float O[8][4];
#pragma unroll
    for (int no = 0; no < 8; no++)
#pragma unroll
        for (int i = 0; i < 4; i++) O[no][i] = 0.f;

    const uint32_t q_base = sb + (uint32_t)((m_off + (lane & 15)) * AROWB + 16 * (lane >> 4));
    const uint32_t k_base = (uint32_t)(((lane & 7) + 8 * (lane >> 4)) * AROWB
                                       + 16 * ((lane >> 3) & 1));
    const uint32_t v_base = (uint32_t)(((lane & 7) + 8 * ((lane >> 3) & 1)) * AROWB
                                       + 16 * (lane >> 4));

    // stage index helper: buffer(t) = t % 3
    for (int t = 0; t < ntiles; t++) {
        if (t + 1 < ntiles) {
            asm volatile("cp.async.wait_group 1;\n" ::: "memory");
        } else {
            asm volatile("cp.async.wait_group 0;\n" ::: "memory");
        }
        __syncthreads();

        // issue tile t+2's load into buffer (t+2)%3 == (t-1)%3 (freed: all
        // warps passed this barrier after finishing tile t-1's reads)
        if (t + 2 < ntiles) {
            uint32_t bidx = (uint32_t)((t + 2) % 3);
            load_kv_tile(Kh, Vf, (t + 2) * AKT, h,
                         sb + ASM_KV0 + bidx * ASET_BYTES, tid);
        }

        const uint32_t kvb = sb + ASM_KV0 + (uint32_t)(t % 3) * ASET_BYTES;
        const int k0 = t * AKT;

        // ---- scores S[8][4] (16 q-rows x 64 keys), single-term fp16 ----
        float S[8][4];
#pragma unroll
        for (int nt = 0; nt < 8; nt++)
#pragma unroll
            for (int i = 0; i < 4; i++) S[nt][i] = 0.f;

#pragma unroll
        for (int ks = 0; ks < 4; ks++) {
            uint32_t qa[4];
            ldsm_x4(qa, q_base + (uint32_t)(ks * 32));

            uint32_t b2[8][2];
#pragma unroll
            for (int np = 0; np < 4; np++) {
                uint32_t r4[4];
                ldsm_x4(r4, kvb + k_base + (uint32_t)(np * 16 * AROWB + ks * 32));
                b2[2*np][0] = r4[0]; b2[2*np][1] = r4[1];
                b2[2*np+1][0] = r4[2]; b2[2*np+1][1] = r4[3];
            }
#pragma unroll
            for (int nt = 0; nt < 8; nt++)
                mma_16816_f16(S[nt], qa, b2[nt]);
        }

        // ---- causal mask (boundary tiles only) ----
        if (k0 + AKT > q0) {
            int qg0 = q0 + m_off + g;
#pragma unroll
            for (int nt = 0; nt < 8; nt++) {
                int kg = k0 + nt * 8 + 2 * qd;
                if (kg     > qg0)     S[nt][0] = -1e30f;
                if (kg + 1 > qg0)     S[nt][1] = -1e30f;
                if (kg     > qg0 + 8) S[nt][2] = -1e30f;
                if (kg + 1 > qg0 + 8) S[nt][3] = -1e30f;
            }
        }

        // ---- online softmax per row half (rows g and g+8) ----
        float f[2];
#pragma unroll
        for (int hf = 0; hf < 2; hf++) {
            float mx = -1e30f;
#pragma unroll
            for (int nt = 0; nt < 8; nt++)
                mx = fmaxf(mx, fmaxf(S[nt][2*hf], S[nt][2*hf+1]));
            mx = fmaxf(mx, __shfl_xor_sync(0xffffffffu, mx, 1));
            mx = fmaxf(mx, __shfl_xor_sync(0xffffffffu, mx, 2));
            float mold = m_i[hf];
            float mnew = fmaxf(mold, mx);
            f[hf] = fast_exp2((mold - mnew) * FA_C1);
            float nm = mnew * FA_C1;
            float sum = 0.f;
#pragma unroll
            for (int nt = 0; nt < 8; nt++) {
                float p0 = fast_exp2(fmaf(S[nt][2*hf],   FA_C1, -nm));
                float p1 = fast_exp2(fmaf(S[nt][2*hf+1], FA_C1, -nm));
                S[nt][2*hf] = p0; S[nt][2*hf+1] = p1;
                sum += p0 + p1;
            }
            sum += __shfl_xor_sync(0xffffffffu, sum, 1);
            sum += __shfl_xor_sync(0xffffffffu, sum, 2);
            l_i[hf] = l_i[hf] * f[hf] + sum;
            m_i[hf] = mnew;
        }

        // ---- P·V (single-term fp16) ----
#pragma unroll
        for (int no = 0; no < 8; no++) {
            O[no][0] *= f[0]; O[no][1] *= f[0];
            O[no][2] *= f[1]; O[no][3] *= f[1];
        }
#pragma unroll
        for (int j = 0; j < 4; j++) {
            uint32_t ph[4];
            ph[0] = pack_f16(S[2*j][0],   S[2*j][1]);
            ph[1] = pack_f16(S[2*j][2],   S[2*j][3]);
            ph[2] = pack_f16(S[2*j+1][0], S[2*j+1][1]);
            ph[3] = pack_f16(S[2*j+1][2], S[2*j+1][3]);

            uint32_t v2[8][2];
#pragma unroll
            for (int np = 0; np < 4; np++) {
                uint32_t r4[4];
                ldsm_x4_t(r4, kvb + AKV_BYTES + v_base
                              + (uint32_t)(j * 16 * AROWB + np * 32));
                v2[2*np][0] = r4[0]; v2[2*np][1] = r4[1];
                v2[2*np+1][0] = r4[2]; v2[2*np+1][1] = r4[3];
            }
#pragma unroll
            for (int no = 0; no < 8; no++)
                mma_16816_f16(O[no], ph, v2[no]);
        }
    }

    // ---- epilogue: normalize + write single fp16 context ----
    {
        float inv0 = 1.f / l_i[0];
        float inv1 = 1.f / l_i[1];
        int r0 = q0 + m_off + g;
#pragma unroll
        for (int no = 0; no < 8; no++) {
            int col = h * D_K + no * 8 + 2 * qd;
            *(uint32_t*)(Cx + (size_t)r0 * D_MODEL + col) =
                pack_f16(O[no][0] * inv0, O[no][1] * inv0);
            *(uint32_t*)(Cx + (size_t)(r0 + 8) * D_MODEL + col) =
                pack_f16(O[no][2] * inv1, O[no][3] * inv1);
        }
    }
}

// ---------------------------------------------------------------------------
// Launch
// ---------------------------------------------------------------------------
extern "C" void kernel_launch(void* const* d_in, const int* in_sizes, int n_in,
                              void* d_out, int out_size)
{
    const float* x   = (const float*)d_in[0];
    const float* W_q = (const float*)d_in[1];
    const float* W_k = (const float*)d_in[2];
    const float* W_v = (const float*)d_in[3];
    const float* W_o = (const float*)d_in[4];
    float* out = (float*)d_out;

    static __half* xf = nullptr;
    static __half *cf, *qf, *kh, *vf;
    static __half *wq, *wk, *wv, *wo;
    if (xf == nullptr) {
        cudaGetSymbolAddress((void**)&cf, g_cf);
        cudaGetSymbolAddress((void**)&qf, g_Qf);
        cudaGetSymbolAddress((void**)&kh, g_Kh);
        cudaGetSymbolAddress((void**)&vf, g_Vf);
        cudaGetSymbolAddress((void**)&wq, g_wq);
        cudaGetSymbolAddress((void**)&wk, g_wk);
        cudaGetSymbolAddress((void**)&wv, g_wv);
        cudaGetSymbolAddress((void**)&wo, g_wo);
        cudaFuncSetAttribute(flash_mma_kernel,
                             cudaFuncAttributeMaxDynamicSharedMemorySize, ASM_TOTAL);
        cudaFuncSetAttribute(gemm_qkv_kernel,
                             cudaFuncAttributeMaxDynamicSharedMemorySize, GSM1);
        cudaFuncSetAttribute(gemm_out_kernel,
                             cudaFuncAttributeMaxDynamicSharedMemorySize, GSM1);
        cudaGetSymbolAddress((void**)&xf, g_xf);   // last: publishes init
    }

    // x: 1M float4s (4 * 2^18), 4 weights: 2^18 each -> 8 * 2^18 total
    conv_all_kernel<<<(8 * (1 << 18)) / 256, 256>>>(
        x, W_q, W_k, W_v, W_o, xf, wq, wk, wv, wo);

    dim3 qkvgrid(24, 32);
    gemm_qkv_kernel<<<qkvgrid, 256, GSM1>>>(xf, wq, wk, wv, qf, kh, vf);

    dim3 agrid(S_LEN / AQT, NHEADS);          // (32, 16)
    flash_mma_kernel<<<agrid, 256, ASM_TOTAL>>>(qf, kh, vf, cf);

    dim3 ogrid(8, 32);
    gemm_out_kernel<<<ogrid, 256, GSM1>>>(cf, wo, out);
}

// round 17
// speedup vs baseline: 2.5013x; 1.0216x over previous
#include <cuda_runtime.h>
#include <cuda_bf16.h>
#include <cuda_fp16.h>
#include <math.h>
#include <stdint.h>

// Problem constants (fixed shapes per reference)
#define S_LEN   4096
#define D_MODEL 1024
#define NHEADS  16
#define D_K     64

// ---------------------------------------------------------------------------
// Scratch (device globals; no allocation allowed)
// ---------------------------------------------------------------------------
__device__ __half g_xf[S_LEN * D_MODEL];
__device__ __half g_cf[S_LEN * D_MODEL];
__device__ __half g_Qf[S_LEN * D_MODEL];
__device__ __half g_Kh[S_LEN * D_MODEL];
__device__ __half g_Vf[S_LEN * D_MODEL];
__device__ __half g_wq[D_MODEL * D_MODEL];
__device__ __half g_wk[D_MODEL * D_MODEL];
__device__ __half g_wv[D_MODEL * D_MODEL];
__device__ __half g_wo[D_MODEL * D_MODEL];

// ---------------------------------------------------------------------------
// PTX helpers (base sm_80+ features only — build targets plain compute_103)
// ---------------------------------------------------------------------------
__device__ __forceinline__ uint32_t smem_u32(const void* p) {
    uint32_t a;
    asm("{ .reg .u64 t; cvta.to.shared.u64 t, %1; cvt.u32.u64 %0, t; }"
        : "=r"(a) : "l"(p));
    return a;
}

__device__ __forceinline__ void cp_async16(uint32_t smem_dst, const void* gmem_src) {
    asm volatile("cp.async.cg.shared.global [%0], [%1], 16;\n"
                 :: "r"(smem_dst), "l"(gmem_src));
}

__device__ __forceinline__ void ldsm_x4(uint32_t* r, uint32_t addr) {
    asm volatile("ldmatrix.sync.aligned.m8n8.x4.shared.b16 {%0,%1,%2,%3}, [%4];"
                 : "=r"(r[0]), "=r"(r[1]), "=r"(r[2]), "=r"(r[3]) : "r"(addr));
}

__device__ __forceinline__ void ldsm_x4_t(uint32_t* r, uint32_t addr) {
    asm volatile("ldmatrix.sync.aligned.m8n8.x4.trans.shared.b16 {%0,%1,%2,%3}, [%4];"
                 : "=r"(r[0]), "=r"(r[1]), "=r"(r[2]), "=r"(r[3]) : "r"(addr));
}

// fp16 MMA, fp32 accumulate
__device__ __forceinline__ void mma_16816_f16(float* d, const uint32_t* a, const uint32_t* b) {
    asm volatile(
        "mma.sync.aligned.m16n8k16.row.col.f32.f16.f16.f32 "
        "{%0,%1,%2,%3}, {%4,%5,%6,%7}, {%8,%9}, {%0,%1,%2,%3};"
        : "+f"(d[0]), "+f"(d[1]), "+f"(d[2]), "+f"(d[3])
        : "r"(a[0]), "r"(a[1]), "r"(a[2]), "r"(a[3]), "r"(b[0]), "r"(b[1]));
}

__device__ __forceinline__ float fast_exp2(float x) {
    float r; asm("ex2.approx.f32 %0, %1;" : "=f"(r) : "f"(x)); return r;
}

// pack two fp32 -> fp16x2 (x in low half, y in high half)
__device__ __forceinline__ uint32_t pack_f16(float x, float y) {
    uint32_t r;
    asm("cvt.rn.f16x2.f32 %0, %1, %2;" : "=r"(r) : "f"(y), "f"(x));
    return r;
}

// ---------------------------------------------------------------------------
// Fused conversion: x (1M float4) + 4 weights (256K float4 each) -> fp16.
// ---------------------------------------------------------------------------
__global__ void conv_all_kernel(
    const float* __restrict__ x,
    const float* __restrict__ w0, const float* __restrict__ w1,
    const float* __restrict__ w2, const float* __restrict__ w3,
    __half* __restrict__ xo,
    __half* __restrict__ o0, __half* __restrict__ o1,
    __half* __restrict__ o2, __half* __restrict__ o3)
{
    int idx = blockIdx.x * blockDim.x + threadIdx.x;
    int sel = idx >> 18;          // 0..7
    const float* in;
    __half* out;
    int i;
    if (sel < 4) { in = x; out = xo; i = idx; }
    else {
        i = idx & ((1 << 18) - 1);
        in  = sel == 4 ? w0 : sel == 5 ? w1 : sel == 6 ? w2 : w3;
        out = sel == 4 ? o0 : sel == 5 ? o1 : sel == 6 ? o2 : o3;
    }
    float4 v = ((const float4*)in)[i];
    ((uint32_t*)out)[i * 2 + 0] = pack_f16(v.x, v.y);
    ((uint32_t*)out)[i * 2 + 1] = pack_f16(v.z, v.w);
}

// ---------------------------------------------------------------------------
// GEMM (single-term fp16): acc = A*B^T, tile 128x128, BK=64, 3-stage ring
// with ONE __syncthreads per chunk: wait -> sync -> issue load(i+2) into the
// buffer freed by chunk i-1 (WAR-safe past this barrier) -> compute chunk i.
// Prefetch distance 2 chunks (128 K-rows).
// ---------------------------------------------------------------------------
#define GK     1024
#define GBK    64
#define ROWB   144              // 128B payload + 16B pad
#define TILEB  (128 * ROWB)     // 18432
#define NKCH   16
#define SETB1  (2 * TILEB)      // 36864 per stage (A, B)
#define GSM1   (3 * SETB1)      // 110592

__device__ __forceinline__ void load_chunk2(
    const __half* __restrict__ A, const __half* __restrict__ B,
    int bm, int bn, int k0, uint32_t dst, int tid)
{
#pragma unroll
    for (int t = 0; t < 4; t++) {
        int u = tid + t * 256;          // 0..1023
        int r = u >> 3;
        int c = (u & 7) * 16;           // byte offset in 128B row
        uint32_t so = (uint32_t)(r * ROWB + c);
        cp_async16(dst + so,         (const char*)(A + (size_t)(bm + r) * GK + k0) + c);
        cp_async16(dst + TILEB + so, (const char*)(B + (size_t)(bn + r) * GK + k0) + c);
    }
    asm volatile("cp.async.commit_group;\n" ::: "memory");
}

__device__ __forceinline__ void gemm_body1(
    const __half* __restrict__ A, const __half* __restrict__ B,
    int bm, int bn, uint32_t sb, float acc[2][8][4])
{
    const int tid  = threadIdx.x;
    const int lane = tid & 31;
    const int w    = tid >> 5;
    const int m_off = (w & 3) * 32;
    const int n_off = (w >> 2) * 64;

#pragma unroll
    for (int mt = 0; mt < 2; mt++)
#pragma unroll
        for (int nt = 0; nt < 8; nt++)
#pragma unroll
            for (int i = 0; i < 4; i++) acc[mt][nt][i] = 0.0f;

    const uint32_t a_off = (uint32_t)((m_off + (lane & 15)) * ROWB + 16 * (lane >> 4));
    const uint32_t b_off = (uint32_t)((n_off + (lane & 7) + 8 * (lane >> 4)) * ROWB
                                      + 16 * ((lane >> 3) & 1));

    load_chunk2(A, B, bm, bn, 0,   sb,         tid);
    load_chunk2(A, B, bm, bn, GBK, sb + SETB1, tid);

    for (int i = 0; i < NKCH; i++) {
        if (i + 1 < NKCH) {
            asm volatile("cp.async.wait_group 1;\n" ::: "memory");
        } else {
            asm volatile("cp.async.wait_group 0;\n" ::: "memory");
        }
        __syncthreads();

        // issue chunk i+2 into buffer (i+2)%3 == (i-1)%3 (freed: all warps
        // passed this barrier after computing chunk i-1)
        if (i + 2 < NKCH)
            load_chunk2(A, B, bm, bn, (i + 2) * GBK,
                        sb + (uint32_t)((i + 2) % 3) * SETB1, tid);

        const uint32_t base = sb + (uint32_t)(i % 3) * SETB1;
#pragma unroll
        for (int ks = 0; ks < 4; ks++) {
            uint32_t a2[2][4];
#pragma unroll
            for (int mt = 0; mt < 2; mt++)
                ldsm_x4(a2[mt], base + a_off + (uint32_t)(mt * 16 * ROWB + ks * 32));
            uint32_t b2[8][2];
#pragma unroll
            for (int np = 0; np < 4; np++) {
                uint32_t r4[4];
                ldsm_x4(r4, base + TILEB + b_off + (uint32_t)(np * 16 * ROWB + ks * 32));
                b2[2*np][0] = r4[0]; b2[2*np][1] = r4[1];
                b2[2*np+1][0] = r4[2]; b2[2*np+1][1] = r4[3];
            }
#pragma unroll
            for (int mt = 0; mt < 2; mt++)
#pragma unroll
                for (int nt = 0; nt < 8; nt++)
                    mma_16816_f16(acc[mt][nt], a2[mt], b2[nt]);
        }
    }
}

// Fused QKV (single-term x * W): blockIdx.x in [0,24); sel routes.
__global__ __launch_bounds__(256, 2) void gemm_qkv_kernel(
    const __half* __restrict__ Xf,
    const __half* __restrict__ Wq, const __half* __restrict__ Wk,
    const __half* __restrict__ Wv,
    __half* __restrict__ Qf, __half* __restrict__ Kh, __half* __restrict__ Vf)
{
    extern __shared__ __align__(16) char gsm[];
    const uint32_t sb = smem_u32(gsm);
    const int sel = blockIdx.x >> 3;
    const int bn  = (blockIdx.x & 7) * 128;
    const int bm  = blockIdx.y * 128;
    const __half* B = sel == 0 ? Wq : sel == 1 ? Wk : Wv;
    __half* Dst = sel == 0 ? Qf : sel == 1 ? Kh : Vf;

    float acc[2][8][4];
    gemm_body1(Xf, B, bm, bn, sb, acc);

    const int lane = threadIdx.x & 31;
    const int w    = threadIdx.x >> 5;
    const int m_off = (w & 3) * 32;
    const int n_off = (w >> 2) * 64;
    const int g = lane >> 2;
    const int q = lane & 3;
#pragma unroll
    for (int mt = 0; mt < 2; mt++) {
#pragma unroll
        for (int nt = 0; nt < 8; nt++) {
            int row = bm + m_off + mt * 16 + g;
            int col = bn + n_off + nt * 8 + q * 2;
            *(uint32_t*)(Dst + (size_t)row * D_MODEL + col) =
                pack_f16(acc[mt][nt][0], acc[mt][nt][1]);
            *(uint32_t*)(Dst + (size_t)(row + 8) * D_MODEL + col) =
                pack_f16(acc[mt][nt][2], acc[mt][nt][3]);
        }
    }
}

// Output GEMM: single-term context * Wo^T -> fp32
__global__ __launch_bounds__(256, 2) void gemm_out_kernel(
    const __half* __restrict__ Cx, const __half* __restrict__ B,
    float* __restrict__ Cf)
{
    extern __shared__ __align__(16) char gsm[];
    const uint32_t sb = smem_u32(gsm);
    const int bn = blockIdx.x * 128;
    const int bm = blockIdx.y * 128;

    float acc[2][8][4];
    gemm_body1(Cx, B, bm, bn, sb, acc);

    const int lane = threadIdx.x & 31;
    const int w    = threadIdx.x >> 5;
    const int m_off = (w & 3) * 32;
    const int n_off = (w >> 2) * 64;
    const int g = lane >> 2;
    const int q = lane & 3;
#pragma unroll
    for (int mt = 0; mt < 2; mt++) {
#pragma unroll
        for (int nt = 0; nt < 8; nt++) {
            int row = bm + m_off + mt * 16 + g;
            int col = bn + n_off + nt * 8 + q * 2;
            *(float2*)(Cf + (size_t)row * D_MODEL + col) =
                make_float2(acc[mt][nt][0], acc[mt][nt][1]);
            *(float2*)(Cf + (size_t)(row + 8) * D_MODEL + col) =
                make_float2(acc[mt][nt][2], acc[mt][nt][3]);
        }
    }
}

// ---------------------------------------------------------------------------
// Tensor-core causal flash attention, fp16 single-term, 64-key tiles in a
// 3-stage cp.async ring with ONE __syncthreads per tile (unchanged from R16).
// ---------------------------------------------------------------------------
#define AQT 128
#define AKT 64
#define AROWB 144
#define AQ_BYTES   (128 * AROWB)       // 18432
#define AKV_BYTES  (64 * AROWB)        // 9216 per component
#define ASET_BYTES (2 * AKV_BYTES)     // 18432 per stage (Kh, V)
#define ANSTAGE    3
#define ASM_KV0    AQ_BYTES            // 18432 (single Q buffer)
#define ASM_TOTAL  (ASM_KV0 + ANSTAGE * ASET_BYTES)   // 73728

#define FA_C1 0.18033688011112042f   // log2(e) / sqrt(64)

__device__ __forceinline__ void load_kv_tile(
    const __half* __restrict__ Kh, const __half* __restrict__ Vf,
    int k0, int h, uint32_t base, int tid)
{
#pragma unroll
    for (int t = 0; t < 2; t++) {
        int v = t * 256 + tid;              // 0..511
        int r = v >> 3, c = v & 7;
        uint32_t so = (uint32_t)(r * AROWB + c * 16);
        size_t  go = (size_t)(k0 + r) * D_MODEL + h * D_K + c * 8;
        cp_async16(base + so,             Kh + go);
        cp_async16(base + AKV_BYTES + so, Vf + go);
    }
    asm volatile("cp.async.commit_group;\n" ::: "memory");
}

__global__ __launch_bounds__(256, 2) void flash_mma_kernel(
    const __half* __restrict__ Qf,
    const __half* __restrict__ Kh, const __half* __restrict__ Vf,
    __half* __restrict__ Cx)
{
    extern __shared__ char smem[];
    const uint32_t sb = smem_u32(smem);
    const int tid  = threadIdx.x;
    const int lane = tid & 31;
    const int wid  = tid >> 5;
    const int m_off = wid * 16;          // 8 warps x 16 rows
    const int h  = blockIdx.y;
    const int q0 = (int)(gridDim.x - 1 - blockIdx.x) * AQT;   // heavy blocks first
    const int g  = lane >> 2;
    const int qd = lane & 3;

    // Stage Q (group 0): 4 x 16B per thread
#pragma unroll
    for (int t = 0; t < 4; t++) {
        int v = t * 256 + tid;              // 0..1023
        int r = v >> 3, c = v & 7;
        cp_async16(sb + r * AROWB + c * 16,
                   Qf + (size_t)(q0 + r) * D_MODEL + h * D_K + c * 8);
    }
    asm volatile("cp.async.commit_group;\n" ::: "memory");

    const int ntiles = q0 / AKT + AQT / AKT;   // >= 2

    // preload tiles 0 and 1 (one group each)
    load_kv_tile(Kh, Vf, 0 * AKT, h, sb + ASM_KV0 + 0 * ASET_BYTES, tid);
    load_kv_tile(Kh, Vf, 1 * AKT, h, sb + ASM_KV0 + 1 * ASET_BYTES, tid);

    float m_i[2] = { -1e30f, -1e30f };
    float l_i[2] = { 0.f, 0.f };
    float O[8][4];
#pragma unroll
    for (int no = 0; no < 8; no++)
#pragma unroll
        for (int i = 0; i < 4; i++) O[no][i] = 0.f;

    const uint32_t q_base = sb + (uint32_t)((m_off + (lane & 15)) * AROWB + 16 * (lane >> 4));
    const uint32_t k_base = (uint32_t)(((lane & 7) + 8 * (lane >> 4)) * AROWB
                                       + 16 * ((lane >> 3) & 1));
    const uint32_t v_base = (uint32_t)(((lane & 7) + 8 * ((lane >> 3) & 1)) * AROWB
                                       + 16 * (lane >> 4));

    for (int t = 0; t < ntiles; t++) {
        if (t + 1 < ntiles) {
            asm volatile("cp.async.wait_group 1;\n" ::: "memory");
        } else {
            asm volatile("cp.async.wait_group 0;\n" ::: "memory");
        }
        __syncthreads();

        if (t + 2 < ntiles) {
            uint32_t bidx = (uint32_t)((t + 2) % 3);
            load_kv_tile(Kh, Vf, (t + 2) * AKT, h,
                         sb + ASM_KV0 + bidx * ASET_BYTES, tid);
        }

        const uint32_t kvb = sb + ASM_KV0 + (uint32_t)(t % 3) * ASET_BYTES;
        const int k0 = t * AKT;

        // ---- scores S[8][4] (16 q-rows x 64 keys), single-term fp16 ----
        float S[8][4];
#pragma unroll
        for (int nt = 0; nt < 8; nt++)
#pragma unroll
            for (int i = 0; i < 4; i++) S[nt][i] = 0.f;

#pragma unroll
        for (int ks = 0; ks < 4; ks++) {
            uint32_t qa[4];
            ldsm_x4(qa, q_base + (uint32_t)(ks * 32));

            uint32_t b2[8][2];
#pragma unroll
            for (int np = 0; np < 4; np++) {
                uint32_t r4[4];
                ldsm_x4(r4, kvb + k_base + (uint32_t)(np * 16 * AROWB + ks * 32));
                b2[2*np][0] = r4[0]; b2[2*np][1] = r4[1];
                b2[2*np+1][0] = r4[2]; b2[2*np+1][1] = r4[3];
            }
#pragma unroll
            for (int nt = 0; nt < 8; nt++)
                mma_16816_f16(S[nt], qa, b2[nt]);
        }

        // ---- causal mask (boundary tiles only) ----
        if (k0 + AKT > q0) {
            int qg0 = q0 + m_off + g;
#pragma unroll
            for (int nt = 0; nt < 8; nt++) {
                int kg = k0 + nt * 8 + 2 * qd;
                if (kg     > qg0)     S[nt][0] = -1e30f;
                if (kg + 1 > qg0)     S[nt][1] = -1e30f;
                if (kg     > qg0 + 8) S[nt][2] = -1e30f;
                if (kg + 1 > qg0 + 8) S[nt][3] = -1e30f;
            }
        }

        // ---- online softmax per row half (rows g and g+8) ----
        float f[2];
#pragma unroll
        for (int hf = 0; hf < 2; hf++) {
            float mx = -1e30f;
#pragma unroll
            for (int nt = 0; nt < 8; nt++)
                mx = fmaxf(mx, fmaxf(S[nt][2*hf], S[nt][2*hf+1]));
            mx = fmaxf(mx, __shfl_xor_sync(0xffffffffu, mx, 1));
            mx = fmaxf(mx, __shfl_xor_sync(0xffffffffu, mx, 2));
            float mold = m_i[hf];
            float mnew = fmaxf(mold, mx);
            f[hf] = fast_exp2((mold - mnew) * FA_C1);
            float nm = mnew * FA_C1;
            float sum = 0.f;
#pragma unroll
            for (int nt = 0; nt < 8; nt++) {
                float p0 = fast_exp2(fmaf(S[nt][2*hf],   FA_C1, -nm));
                float p1 = fast_exp2(fmaf(S[nt][2*hf+1], FA_C1, -nm));
                S[nt][2*hf] = p0; S[nt][2*hf+1] = p1;
                sum += p0 + p1;
            }
            sum += __shfl_xor_sync(0xffffffffu, sum, 1);
            sum += __shfl_xor_sync(0xffffffffu, sum, 2);
            l_i[hf] = l_i[hf] * f[hf] + sum;
            m_i[hf] = mnew;
        }

        // ---- P·V (single-term fp16) ----
#pragma unroll
        for (int no = 0; no < 8; no++) {
            O[no][0] *= f[0]; O[no][1] *= f[0];
            O[no][2] *= f[1]; O[no][3] *= f[1];
        }
#pragma unroll
        for (int j = 0; j < 4; j++) {
            uint32_t ph[4];
            ph[0] = pack_f16(S[2*j][0],   S[2*j][1]);
            ph[1] = pack_f16(S[2*j][2],   S[2*j][3]);
            ph[2] = pack_f16(S[2*j+1][0], S[2*j+1][1]);
            ph[3] = pack_f16(S[2*j+1][2], S[2*j+1][3]);

            uint32_t v2[8][2];
#pragma unroll
            for (int np = 0; np < 4; np++) {
                uint32_t r4[4];
                ldsm_x4_t(r4, kvb + AKV_BYTES + v_base
                              + (uint32_t)(j * 16 * AROWB + np * 32));
                v2[2*np][0] = r4[0]; v2[2*np][1] = r4[1];
                v2[2*np+1][0] = r4[2]; v2[2*np+1][1] = r4[3];
            }
#pragma unroll
            for (int no = 0; no < 8; no++)
                mma_16816_f16(O[no], ph, v2[no]);
        }
    }

    // ---- epilogue: normalize + write single fp16 context ----
    {
        float inv0 = 1.f / l_i[0];
        float inv1 = 1.f / l_i[1];
        int r0 = q0 + m_off + g;
#pragma unroll
        for (int no = 0; no < 8; no++) {
            int col = h * D_K + no * 8 + 2 * qd;
            *(uint32_t*)(Cx + (size_t)r0 * D_MODEL + col) =
                pack_f16(O[no][0] * inv0, O[no][1] * inv0);
            *(uint32_t*)(Cx + (size_t)(r0 + 8) * D_MODEL + col) =
                pack_f16(O[no][2] * inv1, O[no][3] * inv1);
        }
    }
}

// ---------------------------------------------------------------------------
// Launch
// ---------------------------------------------------------------------------
extern "C" void kernel_launch(void* const* d_in, const int* in_sizes, int n_in,
                              void* d_out, int out_size)
{
    const float* x   = (const float*)d_in[0];
    const float* W_q = (const float*)d_in[1];
    const float* W_k = (const float*)d_in[2];
    const float* W_v = (const float*)d_in[3];
    const float* W_o = (const float*)d_in[4];
    float* out = (float*)d_out;

    static __half* xf = nullptr;
    static __half *cf, *qf, *kh, *vf;
    static __half *wq, *wk, *wv, *wo;
    if (xf == nullptr) {
        cudaGetSymbolAddress((void**)&cf, g_cf);
        cudaGetSymbolAddress((void**)&qf, g_Qf);
        cudaGetSymbolAddress((void**)&kh, g_Kh);
        cudaGetSymbolAddress((void**)&vf, g_Vf);
        cudaGetSymbolAddress((void**)&wq, g_wq);
        cudaGetSymbolAddress((void**)&wk, g_wk);
        cudaGetSymbolAddress((void**)&wv, g_wv);
        cudaGetSymbolAddress((void**)&wo, g_wo);
        cudaFuncSetAttribute(flash_mma_kernel,
                             cudaFuncAttributeMaxDynamicSharedMemorySize, ASM_TOTAL);
        cudaFuncSetAttribute(gemm_qkv_kernel,
                             cudaFuncAttributeMaxDynamicSharedMemorySize, GSM1);
        cudaFuncSetAttribute(gemm_out_kernel,
                             cudaFuncAttributeMaxDynamicSharedMemorySize, GSM1);
        cudaGetSymbolAddress((void**)&xf, g_xf);   // last: publishes init
    }

    // x: 1M float4s (4 * 2^18), 4 weights: 2^18 each -> 8 * 2^18 total
    conv_all_kernel<<<(8 * (1 << 18)) / 256, 256>>>(
        x, W_q, W_k, W_v, W_o, xf, wq, wk, wv, wo);

    dim3 qkvgrid(24, 32);
    gemm_qkv_kernel<<<qkvgrid, 256, GSM1>>>(xf, wq, wk, wv, qf, kh, vf);

    dim3 agrid(S_LEN / AQT, NHEADS);          // (32, 16)
    flash_mma_kernel<<<agrid, 256, ASM_TOTAL>>>(qf, kh, vf, cf);

    dim3 ogrid(8, 32);
    gemm_out_kernel<<<ogrid, 256, GSM1>>>(cf, wo, out);
}